// round 4
// baseline (speedup 1.0000x reference)
#include <cuda_runtime.h>
#include <cuda_bf16.h>
#include <cstdint>
#include <cstddef>

#define D_DIM 512
#define AGENTS 64
#define NBATCH 512
#define MTOT (NBATCH * AGENTS)   // 32768
#define NTVR 1536

// ---------------- scratch (device globals: allocation-free) ----------------
__device__ __align__(128) float           g_X   [MTOT * D_DIM];
__device__ __align__(128) __nv_bfloat16   g_Xhi [MTOT * D_DIM];
__device__ __align__(128) __nv_bfloat16   g_Xlo [MTOT * D_DIM];
__device__ __align__(128) __nv_bfloat16   g_Ihi [MTOT * D_DIM];
__device__ __align__(128) __nv_bfloat16   g_Ilo [MTOT * D_DIM];
__device__ __align__(128) float           g_TVR [MTOT * NTVR];
__device__ __align__(128) float           g_Wqk [D_DIM * D_DIM];
__device__ __align__(128) float           g_Wvo [D_DIM * D_DIM];
__device__ __align__(128) float           g_Wro [D_DIM * D_DIM];
__device__ __align__(128) __nv_bfloat16   g_WinT_hi[D_DIM * D_DIM];
__device__ __align__(128) __nv_bfloat16   g_WinT_lo[D_DIM * D_DIM];
__device__ __align__(128) __nv_bfloat16   g_WbT_hi [NTVR * D_DIM];
__device__ __align__(128) __nv_bfloat16   g_WbT_lo [NTVR * D_DIM];
__device__ __align__(128) float           g_gv  [D_DIM];
__device__ __align__(128) float           g_bias2[NTVR];

#define SWZ(o) ((o) ^ (((o) >> 3) & 0x70))

__device__ __forceinline__ uint32_t smem_u32(const void* p) {
    uint32_t a;
    asm("{ .reg .u64 t; cvta.to.shared.u64 t, %1; cvt.u32.u64 %0, t; }" : "=r"(a) : "l"(p));
    return a;
}
__device__ __forceinline__ void split1(float x, __nv_bfloat16& h, __nv_bfloat16& l) {
    h = __float2bfloat16(x);
    l = __float2bfloat16(x - __bfloat162float(h));
}
__device__ __forceinline__ void ldsm4(uint32_t* r, uint32_t addr) {
    asm volatile("ldmatrix.sync.aligned.m8n8.x4.shared.b16 {%0,%1,%2,%3}, [%4];"
                 : "=r"(r[0]), "=r"(r[1]), "=r"(r[2]), "=r"(r[3]) : "r"(addr));
}
__device__ __forceinline__ void mma16816(float* d, const uint32_t* a, uint32_t b0, uint32_t b1) {
    asm volatile(
        "mma.sync.aligned.m16n8k16.row.col.f32.bf16.bf16.f32 "
        "{%0,%1,%2,%3}, {%4,%5,%6,%7}, {%8,%9}, {%0,%1,%2,%3};"
        : "+f"(d[0]), "+f"(d[1]), "+f"(d[2]), "+f"(d[3])
        : "r"(a[0]), "r"(a[1]), "r"(a[2]), "r"(a[3]), "r"(b0), "r"(b1));
}
__device__ __forceinline__ void cpasync16(uint32_t dst, const void* src) {
    asm volatile("cp.async.cg.shared.global [%0], [%1], 16;" :: "r"(dst), "l"(src));
}
#define CP_COMMIT() asm volatile("cp.async.commit_group;" ::: "memory")
#define CP_WAIT(N)  asm volatile("cp.async.wait_group " #N ";" ::: "memory")

// ---------------- split inputs (fp32 -> bf16 hi/lo) ----------------
__global__ void split_k(const float* __restrict__ src,
                        __nv_bfloat16* __restrict__ hi, __nv_bfloat16* __restrict__ lo, int n4) {
    int i = blockIdx.x * blockDim.x + threadIdx.x;
    if (i >= n4) return;
    float4 v = ((const float4*)src)[i];
    __nv_bfloat16 h0,h1,h2,h3,l0,l1,l2,l3;
    split1(v.x,h0,l0); split1(v.y,h1,l1); split1(v.z,h2,l2); split1(v.w,h3,l3);
    uint32_t ha = (uint32_t)__bfloat16_as_ushort(h0) | ((uint32_t)__bfloat16_as_ushort(h1) << 16);
    uint32_t hb = (uint32_t)__bfloat16_as_ushort(h2) | ((uint32_t)__bfloat16_as_ushort(h3) << 16);
    uint32_t la = (uint32_t)__bfloat16_as_ushort(l0) | ((uint32_t)__bfloat16_as_ushort(l1) << 16);
    uint32_t lb = (uint32_t)__bfloat16_as_ushort(l2) | ((uint32_t)__bfloat16_as_ushort(l3) << 16);
    ((uint2*)hi)[i] = make_uint2(ha, hb);
    ((uint2*)lo)[i] = make_uint2(la, lb);
}

// ---------------- transpose + split weights: W[K,N] -> Wt[n_off+n][k] ----------------
__global__ void tsplit_k(const float* __restrict__ W,
                         __nv_bfloat16* __restrict__ hiT, __nv_bfloat16* __restrict__ loT,
                         int n_off) {
    __shared__ float tle[32][33];
    int tx = threadIdx.x, ty = threadIdx.y;
    int n0 = blockIdx.x * 32, k0 = blockIdx.y * 32;
    tle[ty][tx] = W[(size_t)(k0 + ty) * 512 + n0 + tx];
    __syncthreads();
    float v = tle[tx][ty];                 // W[k0+tx][n0+ty]
    int drow = n_off + n0 + ty, dcol = k0 + tx;
    __nv_bfloat16 h, l; split1(v, h, l);
    hiT[(size_t)drow * 512 + dcol] = h;
    loT[(size_t)drow * 512 + dcol] = l;
}

// ---------------- vector precompute: gv = Wk@bq ; bias2 = {0, bv@Wo, br@Wo+bo} ----------------
__global__ void vec_pre_k(const float* __restrict__ Wo,
                          const float* __restrict__ bv,
                          const float* __restrict__ br,
                          const float* __restrict__ bo,
                          const float* __restrict__ Wk,
                          const float* __restrict__ bq,
                          float* __restrict__ gv,
                          float* __restrict__ bias2) {
    int j = threadIdx.x;
    if (j < D_DIM) {
        float s1 = 0.f, s2 = 0.f;
        for (int d = 0; d < D_DIM; ++d) {
            float w = Wo[d * D_DIM + j];
            s1 += bv[d] * w;
            s2 += br[d] * w;
        }
        float s3 = 0.f;
        const float* wk = Wk + (size_t)j * D_DIM;
        for (int t = 0; t < D_DIM; ++t) s3 += wk[t] * bq[t];
        gv[j] = s3;
        bias2[j] = 0.f;
        bias2[512 + j] = s1;
        bias2[1024 + j] = s2 + bo[j];
    }
}

// ---------------- weight precompute: 3 fp32 512x512x512 GEMMs, 64x64 tiles ----------------
__global__ __launch_bounds__(256)
void wpre_k(const float* __restrict__ Wq, const float* __restrict__ Wk,
            const float* __restrict__ Wv, const float* __restrict__ Wr,
            const float* __restrict__ Wo,
            float* __restrict__ Wqk, float* __restrict__ Wvo, float* __restrict__ Wro) {
    const int z = blockIdx.z;
    const float* A = (z == 0) ? Wq : ((z == 1) ? Wv : Wr);
    const float* B = (z == 0) ? Wk : Wo;
    float* C = (z == 0) ? Wqk : ((z == 1) ? Wvo : Wro);
    const bool transb = (z == 0);

    __shared__ __align__(16) float As[32][72];
    __shared__ __align__(16) float Bs[32][72];
    const int t = threadIdx.x;
    const int tx = t & 15, ty = t >> 4;
    const int m0 = blockIdx.y * 64, n0 = blockIdx.x * 64;

    float acc[4][4];
#pragma unroll
    for (int i = 0; i < 4; ++i)
#pragma unroll
        for (int j = 0; j < 4; ++j) acc[i][j] = 0.f;

    for (int kt = 0; kt < 16; ++kt) {
        __syncthreads();
#pragma unroll
        for (int i = 0; i < 2; ++i) {
            const int idx = t + i * 256;
            const int row = idx >> 3, c4 = (idx & 7) * 4;
            float4 v = *(const float4*)(A + (size_t)(m0 + row) * 512 + kt * 32 + c4);
            As[c4 + 0][row] = v.x; As[c4 + 1][row] = v.y;
            As[c4 + 2][row] = v.z; As[c4 + 3][row] = v.w;
        }
        if (transb) {
#pragma unroll
            for (int i = 0; i < 2; ++i) {
                const int idx = t + i * 256;
                const int row = idx >> 3, c4 = (idx & 7) * 4;
                float4 v = *(const float4*)(B + (size_t)(n0 + row) * 512 + kt * 32 + c4);
                Bs[c4 + 0][row] = v.x; Bs[c4 + 1][row] = v.y;
                Bs[c4 + 2][row] = v.z; Bs[c4 + 3][row] = v.w;
            }
        } else {
#pragma unroll
            for (int i = 0; i < 2; ++i) {
                const int idx = t + i * 256;
                const int kr = idx >> 4, c4 = (idx & 15) * 4;
                float4 v = *(const float4*)(B + (size_t)(kt * 32 + kr) * 512 + n0 + c4);
                *(float4*)&Bs[kr][c4] = v;
            }
        }
        __syncthreads();
#pragma unroll
        for (int k = 0; k < 32; ++k) {
            float4 av = *(const float4*)&As[k][ty * 4];
            float4 bv = *(const float4*)&Bs[k][tx * 4];
            float a[4] = {av.x, av.y, av.z, av.w};
            float b[4] = {bv.x, bv.y, bv.z, bv.w};
#pragma unroll
            for (int i = 0; i < 4; ++i)
#pragma unroll
                for (int j = 0; j < 4; ++j) acc[i][j] += a[i] * b[j];
        }
    }
#pragma unroll
    for (int i = 0; i < 4; ++i) {
        float4 o = {acc[i][0], acc[i][1], acc[i][2], acc[i][3]};
        *(float4*)(C + (size_t)(m0 + ty * 4 + i) * 512 + n0 + tx * 4) = o;
    }
}

// ---------------- HMMA split-bf16 GEMM (multistage) ----------------
// C[M, Ntot] = (Ahi+Alo)[M,512] @ (Bhi+Blo)^T[Ntot,512] + bias
// Keff=1536 as 24 chunks of BK=64: 0-7 Ahi*Bhi, 8-15 Ahi*Blo, 16-23 Alo*Bhi.
// CTA tile 128x256, 8 warps (2x4), warp tile 64x64, 4-stage cp.async pipeline.
#define MG_STAGES 4
#define MG_STAGE_BYTES 49152          // A 16KB + B 32KB
#define MG_SMEM (MG_STAGES * MG_STAGE_BYTES)
#define MG_CHUNKS 24

template<bool RELU, bool SPLITOUT>
__global__ __launch_bounds__(256, 1)
void mma_gemm(const __nv_bfloat16* __restrict__ Ahi, const __nv_bfloat16* __restrict__ Alo,
              const __nv_bfloat16* __restrict__ Bhi, const __nv_bfloat16* __restrict__ Blo,
              const float* __restrict__ bias, float* __restrict__ C,
              __nv_bfloat16* __restrict__ Chi, __nv_bfloat16* __restrict__ Clo, int Ntot)
{
    extern __shared__ char sm[];
    const uint32_t smS = smem_u32(sm);

    const int t = threadIdx.x;
    const int wid = t >> 5, l = t & 31;
    const int wm = wid >> 2, wn = wid & 3;        // 2x4 warp grid, warp tile 64x64
    const int m0 = blockIdx.y * 128, n0 = blockIdx.x * 256;

    const int arow = l & 15, acol = l >> 4;
    const int brow = (l & 7) + ((l >> 4) & 1) * 8, bcol = (l >> 3) & 1;
    const int lrow = t >> 3, lcg = t & 7;

    float acc[4][8][4];
#pragma unroll
    for (int mi = 0; mi < 4; ++mi)
#pragma unroll
        for (int ni = 0; ni < 8; ++ni)
#pragma unroll
            for (int q = 0; q < 4; ++q) acc[mi][ni][q] = 0.f;

    auto load_chunk = [&](int c, int s) {
        const int seg = c >> 3;
        const int kk = (c & 7) * 64;
        const __nv_bfloat16* Asrc = (seg == 2) ? Alo : Ahi;
        const __nv_bfloat16* Bsrc = (seg == 1) ? Blo : Bhi;
        const uint32_t ab = smS + s * MG_STAGE_BYTES;
        const uint32_t bb = ab + 16384;
        const uint32_t off = SWZ((uint32_t)(lrow * 128 + lcg * 16));
#pragma unroll
        for (int i = 0; i < 4; ++i)
            cpasync16(ab + off + i * 4096,
                      Asrc + (size_t)(m0 + lrow + i * 32) * 512 + kk + lcg * 8);
#pragma unroll
        for (int i = 0; i < 8; ++i)
            cpasync16(bb + off + i * 4096,
                      Bsrc + (size_t)(n0 + lrow + i * 32) * 512 + kk + lcg * 8);
    };

    auto compute = [&](int s) {
        const uint32_t ab = smS + s * MG_STAGE_BYTES;
        const uint32_t bb = ab + 16384;
#pragma unroll
        for (int ks = 0; ks < 4; ++ks) {
            uint32_t a[4][4];
#pragma unroll
            for (int mi = 0; mi < 4; ++mi) {
                const int row = wm * 64 + mi * 16 + arow;
                ldsm4(a[mi], ab + SWZ((uint32_t)(row * 128 + (ks * 2 + acol) * 16)));
            }
#pragma unroll
            for (int nb = 0; nb < 4; ++nb) {
                const int row = wn * 64 + nb * 16 + brow;
                uint32_t b[4];
                ldsm4(b, bb + SWZ((uint32_t)(row * 128 + (ks * 2 + bcol) * 16)));
#pragma unroll
                for (int mi = 0; mi < 4; ++mi) {
                    mma16816(acc[mi][nb * 2],     a[mi], b[0], b[1]);
                    mma16816(acc[mi][nb * 2 + 1], a[mi], b[2], b[3]);
                }
            }
        }
    };

    // prologue: prefetch STAGES-1 chunks
#pragma unroll
    for (int s = 0; s < MG_STAGES - 1; ++s) {
        load_chunk(s, s);
        CP_COMMIT();
    }
    CP_WAIT(2);
    __syncthreads();

    for (int c = 0; c < MG_CHUNKS; ++c) {
        compute(c & 3);
        if (c + MG_STAGES - 1 < MG_CHUNKS)
            load_chunk(c + MG_STAGES - 1, (c + MG_STAGES - 1) & 3);
        CP_COMMIT();
        CP_WAIT(2);
        __syncthreads();
    }

    // epilogue
    const int gid = l >> 2, tig = l & 3;
#pragma unroll
    for (int mi = 0; mi < 4; ++mi) {
#pragma unroll
        for (int ni = 0; ni < 8; ++ni) {
            const int row = m0 + wm * 64 + mi * 16 + gid;
            const int col = n0 + wn * 64 + ni * 8 + tig * 2;
            float2 bb = *(const float2*)(bias + col);
            float v0 = acc[mi][ni][0] + bb.x;
            float v1 = acc[mi][ni][1] + bb.y;
            float v2 = acc[mi][ni][2] + bb.x;
            float v3 = acc[mi][ni][3] + bb.y;
            if (RELU) {
                v0 = fmaxf(v0, 0.f); v1 = fmaxf(v1, 0.f);
                v2 = fmaxf(v2, 0.f); v3 = fmaxf(v3, 0.f);
            }
            *(float2*)(C + (size_t)row * Ntot + col)       = make_float2(v0, v1);
            *(float2*)(C + (size_t)(row + 8) * Ntot + col) = make_float2(v2, v3);
            if (SPLITOUT) {
                __nv_bfloat16 h0,h1,h2,h3,l0,l1,l2,l3;
                split1(v0,h0,l0); split1(v1,h1,l1); split1(v2,h2,l2); split1(v3,h3,l3);
                ushort2 hu0 = {__bfloat16_as_ushort(h0), __bfloat16_as_ushort(h1)};
                ushort2 hu1 = {__bfloat16_as_ushort(h2), __bfloat16_as_ushort(h3)};
                ushort2 lu0 = {__bfloat16_as_ushort(l0), __bfloat16_as_ushort(l1)};
                ushort2 lu1 = {__bfloat16_as_ushort(l2), __bfloat16_as_ushort(l3)};
                *(ushort2*)(Chi + (size_t)row * 512 + col)       = hu0;
                *(ushort2*)(Chi + (size_t)(row + 8) * 512 + col) = hu1;
                *(ushort2*)(Clo + (size_t)row * 512 + col)       = lu0;
                *(ushort2*)(Clo + (size_t)(row + 8) * 512 + col) = lu1;
            }
        }
    }
}

// ---------------- per-batch attention + epilogue ----------------
__global__ __launch_bounds__(256, 2)
void attn_k(const float* __restrict__ X, const float* __restrict__ TVR,
            const float* __restrict__ gv, float* __restrict__ OUT)
{
    __shared__ float sc[64][65];
    __shared__ __align__(16) float sbuf[64 * 68];
    __shared__ float gsh[512];
    __shared__ float wpart[4][64];
    __shared__ float wsh[64];

    const int b = blockIdx.x;
    const float* Xb   = X   + (size_t)b * 64 * 512;
    const float* TVRb = TVR + (size_t)b * 64 * NTVR;
    float*       Ob   = OUT + (size_t)b * 64 * 512;

    const int tid = threadIdx.x;
    const int tx = tid & 15, ty = tid >> 4;

    gsh[tid]       = gv[tid];
    gsh[tid + 256] = gv[tid + 256];
    __syncthreads();

    {
        const int r = tid & 63, p = tid >> 6;
        const float* xr = Xb + r * 512 + p * 128;
        const float* gp = gsh + p * 128;
        float s = 0.f;
#pragma unroll 8
        for (int d = 0; d < 128; ++d) s += xr[d] * gp[d];
        wpart[p][r] = s;
    }

    float acc[4][4];
#pragma unroll
    for (int i = 0; i < 4; ++i)
#pragma unroll
        for (int j = 0; j < 4; ++j) acc[i][j] = 0.f;

    float* TT = sbuf;
    float* XT = sbuf + 32 * 68;

    for (int kt = 0; kt < 16; ++kt) {
        __syncthreads();
#pragma unroll
        for (int q = 0; q < 2; ++q) {
            const int idx = tid + q * 256;
            const int row = idx >> 3;
            const int c4  = (idx & 7) * 4;
            float4 v = *(const float4*)(TVRb + row * NTVR + kt * 32 + c4);
            TT[(c4 + 0) * 68 + row] = v.x; TT[(c4 + 1) * 68 + row] = v.y;
            TT[(c4 + 2) * 68 + row] = v.z; TT[(c4 + 3) * 68 + row] = v.w;
            float4 u = *(const float4*)(Xb + row * 512 + kt * 32 + c4);
            XT[(c4 + 0) * 68 + row] = u.x; XT[(c4 + 1) * 68 + row] = u.y;
            XT[(c4 + 2) * 68 + row] = u.z; XT[(c4 + 3) * 68 + row] = u.w;
        }
        __syncthreads();
#pragma unroll
        for (int k = 0; k < 32; ++k) {
            float4 av = *(const float4*)&TT[k * 68 + ty * 4];
            float4 bv = *(const float4*)&XT[k * 68 + tx * 4];
            float a[4]  = {av.x, av.y, av.z, av.w};
            float bb[4] = {bv.x, bv.y, bv.z, bv.w};
#pragma unroll
            for (int i = 0; i < 4; ++i)
#pragma unroll
                for (int j = 0; j < 4; ++j) acc[i][j] += a[i] * bb[j];
        }
    }
    __syncthreads();
    if (tid < 64)
        wsh[tid] = wpart[0][tid] + wpart[1][tid] + wpart[2][tid] + wpart[3][tid];
    __syncthreads();
#pragma unroll
    for (int i = 0; i < 4; ++i)
#pragma unroll
        for (int j = 0; j < 4; ++j)
            sc[ty * 4 + i][tx * 4 + j] = acc[i][j] + wsh[tx * 4 + j];
    __syncthreads();

    if (tid < 64) {
        float m = -1e30f;
#pragma unroll 8
        for (int c = 0; c < 64; ++c) m = fmaxf(m, sc[tid][c]);
        float s = 0.f;
#pragma unroll 8
        for (int c = 0; c < 64; ++c) { float e = expf(sc[tid][c] - m); sc[tid][c] = e; s += e; }
        const float inv = 1.f / s;
#pragma unroll 8
        for (int c = 0; c < 64; ++c) sc[tid][c] *= inv;
    }

    float* VOt = sbuf;
    for (int nt = 0; nt < 8; ++nt) {
        __syncthreads();
#pragma unroll
        for (int q = 0; q < 4; ++q) {
            const int idx = tid + q * 256;
            const int row = idx >> 4;
            const int c4  = (idx & 15) * 4;
            *(float4*)&VOt[row * 68 + c4] =
                *(const float4*)(TVRb + row * NTVR + 512 + nt * 64 + c4);
        }
        __syncthreads();

        float o[4][4];
#pragma unroll
        for (int i = 0; i < 4; ++i)
#pragma unroll
            for (int j = 0; j < 4; ++j) o[i][j] = 0.f;

#pragma unroll
        for (int k = 0; k < 64; ++k) {
            float a0 = sc[ty * 4 + 0][k];
            float a1 = sc[ty * 4 + 1][k];
            float a2 = sc[ty * 4 + 2][k];
            float a3 = sc[ty * 4 + 3][k];
            float4 bv = *(const float4*)&VOt[k * 68 + tx * 4];
            o[0][0] += a0 * bv.x; o[0][1] += a0 * bv.y; o[0][2] += a0 * bv.z; o[0][3] += a0 * bv.w;
            o[1][0] += a1 * bv.x; o[1][1] += a1 * bv.y; o[1][2] += a1 * bv.z; o[1][3] += a1 * bv.w;
            o[2][0] += a2 * bv.x; o[2][1] += a2 * bv.y; o[2][2] += a2 * bv.z; o[2][3] += a2 * bv.w;
            o[3][0] += a3 * bv.x; o[3][1] += a3 * bv.y; o[3][2] += a3 * bv.z; o[3][3] += a3 * bv.w;
        }
#pragma unroll
        for (int i = 0; i < 4; ++i) {
            const int row = ty * 4 + i;
            float4 rv = *(const float4*)(TVRb + row * NTVR + 1024 + nt * 64 + tx * 4);
            float4 ov;
            ov.x = fmaxf(o[i][0] + rv.x, 0.f);
            ov.y = fmaxf(o[i][1] + rv.y, 0.f);
            ov.z = fmaxf(o[i][2] + rv.z, 0.f);
            ov.w = fmaxf(o[i][3] + rv.w, 0.f);
            *(float4*)(Ob + row * 512 + nt * 64 + tx * 4) = ov;
        }
    }
}

// ---------------- launch ----------------
extern "C" void kernel_launch(void* const* d_in, const int* in_sizes, int n_in,
                              void* d_out, int out_size)
{
    const float* inp = (const float*)d_in[0];
    const float* Win = (const float*)d_in[1];
    const float* bin = (const float*)d_in[2];
    const float* Wq  = (const float*)d_in[3];
    const float* bq  = (const float*)d_in[4];
    const float* Wk  = (const float*)d_in[5];
    // d_in[6] = b_k : provably unused (row-constant, drops out of softmax)
    const float* Wv  = (const float*)d_in[7];
    const float* bv  = (const float*)d_in[8];
    const float* Wr  = (const float*)d_in[9];
    const float* br  = (const float*)d_in[10];
    const float* Wo  = (const float*)d_in[11];
    const float* bo  = (const float*)d_in[12];
    float* out = (float*)d_out;

    float *X, *TVR, *Wqk, *Wvo, *Wro, *gv, *bias2;
    __nv_bfloat16 *Xhi, *Xlo, *Ihi, *Ilo, *WinT_hi, *WinT_lo, *WbT_hi, *WbT_lo;
    cudaGetSymbolAddress((void**)&X,       g_X);
    cudaGetSymbolAddress((void**)&TVR,     g_TVR);
    cudaGetSymbolAddress((void**)&Wqk,     g_Wqk);
    cudaGetSymbolAddress((void**)&Wvo,     g_Wvo);
    cudaGetSymbolAddress((void**)&Wro,     g_Wro);
    cudaGetSymbolAddress((void**)&gv,      g_gv);
    cudaGetSymbolAddress((void**)&bias2,   g_bias2);
    cudaGetSymbolAddress((void**)&Xhi,     g_Xhi);
    cudaGetSymbolAddress((void**)&Xlo,     g_Xlo);
    cudaGetSymbolAddress((void**)&Ihi,     g_Ihi);
    cudaGetSymbolAddress((void**)&Ilo,     g_Ilo);
    cudaGetSymbolAddress((void**)&WinT_hi, g_WinT_hi);
    cudaGetSymbolAddress((void**)&WinT_lo, g_WinT_lo);
    cudaGetSymbolAddress((void**)&WbT_hi,  g_WbT_hi);
    cudaGetSymbolAddress((void**)&WbT_lo,  g_WbT_lo);

    cudaFuncSetAttribute(mma_gemm<true,  true >, cudaFuncAttributeMaxDynamicSharedMemorySize, MG_SMEM);
    cudaFuncSetAttribute(mma_gemm<false, false>, cudaFuncAttributeMaxDynamicSharedMemorySize, MG_SMEM);

    const dim3 bs(256);

    // weight-space precompute (fp32-exact, small)
    vec_pre_k<<<1, 512>>>(Wo, bv, br, bo, Wk, bq, gv, bias2);
    wpre_k<<<dim3(8, 8, 3), bs>>>(Wq, Wk, Wv, Wr, Wo, Wqk, Wvo, Wro);

    // transpose + bf16-split weights
    dim3 tb32(32, 32), tg(16, 16);
    tsplit_k<<<tg, tb32>>>(Win, WinT_hi, WinT_lo, 0);
    tsplit_k<<<tg, tb32>>>(Wqk, WbT_hi, WbT_lo, 0);
    tsplit_k<<<tg, tb32>>>(Wvo, WbT_hi, WbT_lo, 512);
    tsplit_k<<<tg, tb32>>>(Wro, WbT_hi, WbT_lo, 1024);

    // split activations
    const int n4 = MTOT * D_DIM / 4;
    split_k<<<(n4 + 255) / 256, 256>>>(inp, Ihi, Ilo, n4);

    // big GEMMs on tensor cores (mma.sync bf16, 3-term split)
    mma_gemm<true,  true ><<<dim3(2, 256), bs, MG_SMEM>>>(Ihi, Ilo, WinT_hi, WinT_lo,
                                                          bin, X, Xhi, Xlo, 512);
    mma_gemm<false, false><<<dim3(6, 256), bs, MG_SMEM>>>(Xhi, Xlo, WbT_hi, WbT_lo,
                                                          bias2, TVR, nullptr, nullptr, NTVR);

    // attention + epilogue
    attn_k<<<NBATCH, bs>>>(X, TVR, gv, out);
}

// round 5
// speedup vs baseline: 1.2286x; 1.2286x over previous
#include <cuda_runtime.h>
#include <cuda_bf16.h>
#include <cuda_fp16.h>
#include <cstdint>
#include <cstddef>

#define D_DIM 512
#define AGENTS 64
#define NBATCH 512
#define MTOT (NBATCH * AGENTS)   // 32768
#define NTVR 1536

// ---------------- scratch (device globals: allocation-free) ----------------
__device__ __align__(128) float           g_X   [MTOT * D_DIM];
__device__ __align__(128) __half          g_Xf16[MTOT * D_DIM];
__device__ __align__(128) __nv_bfloat16   g_Ihi [MTOT * D_DIM];
__device__ __align__(128) __nv_bfloat16   g_Ilo [MTOT * D_DIM];
__device__ __align__(128) float           g_TVR [MTOT * NTVR];
__device__ __align__(128) float           g_Wqk [D_DIM * D_DIM];
__device__ __align__(128) float           g_Wvo [D_DIM * D_DIM];
__device__ __align__(128) float           g_Wro [D_DIM * D_DIM];
__device__ __align__(128) __nv_bfloat16   g_WinT_hi[D_DIM * D_DIM];
__device__ __align__(128) __nv_bfloat16   g_WinT_lo[D_DIM * D_DIM];
__device__ __align__(128) __half          g_Wb_hi [NTVR * D_DIM];
__device__ __align__(128) __half          g_Wb_lo [NTVR * D_DIM];   // scaled x1024
__device__ __align__(128) float           g_gv  [D_DIM];
__device__ __align__(128) float           g_bias2[NTVR];

#define SWZ(o) ((o) ^ (((o) >> 3) & 0x70))

__device__ __forceinline__ uint32_t smem_u32(const void* p) {
    uint32_t a;
    asm("{ .reg .u64 t; cvta.to.shared.u64 t, %1; cvt.u32.u64 %0, t; }" : "=r"(a) : "l"(p));
    return a;
}
__device__ __forceinline__ void split1(float x, __nv_bfloat16& h, __nv_bfloat16& l) {
    h = __float2bfloat16(x);
    l = __float2bfloat16(x - __bfloat162float(h));
}
__device__ __forceinline__ void ldsm4(uint32_t* r, uint32_t addr) {
    asm volatile("ldmatrix.sync.aligned.m8n8.x4.shared.b16 {%0,%1,%2,%3}, [%4];"
                 : "=r"(r[0]), "=r"(r[1]), "=r"(r[2]), "=r"(r[3]) : "r"(addr));
}
__device__ __forceinline__ void mma_bf16(float* d, const uint32_t* a, uint32_t b0, uint32_t b1) {
    asm volatile(
        "mma.sync.aligned.m16n8k16.row.col.f32.bf16.bf16.f32 "
        "{%0,%1,%2,%3}, {%4,%5,%6,%7}, {%8,%9}, {%0,%1,%2,%3};"
        : "+f"(d[0]), "+f"(d[1]), "+f"(d[2]), "+f"(d[3])
        : "r"(a[0]), "r"(a[1]), "r"(a[2]), "r"(a[3]), "r"(b0), "r"(b1));
}
__device__ __forceinline__ void mma_f16(float* d, const uint32_t* a, uint32_t b0, uint32_t b1) {
    asm volatile(
        "mma.sync.aligned.m16n8k16.row.col.f32.f16.f16.f32 "
        "{%0,%1,%2,%3}, {%4,%5,%6,%7}, {%8,%9}, {%0,%1,%2,%3};"
        : "+f"(d[0]), "+f"(d[1]), "+f"(d[2]), "+f"(d[3])
        : "r"(a[0]), "r"(a[1]), "r"(a[2]), "r"(a[3]), "r"(b0), "r"(b1));
}
__device__ __forceinline__ void cpasync16(uint32_t dst, const void* src) {
    asm volatile("cp.async.cg.shared.global [%0], [%1], 16;" :: "r"(dst), "l"(src));
}
#define CP_COMMIT() asm volatile("cp.async.commit_group;" ::: "memory")
#define CP_WAIT(N)  asm volatile("cp.async.wait_group " #N ";" ::: "memory")

// ---------------- split inputs (fp32 -> bf16 hi/lo) ----------------
__global__ void split_k(const float* __restrict__ src,
                        __nv_bfloat16* __restrict__ hi, __nv_bfloat16* __restrict__ lo, int n4) {
    int i = blockIdx.x * blockDim.x + threadIdx.x;
    if (i >= n4) return;
    float4 v = ((const float4*)src)[i];
    __nv_bfloat16 h0,h1,h2,h3,l0,l1,l2,l3;
    split1(v.x,h0,l0); split1(v.y,h1,l1); split1(v.z,h2,l2); split1(v.w,h3,l3);
    uint32_t ha = (uint32_t)__bfloat16_as_ushort(h0) | ((uint32_t)__bfloat16_as_ushort(h1) << 16);
    uint32_t hb = (uint32_t)__bfloat16_as_ushort(h2) | ((uint32_t)__bfloat16_as_ushort(h3) << 16);
    uint32_t la = (uint32_t)__bfloat16_as_ushort(l0) | ((uint32_t)__bfloat16_as_ushort(l1) << 16);
    uint32_t lb = (uint32_t)__bfloat16_as_ushort(l2) | ((uint32_t)__bfloat16_as_ushort(l3) << 16);
    ((uint2*)hi)[i] = make_uint2(ha, hb);
    ((uint2*)lo)[i] = make_uint2(la, lb);
}

// ---------------- transpose+split Win (bf16 pair) ----------------
__global__ void tsplit_bf_k(const float* __restrict__ W,
                            __nv_bfloat16* __restrict__ hiT, __nv_bfloat16* __restrict__ loT) {
    __shared__ float tle[32][33];
    int tx = threadIdx.x, ty = threadIdx.y;
    int n0 = blockIdx.x * 32, k0 = blockIdx.y * 32;
    tle[ty][tx] = W[(size_t)(k0 + ty) * 512 + n0 + tx];
    __syncthreads();
    float v = tle[tx][ty];
    int drow = n0 + ty, dcol = k0 + tx;
    __nv_bfloat16 h, l; split1(v, h, l);
    hiT[(size_t)drow * 512 + dcol] = h;
    loT[(size_t)drow * 512 + dcol] = l;
}

// ---------------- transpose+split derived weights (fp16 pair, lo x1024) ----------------
__global__ void tsplit_f16_k(const float* __restrict__ W,
                             __half* __restrict__ hiT, __half* __restrict__ loT, int n_off) {
    __shared__ float tle[32][33];
    int tx = threadIdx.x, ty = threadIdx.y;
    int n0 = blockIdx.x * 32, k0 = blockIdx.y * 32;
    tle[ty][tx] = W[(size_t)(k0 + ty) * 512 + n0 + tx];
    __syncthreads();
    float v = tle[tx][ty];
    int drow = n_off + n0 + ty, dcol = k0 + tx;
    __half h = __float2half_rn(v);
    __half l = __float2half_rn((v - __half2float(h)) * 1024.0f);
    hiT[(size_t)drow * 512 + dcol] = h;
    loT[(size_t)drow * 512 + dcol] = l;
}

// ---------------- vector precompute: gv = Wk@bq ; bias2 = {0, bv@Wo, br@Wo+bo} ----------------
__global__ void vec_pre_k(const float* __restrict__ Wo,
                          const float* __restrict__ bv,
                          const float* __restrict__ br,
                          const float* __restrict__ bo,
                          const float* __restrict__ Wk,
                          const float* __restrict__ bq,
                          float* __restrict__ gv,
                          float* __restrict__ bias2) {
    int j = threadIdx.x;
    if (j < D_DIM) {
        float s1 = 0.f, s2 = 0.f;
        for (int d = 0; d < D_DIM; ++d) {
            float w = Wo[d * D_DIM + j];
            s1 += bv[d] * w;
            s2 += br[d] * w;
        }
        float s3 = 0.f;
        const float* wk = Wk + (size_t)j * D_DIM;
        for (int t = 0; t < D_DIM; ++t) s3 += wk[t] * bq[t];
        gv[j] = s3;
        bias2[j] = 0.f;
        bias2[512 + j] = s1;
        bias2[1024 + j] = s2 + bo[j];
    }
}

// ---------------- weight precompute: 3 fp32 512x512x512 GEMMs, 64x64 tiles ----------------
__global__ __launch_bounds__(256)
void wpre_k(const float* __restrict__ Wq, const float* __restrict__ Wk,
            const float* __restrict__ Wv, const float* __restrict__ Wr,
            const float* __restrict__ Wo,
            float* __restrict__ Wqk, float* __restrict__ Wvo, float* __restrict__ Wro) {
    const int z = blockIdx.z;
    const float* A = (z == 0) ? Wq : ((z == 1) ? Wv : Wr);
    const float* B = (z == 0) ? Wk : Wo;
    float* C = (z == 0) ? Wqk : ((z == 1) ? Wvo : Wro);
    const bool transb = (z == 0);

    __shared__ __align__(16) float As[32][72];
    __shared__ __align__(16) float Bs[32][72];
    const int t = threadIdx.x;
    const int tx = t & 15, ty = t >> 4;
    const int m0 = blockIdx.y * 64, n0 = blockIdx.x * 64;

    float acc[4][4];
#pragma unroll
    for (int i = 0; i < 4; ++i)
#pragma unroll
        for (int j = 0; j < 4; ++j) acc[i][j] = 0.f;

    for (int kt = 0; kt < 16; ++kt) {
        __syncthreads();
#pragma unroll
        for (int i = 0; i < 2; ++i) {
            const int idx = t + i * 256;
            const int row = idx >> 3, c4 = (idx & 7) * 4;
            float4 v = *(const float4*)(A + (size_t)(m0 + row) * 512 + kt * 32 + c4);
            As[c4 + 0][row] = v.x; As[c4 + 1][row] = v.y;
            As[c4 + 2][row] = v.z; As[c4 + 3][row] = v.w;
        }
        if (transb) {
#pragma unroll
            for (int i = 0; i < 2; ++i) {
                const int idx = t + i * 256;
                const int row = idx >> 3, c4 = (idx & 7) * 4;
                float4 v = *(const float4*)(B + (size_t)(n0 + row) * 512 + kt * 32 + c4);
                Bs[c4 + 0][row] = v.x; Bs[c4 + 1][row] = v.y;
                Bs[c4 + 2][row] = v.z; Bs[c4 + 3][row] = v.w;
            }
        } else {
#pragma unroll
            for (int i = 0; i < 2; ++i) {
                const int idx = t + i * 256;
                const int kr = idx >> 4, c4 = (idx & 15) * 4;
                float4 v = *(const float4*)(B + (size_t)(kt * 32 + kr) * 512 + n0 + c4);
                *(float4*)&Bs[kr][c4] = v;
            }
        }
        __syncthreads();
#pragma unroll
        for (int k = 0; k < 32; ++k) {
            float4 av = *(const float4*)&As[k][ty * 4];
            float4 bv = *(const float4*)&Bs[k][tx * 4];
            float a[4] = {av.x, av.y, av.z, av.w};
            float b[4] = {bv.x, bv.y, bv.z, bv.w};
#pragma unroll
            for (int i = 0; i < 4; ++i)
#pragma unroll
                for (int j = 0; j < 4; ++j) acc[i][j] += a[i] * b[j];
        }
    }
#pragma unroll
    for (int i = 0; i < 4; ++i) {
        float4 o = {acc[i][0], acc[i][1], acc[i][2], acc[i][3]};
        *(float4*)(C + (size_t)(m0 + ty * 4 + i) * 512 + n0 + tx * 4) = o;
    }
}

// ---------------- GEMM 1: X = relu(inp @ Win + b), bf16 3-term split ----------------
// CTA 128x128, BK=64, 8 warps (4x2), warp tile 32x64, 2-stage cp.async (R3-proven).
#define MG_SMEM 65536

__global__ __launch_bounds__(256)
void gemm_x(const __nv_bfloat16* __restrict__ Ahi, const __nv_bfloat16* __restrict__ Alo,
            const __nv_bfloat16* __restrict__ Bhi, const __nv_bfloat16* __restrict__ Blo,
            const float* __restrict__ bias, float* __restrict__ C,
            __half* __restrict__ Cf16)
{
    extern __shared__ char sm[];
    const uint32_t smA = smem_u32(sm);
    const uint32_t smB = smA + 32768;

    const int t = threadIdx.x;
    const int wid = t >> 5, l = t & 31;
    const int wm = wid >> 1, wn = wid & 1;
    const int m0 = blockIdx.y * 128, n0 = blockIdx.x * 128;

    const int arow = l & 15, acol = l >> 4;
    const int brow = (l & 7) + ((l >> 4) & 1) * 8, bcol = (l >> 3) & 1;
    const int lrow = t >> 3, lcg = t & 7;

    float acc[2][8][4];
#pragma unroll
    for (int mi = 0; mi < 2; ++mi)
#pragma unroll
        for (int ni = 0; ni < 8; ++ni)
#pragma unroll
            for (int q = 0; q < 4; ++q) acc[mi][ni][q] = 0.f;

    auto load_chunk = [&](int c, int s) {
        const int seg = c >> 3;
        const int kk = (c & 7) * 64;
        const __nv_bfloat16* Asrc = (seg == 2) ? Alo : Ahi;
        const __nv_bfloat16* Bsrc = (seg == 1) ? Blo : Bhi;
        const uint32_t ab = smA + s * 16384;
        const uint32_t bb = smB + s * 16384;
#pragma unroll
        for (int i = 0; i < 4; ++i) {
            const int row = lrow + i * 32;
            const uint32_t off = SWZ((uint32_t)(row * 128 + lcg * 16));
            cpasync16(ab + off, Asrc + (size_t)(m0 + row) * 512 + kk + lcg * 8);
            cpasync16(bb + off, Bsrc + (size_t)(n0 + row) * 512 + kk + lcg * 8);
        }
        CP_COMMIT();
    };

    auto compute = [&](int s) {
        const uint32_t ab = smA + s * 16384;
        const uint32_t bb = smB + s * 16384;
#pragma unroll
        for (int ks = 0; ks < 4; ++ks) {
            uint32_t a[2][4];
#pragma unroll
            for (int mi = 0; mi < 2; ++mi) {
                const int row = wm * 32 + mi * 16 + arow;
                ldsm4(a[mi], ab + SWZ((uint32_t)(row * 128 + (ks * 2 + acol) * 16)));
            }
#pragma unroll
            for (int nb = 0; nb < 4; ++nb) {
                const int row = wn * 64 + nb * 16 + brow;
                uint32_t b[4];
                ldsm4(b, bb + SWZ((uint32_t)(row * 128 + (ks * 2 + bcol) * 16)));
                mma_bf16(acc[0][nb * 2],     a[0], b[0], b[1]);
                mma_bf16(acc[1][nb * 2],     a[1], b[0], b[1]);
                mma_bf16(acc[0][nb * 2 + 1], a[0], b[2], b[3]);
                mma_bf16(acc[1][nb * 2 + 1], a[1], b[2], b[3]);
            }
        }
    };

    load_chunk(0, 0);
    load_chunk(1, 1);
    CP_WAIT(1);
    __syncthreads();

    for (int c = 0; c < 24; ++c) {
        const int s = c & 1;
        compute(s);
        if (c == 23) break;
        __syncthreads();
        if (c + 2 < 24) { load_chunk(c + 2, s); CP_WAIT(1); }
        else            { CP_WAIT(0); }
        __syncthreads();
    }

    const int gid = l >> 2, tig = l & 3;
#pragma unroll
    for (int mi = 0; mi < 2; ++mi) {
#pragma unroll
        for (int ni = 0; ni < 8; ++ni) {
            const int row = m0 + wm * 32 + mi * 16 + gid;
            const int col = n0 + wn * 64 + ni * 8 + tig * 2;
            float2 bb = *(const float2*)(bias + col);
            float v0 = fmaxf(acc[mi][ni][0] + bb.x, 0.f);
            float v1 = fmaxf(acc[mi][ni][1] + bb.y, 0.f);
            float v2 = fmaxf(acc[mi][ni][2] + bb.x, 0.f);
            float v3 = fmaxf(acc[mi][ni][3] + bb.y, 0.f);
            *(float2*)(C + (size_t)row * 512 + col)       = make_float2(v0, v1);
            *(float2*)(C + (size_t)(row + 8) * 512 + col) = make_float2(v2, v3);
            __half h0 = __float2half_rn(v0), h1 = __float2half_rn(v1);
            __half h2 = __float2half_rn(v2), h3 = __float2half_rn(v3);
            ushort2 u0 = {__half_as_ushort(h0), __half_as_ushort(h1)};
            ushort2 u1 = {__half_as_ushort(h2), __half_as_ushort(h3)};
            *(ushort2*)(Cf16 + (size_t)row * 512 + col)       = u0;
            *(ushort2*)(Cf16 + (size_t)(row + 8) * 512 + col) = u1;
        }
    }
}

// ---------------- GEMM 2: TVR = Xf16 @ (Wb_hi + Wb_lo/1024)^T + bias2, fp16 2-term ----------------
// Chunks 0-7: Blo (scaled x1024) -> rescale acc x2^-10 after chunk 7; chunks 8-15: Bhi.
__global__ __launch_bounds__(256)
void gemm_tvr(const __half* __restrict__ A,
              const __half* __restrict__ Bhi, const __half* __restrict__ Blo,
              const float* __restrict__ bias, float* __restrict__ C)
{
    extern __shared__ char sm[];
    const uint32_t smA = smem_u32(sm);
    const uint32_t smB = smA + 32768;

    const int t = threadIdx.x;
    const int wid = t >> 5, l = t & 31;
    const int wm = wid >> 1, wn = wid & 1;
    const int m0 = blockIdx.y * 128, n0 = blockIdx.x * 128;

    const int arow = l & 15, acol = l >> 4;
    const int brow = (l & 7) + ((l >> 4) & 1) * 8, bcol = (l >> 3) & 1;
    const int lrow = t >> 3, lcg = t & 7;

    float acc[2][8][4];
#pragma unroll
    for (int mi = 0; mi < 2; ++mi)
#pragma unroll
        for (int ni = 0; ni < 8; ++ni)
#pragma unroll
            for (int q = 0; q < 4; ++q) acc[mi][ni][q] = 0.f;

    auto load_chunk = [&](int c, int s) {
        const int kk = (c & 7) * 64;
        const __half* Bsrc = (c < 8) ? Blo : Bhi;
        const uint32_t ab = smA + s * 16384;
        const uint32_t bb = smB + s * 16384;
#pragma unroll
        for (int i = 0; i < 4; ++i) {
            const int row = lrow + i * 32;
            const uint32_t off = SWZ((uint32_t)(row * 128 + lcg * 16));
            cpasync16(ab + off, A    + (size_t)(m0 + row) * 512 + kk + lcg * 8);
            cpasync16(bb + off, Bsrc + (size_t)(n0 + row) * 512 + kk + lcg * 8);
        }
        CP_COMMIT();
    };

    auto compute = [&](int s) {
        const uint32_t ab = smA + s * 16384;
        const uint32_t bb = smB + s * 16384;
#pragma unroll
        for (int ks = 0; ks < 4; ++ks) {
            uint32_t a[2][4];
#pragma unroll
            for (int mi = 0; mi < 2; ++mi) {
                const int row = wm * 32 + mi * 16 + arow;
                ldsm4(a[mi], ab + SWZ((uint32_t)(row * 128 + (ks * 2 + acol) * 16)));
            }
#pragma unroll
            for (int nb = 0; nb < 4; ++nb) {
                const int row = wn * 64 + nb * 16 + brow;
                uint32_t b[4];
                ldsm4(b, bb + SWZ((uint32_t)(row * 128 + (ks * 2 + bcol) * 16)));
                mma_f16(acc[0][nb * 2],     a[0], b[0], b[1]);
                mma_f16(acc[1][nb * 2],     a[1], b[0], b[1]);
                mma_f16(acc[0][nb * 2 + 1], a[0], b[2], b[3]);
                mma_f16(acc[1][nb * 2 + 1], a[1], b[2], b[3]);
            }
        }
    };

    load_chunk(0, 0);
    load_chunk(1, 1);
    CP_WAIT(1);
    __syncthreads();

    for (int c = 0; c < 16; ++c) {
        const int s = c & 1;
        compute(s);
        if (c == 7) {
            // descale the Blo (x1024) partial sums
#pragma unroll
            for (int mi = 0; mi < 2; ++mi)
#pragma unroll
                for (int ni = 0; ni < 8; ++ni)
#pragma unroll
                    for (int q = 0; q < 4; ++q) acc[mi][ni][q] *= 0.0009765625f;
        }
        if (c == 15) break;
        __syncthreads();
        if (c + 2 < 16) { load_chunk(c + 2, s); CP_WAIT(1); }
        else            { CP_WAIT(0); }
        __syncthreads();
    }

    const int gid = l >> 2, tig = l & 3;
#pragma unroll
    for (int mi = 0; mi < 2; ++mi) {
#pragma unroll
        for (int ni = 0; ni < 8; ++ni) {
            const int row = m0 + wm * 32 + mi * 16 + gid;
            const int col = n0 + wn * 64 + ni * 8 + tig * 2;
            float2 bb = *(const float2*)(bias + col);
            *(float2*)(C + (size_t)row * NTVR + col) =
                make_float2(acc[mi][ni][0] + bb.x, acc[mi][ni][1] + bb.y);
            *(float2*)(C + (size_t)(row + 8) * NTVR + col) =
                make_float2(acc[mi][ni][2] + bb.x, acc[mi][ni][3] + bb.y);
        }
    }
}

// ---------------- per-batch attention + epilogue ----------------
__global__ __launch_bounds__(256, 2)
void attn_k(const float* __restrict__ X, const float* __restrict__ TVR,
            const float* __restrict__ gv, float* __restrict__ OUT)
{
    __shared__ float sc[64][65];
    __shared__ __align__(16) float sbuf[64 * 68];
    __shared__ float gsh[512];
    __shared__ float wpart[4][64];
    __shared__ float wsh[64];

    const int b = blockIdx.x;
    const float* Xb   = X   + (size_t)b * 64 * 512;
    const float* TVRb = TVR + (size_t)b * 64 * NTVR;
    float*       Ob   = OUT + (size_t)b * 64 * 512;

    const int tid = threadIdx.x;
    const int tx = tid & 15, ty = tid >> 4;

    gsh[tid]       = gv[tid];
    gsh[tid + 256] = gv[tid + 256];
    __syncthreads();

    {
        const int r = tid & 63, p = tid >> 6;
        const float* xr = Xb + r * 512 + p * 128;
        const float* gp = gsh + p * 128;
        float s = 0.f;
#pragma unroll 8
        for (int d = 0; d < 128; ++d) s += xr[d] * gp[d];
        wpart[p][r] = s;
    }

    float acc[4][4];
#pragma unroll
    for (int i = 0; i < 4; ++i)
#pragma unroll
        for (int j = 0; j < 4; ++j) acc[i][j] = 0.f;

    float* TT = sbuf;
    float* XT = sbuf + 32 * 68;

    for (int kt = 0; kt < 16; ++kt) {
        __syncthreads();
#pragma unroll
        for (int q = 0; q < 2; ++q) {
            const int idx = tid + q * 256;
            const int row = idx >> 3;
            const int c4  = (idx & 7) * 4;
            float4 v = *(const float4*)(TVRb + row * NTVR + kt * 32 + c4);
            TT[(c4 + 0) * 68 + row] = v.x; TT[(c4 + 1) * 68 + row] = v.y;
            TT[(c4 + 2) * 68 + row] = v.z; TT[(c4 + 3) * 68 + row] = v.w;
            float4 u = *(const float4*)(Xb + row * 512 + kt * 32 + c4);
            XT[(c4 + 0) * 68 + row] = u.x; XT[(c4 + 1) * 68 + row] = u.y;
            XT[(c4 + 2) * 68 + row] = u.z; XT[(c4 + 3) * 68 + row] = u.w;
        }
        __syncthreads();
#pragma unroll
        for (int k = 0; k < 32; ++k) {
            float4 av = *(const float4*)&TT[k * 68 + ty * 4];
            float4 bv = *(const float4*)&XT[k * 68 + tx * 4];
            float a[4]  = {av.x, av.y, av.z, av.w};
            float bb[4] = {bv.x, bv.y, bv.z, bv.w};
#pragma unroll
            for (int i = 0; i < 4; ++i)
#pragma unroll
                for (int j = 0; j < 4; ++j) acc[i][j] += a[i] * bb[j];
        }
    }
    __syncthreads();
    if (tid < 64)
        wsh[tid] = wpart[0][tid] + wpart[1][tid] + wpart[2][tid] + wpart[3][tid];
    __syncthreads();
#pragma unroll
    for (int i = 0; i < 4; ++i)
#pragma unroll
        for (int j = 0; j < 4; ++j)
            sc[ty * 4 + i][tx * 4 + j] = acc[i][j] + wsh[tx * 4 + j];
    __syncthreads();

    if (tid < 64) {
        float m = -1e30f;
#pragma unroll 8
        for (int c = 0; c < 64; ++c) m = fmaxf(m, sc[tid][c]);
        float s = 0.f;
#pragma unroll 8
        for (int c = 0; c < 64; ++c) { float e = expf(sc[tid][c] - m); sc[tid][c] = e; s += e; }
        const float inv = 1.f / s;
#pragma unroll 8
        for (int c = 0; c < 64; ++c) sc[tid][c] *= inv;
    }

    float* VOt = sbuf;
    for (int nt = 0; nt < 8; ++nt) {
        __syncthreads();
#pragma unroll
        for (int q = 0; q < 4; ++q) {
            const int idx = tid + q * 256;
            const int row = idx >> 4;
            const int c4  = (idx & 15) * 4;
            *(float4*)&VOt[row * 68 + c4] =
                *(const float4*)(TVRb + row * NTVR + 512 + nt * 64 + c4);
        }
        __syncthreads();

        float o[4][4];
#pragma unroll
        for (int i = 0; i < 4; ++i)
#pragma unroll
            for (int j = 0; j < 4; ++j) o[i][j] = 0.f;

#pragma unroll
        for (int k = 0; k < 64; ++k) {
            float a0 = sc[ty * 4 + 0][k];
            float a1 = sc[ty * 4 + 1][k];
            float a2 = sc[ty * 4 + 2][k];
            float a3 = sc[ty * 4 + 3][k];
            float4 bv = *(const float4*)&VOt[k * 68 + tx * 4];
            o[0][0] += a0 * bv.x; o[0][1] += a0 * bv.y; o[0][2] += a0 * bv.z; o[0][3] += a0 * bv.w;
            o[1][0] += a1 * bv.x; o[1][1] += a1 * bv.y; o[1][2] += a1 * bv.z; o[1][3] += a1 * bv.w;
            o[2][0] += a2 * bv.x; o[2][1] += a2 * bv.y; o[2][2] += a2 * bv.z; o[2][3] += a2 * bv.w;
            o[3][0] += a3 * bv.x; o[3][1] += a3 * bv.y; o[3][2] += a3 * bv.z; o[3][3] += a3 * bv.w;
        }
#pragma unroll
        for (int i = 0; i < 4; ++i) {
            const int row = ty * 4 + i;
            float4 rv = *(const float4*)(TVRb + row * NTVR + 1024 + nt * 64 + tx * 4);
            float4 ov;
            ov.x = fmaxf(o[i][0] + rv.x, 0.f);
            ov.y = fmaxf(o[i][1] + rv.y, 0.f);
            ov.z = fmaxf(o[i][2] + rv.z, 0.f);
            ov.w = fmaxf(o[i][3] + rv.w, 0.f);
            *(float4*)(Ob + row * 512 + nt * 64 + tx * 4) = ov;
        }
    }
}

// ---------------- launch ----------------
extern "C" void kernel_launch(void* const* d_in, const int* in_sizes, int n_in,
                              void* d_out, int out_size)
{
    const float* inp = (const float*)d_in[0];
    const float* Win = (const float*)d_in[1];
    const float* bin = (const float*)d_in[2];
    const float* Wq  = (const float*)d_in[3];
    const float* bq  = (const float*)d_in[4];
    const float* Wk  = (const float*)d_in[5];
    // d_in[6] = b_k : provably unused (row-constant, drops out of softmax)
    const float* Wv  = (const float*)d_in[7];
    const float* bv  = (const float*)d_in[8];
    const float* Wr  = (const float*)d_in[9];
    const float* br  = (const float*)d_in[10];
    const float* Wo  = (const float*)d_in[11];
    const float* bo  = (const float*)d_in[12];
    float* out = (float*)d_out;

    float *X, *TVR, *Wqk, *Wvo, *Wro, *gv, *bias2;
    __nv_bfloat16 *Ihi, *Ilo, *WinT_hi, *WinT_lo;
    __half *Xf16, *Wb_hi, *Wb_lo;
    cudaGetSymbolAddress((void**)&X,       g_X);
    cudaGetSymbolAddress((void**)&TVR,     g_TVR);
    cudaGetSymbolAddress((void**)&Wqk,     g_Wqk);
    cudaGetSymbolAddress((void**)&Wvo,     g_Wvo);
    cudaGetSymbolAddress((void**)&Wro,     g_Wro);
    cudaGetSymbolAddress((void**)&gv,      g_gv);
    cudaGetSymbolAddress((void**)&bias2,   g_bias2);
    cudaGetSymbolAddress((void**)&Xf16,    g_Xf16);
    cudaGetSymbolAddress((void**)&Ihi,     g_Ihi);
    cudaGetSymbolAddress((void**)&Ilo,     g_Ilo);
    cudaGetSymbolAddress((void**)&WinT_hi, g_WinT_hi);
    cudaGetSymbolAddress((void**)&WinT_lo, g_WinT_lo);
    cudaGetSymbolAddress((void**)&Wb_hi,   g_Wb_hi);
    cudaGetSymbolAddress((void**)&Wb_lo,   g_Wb_lo);

    cudaFuncSetAttribute(gemm_x,   cudaFuncAttributeMaxDynamicSharedMemorySize, MG_SMEM);
    cudaFuncSetAttribute(gemm_tvr, cudaFuncAttributeMaxDynamicSharedMemorySize, MG_SMEM);

    const dim3 bs(256);

    // weight-space precompute (fp32-exact, small)
    vec_pre_k<<<1, 512>>>(Wo, bv, br, bo, Wk, bq, gv, bias2);
    wpre_k<<<dim3(8, 8, 3), bs>>>(Wq, Wk, Wv, Wr, Wo, Wqk, Wvo, Wro);

    // transpose + split weights
    dim3 tb32(32, 32), tg(16, 16);
    tsplit_bf_k <<<tg, tb32>>>(Win, WinT_hi, WinT_lo);
    tsplit_f16_k<<<tg, tb32>>>(Wqk, Wb_hi, Wb_lo, 0);
    tsplit_f16_k<<<tg, tb32>>>(Wvo, Wb_hi, Wb_lo, 512);
    tsplit_f16_k<<<tg, tb32>>>(Wro, Wb_hi, Wb_lo, 1024);

    // split activations (bf16 hi/lo)
    const int n4 = MTOT * D_DIM / 4;
    split_k<<<(n4 + 255) / 256, 256>>>(inp, Ihi, Ilo, n4);

    // big GEMMs on tensor cores
    gemm_x  <<<dim3(4, 256),  bs, MG_SMEM>>>(Ihi, Ilo, WinT_hi, WinT_lo, bin, X, Xf16);
    gemm_tvr<<<dim3(12, 256), bs, MG_SMEM>>>(Xf16, Wb_hi, Wb_lo, bias2, TVR);

    // attention + epilogue
    attn_k<<<NBATCH, bs>>>(X, TVR, gv, out);
}

// round 6
// speedup vs baseline: 1.4054x; 1.1440x over previous
#include <cuda_runtime.h>
#include <cuda_bf16.h>
#include <cuda_fp16.h>
#include <cstdint>
#include <cstddef>

#define D_DIM 512
#define AGENTS 64
#define NBATCH 512
#define MTOT (NBATCH * AGENTS)   // 32768
#define NTVR 1536

// ---------------- scratch (device globals: allocation-free) ----------------
__device__ __align__(128) float           g_X   [MTOT * D_DIM];
__device__ __align__(128) __half          g_Xf16[MTOT * D_DIM];
__device__ __align__(128) __nv_bfloat16   g_Ihi [MTOT * D_DIM];
__device__ __align__(128) __nv_bfloat16   g_Ilo [MTOT * D_DIM];
__device__ __align__(128) float           g_TVR [MTOT * NTVR];
__device__ __align__(128) float           g_Wqk [D_DIM * D_DIM];
__device__ __align__(128) float           g_Wvo [D_DIM * D_DIM];
__device__ __align__(128) float           g_Wro [D_DIM * D_DIM];
__device__ __align__(128) __nv_bfloat16   g_WinT_hi[D_DIM * D_DIM];
__device__ __align__(128) __nv_bfloat16   g_WinT_lo[D_DIM * D_DIM];
__device__ __align__(128) __half          g_Wb_hi [NTVR * D_DIM];
__device__ __align__(128) float           g_gv  [D_DIM];
__device__ __align__(128) float           g_bias2[NTVR];

#define SWZ(o) ((o) ^ (((o) >> 3) & 0x70))

__device__ __forceinline__ uint32_t smem_u32(const void* p) {
    uint32_t a;
    asm("{ .reg .u64 t; cvta.to.shared.u64 t, %1; cvt.u32.u64 %0, t; }" : "=r"(a) : "l"(p));
    return a;
}
__device__ __forceinline__ void split1(float x, __nv_bfloat16& h, __nv_bfloat16& l) {
    h = __float2bfloat16(x);
    l = __float2bfloat16(x - __bfloat162float(h));
}
__device__ __forceinline__ void ldsm4(uint32_t* r, uint32_t addr) {
    asm volatile("ldmatrix.sync.aligned.m8n8.x4.shared.b16 {%0,%1,%2,%3}, [%4];"
                 : "=r"(r[0]), "=r"(r[1]), "=r"(r[2]), "=r"(r[3]) : "r"(addr));
}
__device__ __forceinline__ void mma_bf16(float* d, const uint32_t* a, uint32_t b0, uint32_t b1) {
    asm volatile(
        "mma.sync.aligned.m16n8k16.row.col.f32.bf16.bf16.f32 "
        "{%0,%1,%2,%3}, {%4,%5,%6,%7}, {%8,%9}, {%0,%1,%2,%3};"
        : "+f"(d[0]), "+f"(d[1]), "+f"(d[2]), "+f"(d[3])
        : "r"(a[0]), "r"(a[1]), "r"(a[2]), "r"(a[3]), "r"(b0), "r"(b1));
}
__device__ __forceinline__ void mma_f16(float* d, const uint32_t* a, uint32_t b0, uint32_t b1) {
    asm volatile(
        "mma.sync.aligned.m16n8k16.row.col.f32.f16.f16.f32 "
        "{%0,%1,%2,%3}, {%4,%5,%6,%7}, {%8,%9}, {%0,%1,%2,%3};"
        : "+f"(d[0]), "+f"(d[1]), "+f"(d[2]), "+f"(d[3])
        : "r"(a[0]), "r"(a[1]), "r"(a[2]), "r"(a[3]), "r"(b0), "r"(b1));
}
__device__ __forceinline__ void cpasync16(uint32_t dst, const void* src) {
    asm volatile("cp.async.cg.shared.global [%0], [%1], 16;" :: "r"(dst), "l"(src));
}
#define CP_COMMIT() asm volatile("cp.async.commit_group;" ::: "memory")
#define CP_WAIT(N)  asm volatile("cp.async.wait_group " #N ";" ::: "memory")

// ---------------- split inputs (fp32 -> bf16 hi/lo) ----------------
__global__ void split_k(const float* __restrict__ src,
                        __nv_bfloat16* __restrict__ hi, __nv_bfloat16* __restrict__ lo, int n4) {
    int i = blockIdx.x * blockDim.x + threadIdx.x;
    if (i >= n4) return;
    float4 v = ((const float4*)src)[i];
    __nv_bfloat16 h0,h1,h2,h3,l0,l1,l2,l3;
    split1(v.x,h0,l0); split1(v.y,h1,l1); split1(v.z,h2,l2); split1(v.w,h3,l3);
    uint32_t ha = (uint32_t)__bfloat16_as_ushort(h0) | ((uint32_t)__bfloat16_as_ushort(h1) << 16);
    uint32_t hb = (uint32_t)__bfloat16_as_ushort(h2) | ((uint32_t)__bfloat16_as_ushort(h3) << 16);
    uint32_t la = (uint32_t)__bfloat16_as_ushort(l0) | ((uint32_t)__bfloat16_as_ushort(l1) << 16);
    uint32_t lb = (uint32_t)__bfloat16_as_ushort(l2) | ((uint32_t)__bfloat16_as_ushort(l3) << 16);
    ((uint2*)hi)[i] = make_uint2(ha, hb);
    ((uint2*)lo)[i] = make_uint2(la, lb);
}

// ---------------- transpose+split Win (bf16 pair) ----------------
__global__ void tsplit_bf_k(const float* __restrict__ W,
                            __nv_bfloat16* __restrict__ hiT, __nv_bfloat16* __restrict__ loT) {
    __shared__ float tle[32][33];
    int tx = threadIdx.x, ty = threadIdx.y;
    int n0 = blockIdx.x * 32, k0 = blockIdx.y * 32;
    tle[ty][tx] = W[(size_t)(k0 + ty) * 512 + n0 + tx];
    __syncthreads();
    float v = tle[tx][ty];
    int drow = n0 + ty, dcol = k0 + tx;
    __nv_bfloat16 h, l; split1(v, h, l);
    hiT[(size_t)drow * 512 + dcol] = h;
    loT[(size_t)drow * 512 + dcol] = l;
}

// ---------------- transpose derived weights to fp16 (single term) ----------------
__global__ void t_f16_k(const float* __restrict__ W,
                        __half* __restrict__ hiT, int n_off) {
    __shared__ float tle[32][33];
    int tx = threadIdx.x, ty = threadIdx.y;
    int n0 = blockIdx.x * 32, k0 = blockIdx.y * 32;
    tle[ty][tx] = W[(size_t)(k0 + ty) * 512 + n0 + tx];
    __syncthreads();
    float v = tle[tx][ty];
    hiT[(size_t)(n_off + n0 + ty) * 512 + k0 + tx] = __float2half_rn(v);
}

// ---------------- vector precompute: gv = Wk@bq ; bias2 = {0, bv@Wo, br@Wo+bo} ----------------
__global__ void vec_pre_k(const float* __restrict__ Wo,
                          const float* __restrict__ bv,
                          const float* __restrict__ br,
                          const float* __restrict__ bo,
                          const float* __restrict__ Wk,
                          const float* __restrict__ bq,
                          float* __restrict__ gv,
                          float* __restrict__ bias2) {
    int j = threadIdx.x;
    if (j < D_DIM) {
        float s1 = 0.f, s2 = 0.f;
        for (int d = 0; d < D_DIM; ++d) {
            float w = Wo[d * D_DIM + j];
            s1 += bv[d] * w;
            s2 += br[d] * w;
        }
        float s3 = 0.f;
        const float* wk = Wk + (size_t)j * D_DIM;
        for (int t = 0; t < D_DIM; ++t) s3 += wk[t] * bq[t];
        gv[j] = s3;
        bias2[j] = 0.f;
        bias2[512 + j] = s1;
        bias2[1024 + j] = s2 + bo[j];
    }
}

// ---------------- weight precompute: 3 fp32 512x512x512 GEMMs, 64x64 tiles ----------------
__global__ __launch_bounds__(256)
void wpre_k(const float* __restrict__ Wq, const float* __restrict__ Wk,
            const float* __restrict__ Wv, const float* __restrict__ Wr,
            const float* __restrict__ Wo,
            float* __restrict__ Wqk, float* __restrict__ Wvo, float* __restrict__ Wro) {
    const int z = blockIdx.z;
    const float* A = (z == 0) ? Wq : ((z == 1) ? Wv : Wr);
    const float* B = (z == 0) ? Wk : Wo;
    float* C = (z == 0) ? Wqk : ((z == 1) ? Wvo : Wro);
    const bool transb = (z == 0);

    __shared__ __align__(16) float As[32][72];
    __shared__ __align__(16) float Bs[32][72];
    const int t = threadIdx.x;
    const int tx = t & 15, ty = t >> 4;
    const int m0 = blockIdx.y * 64, n0 = blockIdx.x * 64;

    float acc[4][4];
#pragma unroll
    for (int i = 0; i < 4; ++i)
#pragma unroll
        for (int j = 0; j < 4; ++j) acc[i][j] = 0.f;

    for (int kt = 0; kt < 16; ++kt) {
        __syncthreads();
#pragma unroll
        for (int i = 0; i < 2; ++i) {
            const int idx = t + i * 256;
            const int row = idx >> 3, c4 = (idx & 7) * 4;
            float4 v = *(const float4*)(A + (size_t)(m0 + row) * 512 + kt * 32 + c4);
            As[c4 + 0][row] = v.x; As[c4 + 1][row] = v.y;
            As[c4 + 2][row] = v.z; As[c4 + 3][row] = v.w;
        }
        if (transb) {
#pragma unroll
            for (int i = 0; i < 2; ++i) {
                const int idx = t + i * 256;
                const int row = idx >> 3, c4 = (idx & 7) * 4;
                float4 v = *(const float4*)(B + (size_t)(n0 + row) * 512 + kt * 32 + c4);
                Bs[c4 + 0][row] = v.x; Bs[c4 + 1][row] = v.y;
                Bs[c4 + 2][row] = v.z; Bs[c4 + 3][row] = v.w;
            }
        } else {
#pragma unroll
            for (int i = 0; i < 2; ++i) {
                const int idx = t + i * 256;
                const int kr = idx >> 4, c4 = (idx & 15) * 4;
                float4 v = *(const float4*)(B + (size_t)(kt * 32 + kr) * 512 + n0 + c4);
                *(float4*)&Bs[kr][c4] = v;
            }
        }
        __syncthreads();
#pragma unroll
        for (int k = 0; k < 32; ++k) {
            float4 av = *(const float4*)&As[k][ty * 4];
            float4 bv = *(const float4*)&Bs[k][tx * 4];
            float a[4] = {av.x, av.y, av.z, av.w};
            float b[4] = {bv.x, bv.y, bv.z, bv.w};
#pragma unroll
            for (int i = 0; i < 4; ++i)
#pragma unroll
                for (int j = 0; j < 4; ++j) acc[i][j] += a[i] * b[j];
        }
    }
#pragma unroll
    for (int i = 0; i < 4; ++i) {
        float4 o = {acc[i][0], acc[i][1], acc[i][2], acc[i][3]};
        *(float4*)(C + (size_t)(m0 + ty * 4 + i) * 512 + n0 + tx * 4) = o;
    }
}

// ---------------- GEMM 1: X = relu(inp @ Win + b), bf16 3-term split ----------------
// CTA 128x128, BK=64, 8 warps (4x2), warp tile 32x64, 2-stage cp.async (R3-proven).
#define MG_SMEM 65536

__global__ __launch_bounds__(256)
void gemm_x(const __nv_bfloat16* __restrict__ Ahi, const __nv_bfloat16* __restrict__ Alo,
            const __nv_bfloat16* __restrict__ Bhi, const __nv_bfloat16* __restrict__ Blo,
            const float* __restrict__ bias, float* __restrict__ C,
            __half* __restrict__ Cf16)
{
    extern __shared__ char sm[];
    const uint32_t smA = smem_u32(sm);
    const uint32_t smB = smA + 32768;

    const int t = threadIdx.x;
    const int wid = t >> 5, l = t & 31;
    const int wm = wid >> 1, wn = wid & 1;
    const int m0 = blockIdx.y * 128, n0 = blockIdx.x * 128;

    const int arow = l & 15, acol = l >> 4;
    const int brow = (l & 7) + ((l >> 4) & 1) * 8, bcol = (l >> 3) & 1;
    const int lrow = t >> 3, lcg = t & 7;

    float acc[2][8][4];
#pragma unroll
    for (int mi = 0; mi < 2; ++mi)
#pragma unroll
        for (int ni = 0; ni < 8; ++ni)
#pragma unroll
            for (int q = 0; q < 4; ++q) acc[mi][ni][q] = 0.f;

    auto load_chunk = [&](int c, int s) {
        const int seg = c >> 3;
        const int kk = (c & 7) * 64;
        const __nv_bfloat16* Asrc = (seg == 2) ? Alo : Ahi;
        const __nv_bfloat16* Bsrc = (seg == 1) ? Blo : Bhi;
        const uint32_t ab = smA + s * 16384;
        const uint32_t bb = smB + s * 16384;
#pragma unroll
        for (int i = 0; i < 4; ++i) {
            const int row = lrow + i * 32;
            const uint32_t off = SWZ((uint32_t)(row * 128 + lcg * 16));
            cpasync16(ab + off, Asrc + (size_t)(m0 + row) * 512 + kk + lcg * 8);
            cpasync16(bb + off, Bsrc + (size_t)(n0 + row) * 512 + kk + lcg * 8);
        }
        CP_COMMIT();
    };

    auto compute = [&](int s) {
        const uint32_t ab = smA + s * 16384;
        const uint32_t bb = smB + s * 16384;
#pragma unroll
        for (int ks = 0; ks < 4; ++ks) {
            uint32_t a[2][4];
#pragma unroll
            for (int mi = 0; mi < 2; ++mi) {
                const int row = wm * 32 + mi * 16 + arow;
                ldsm4(a[mi], ab + SWZ((uint32_t)(row * 128 + (ks * 2 + acol) * 16)));
            }
#pragma unroll
            for (int nb = 0; nb < 4; ++nb) {
                const int row = wn * 64 + nb * 16 + brow;
                uint32_t b[4];
                ldsm4(b, bb + SWZ((uint32_t)(row * 128 + (ks * 2 + bcol) * 16)));
                mma_bf16(acc[0][nb * 2],     a[0], b[0], b[1]);
                mma_bf16(acc[1][nb * 2],     a[1], b[0], b[1]);
                mma_bf16(acc[0][nb * 2 + 1], a[0], b[2], b[3]);
                mma_bf16(acc[1][nb * 2 + 1], a[1], b[2], b[3]);
            }
        }
    };

    load_chunk(0, 0);
    load_chunk(1, 1);
    CP_WAIT(1);
    __syncthreads();

    for (int c = 0; c < 24; ++c) {
        const int s = c & 1;
        compute(s);
        if (c == 23) break;
        __syncthreads();
        if (c + 2 < 24) { load_chunk(c + 2, s); CP_WAIT(1); }
        else            { CP_WAIT(0); }
        __syncthreads();
    }

    const int gid = l >> 2, tig = l & 3;
#pragma unroll
    for (int mi = 0; mi < 2; ++mi) {
#pragma unroll
        for (int ni = 0; ni < 8; ++ni) {
            const int row = m0 + wm * 32 + mi * 16 + gid;
            const int col = n0 + wn * 64 + ni * 8 + tig * 2;
            float2 bb = *(const float2*)(bias + col);
            float v0 = fmaxf(acc[mi][ni][0] + bb.x, 0.f);
            float v1 = fmaxf(acc[mi][ni][1] + bb.y, 0.f);
            float v2 = fmaxf(acc[mi][ni][2] + bb.x, 0.f);
            float v3 = fmaxf(acc[mi][ni][3] + bb.y, 0.f);
            *(float2*)(C + (size_t)row * 512 + col)       = make_float2(v0, v1);
            *(float2*)(C + (size_t)(row + 8) * 512 + col) = make_float2(v2, v3);
            __half h0 = __float2half_rn(v0), h1 = __float2half_rn(v1);
            __half h2 = __float2half_rn(v2), h3 = __float2half_rn(v3);
            ushort2 u0 = {__half_as_ushort(h0), __half_as_ushort(h1)};
            ushort2 u1 = {__half_as_ushort(h2), __half_as_ushort(h3)};
            *(ushort2*)(Cf16 + (size_t)row * 512 + col)       = u0;
            *(ushort2*)(Cf16 + (size_t)(row + 8) * 512 + col) = u1;
        }
    }
}

// ---------------- GEMM 2: TVR = Xf16 @ Wb^T + bias2, fp16 single-term ----------------
__global__ __launch_bounds__(256)
void gemm_tvr(const __half* __restrict__ A,
              const __half* __restrict__ B,
              const float* __restrict__ bias, float* __restrict__ C)
{
    extern __shared__ char sm[];
    const uint32_t smA = smem_u32(sm);
    const uint32_t smB = smA + 32768;

    const int t = threadIdx.x;
    const int wid = t >> 5, l = t & 31;
    const int wm = wid >> 1, wn = wid & 1;
    const int m0 = blockIdx.y * 128, n0 = blockIdx.x * 128;

    const int arow = l & 15, acol = l >> 4;
    const int brow = (l & 7) + ((l >> 4) & 1) * 8, bcol = (l >> 3) & 1;
    const int lrow = t >> 3, lcg = t & 7;

    float acc[2][8][4];
#pragma unroll
    for (int mi = 0; mi < 2; ++mi)
#pragma unroll
        for (int ni = 0; ni < 8; ++ni)
#pragma unroll
            for (int q = 0; q < 4; ++q) acc[mi][ni][q] = 0.f;

    auto load_chunk = [&](int c, int s) {
        const int kk = c * 64;
        const uint32_t ab = smA + s * 16384;
        const uint32_t bb = smB + s * 16384;
#pragma unroll
        for (int i = 0; i < 4; ++i) {
            const int row = lrow + i * 32;
            const uint32_t off = SWZ((uint32_t)(row * 128 + lcg * 16));
            cpasync16(ab + off, A + (size_t)(m0 + row) * 512 + kk + lcg * 8);
            cpasync16(bb + off, B + (size_t)(n0 + row) * 512 + kk + lcg * 8);
        }
        CP_COMMIT();
    };

    auto compute = [&](int s) {
        const uint32_t ab = smA + s * 16384;
        const uint32_t bb = smB + s * 16384;
#pragma unroll
        for (int ks = 0; ks < 4; ++ks) {
            uint32_t a[2][4];
#pragma unroll
            for (int mi = 0; mi < 2; ++mi) {
                const int row = wm * 32 + mi * 16 + arow;
                ldsm4(a[mi], ab + SWZ((uint32_t)(row * 128 + (ks * 2 + acol) * 16)));
            }
#pragma unroll
            for (int nb = 0; nb < 4; ++nb) {
                const int row = wn * 64 + nb * 16 + brow;
                uint32_t b[4];
                ldsm4(b, bb + SWZ((uint32_t)(row * 128 + (ks * 2 + bcol) * 16)));
                mma_f16(acc[0][nb * 2],     a[0], b[0], b[1]);
                mma_f16(acc[1][nb * 2],     a[1], b[0], b[1]);
                mma_f16(acc[0][nb * 2 + 1], a[0], b[2], b[3]);
                mma_f16(acc[1][nb * 2 + 1], a[1], b[2], b[3]);
            }
        }
    };

    load_chunk(0, 0);
    load_chunk(1, 1);
    CP_WAIT(1);
    __syncthreads();

    for (int c = 0; c < 8; ++c) {
        const int s = c & 1;
        compute(s);
        if (c == 7) break;
        __syncthreads();
        if (c + 2 < 8) { load_chunk(c + 2, s); CP_WAIT(1); }
        else           { CP_WAIT(0); }
        __syncthreads();
    }

    const int gid = l >> 2, tig = l & 3;
#pragma unroll
    for (int mi = 0; mi < 2; ++mi) {
#pragma unroll
        for (int ni = 0; ni < 8; ++ni) {
            const int row = m0 + wm * 32 + mi * 16 + gid;
            const int col = n0 + wn * 64 + ni * 8 + tig * 2;
            float2 bb = *(const float2*)(bias + col);
            *(float2*)(C + (size_t)row * NTVR + col) =
                make_float2(acc[mi][ni][0] + bb.x, acc[mi][ni][1] + bb.y);
            *(float2*)(C + (size_t)(row + 8) * NTVR + col) =
                make_float2(acc[mi][ni][2] + bb.x, acc[mi][ni][3] + bb.y);
        }
    }
}

// ---------------- per-batch attention + epilogue ----------------
__global__ __launch_bounds__(256, 2)
void attn_k(const float* __restrict__ X, const float* __restrict__ TVR,
            const float* __restrict__ gv, float* __restrict__ OUT)
{
    __shared__ float sc[64][65];
    __shared__ __align__(16) float sbuf[64 * 68];
    __shared__ float gsh[512];
    __shared__ float wpart[4][64];
    __shared__ float wsh[64];

    const int b = blockIdx.x;
    const float* Xb   = X   + (size_t)b * 64 * 512;
    const float* TVRb = TVR + (size_t)b * 64 * NTVR;
    float*       Ob   = OUT + (size_t)b * 64 * 512;

    const int tid = threadIdx.x;
    const int tx = tid & 15, ty = tid >> 4;

    gsh[tid]       = gv[tid];
    gsh[tid + 256] = gv[tid + 256];
    __syncthreads();

    {
        const int r = tid & 63, p = tid >> 6;
        const float* xr = Xb + r * 512 + p * 128;
        const float* gp = gsh + p * 128;
        float s = 0.f;
#pragma unroll 8
        for (int d = 0; d < 128; ++d) s += xr[d] * gp[d];
        wpart[p][r] = s;
    }

    float acc[4][4];
#pragma unroll
    for (int i = 0; i < 4; ++i)
#pragma unroll
        for (int j = 0; j < 4; ++j) acc[i][j] = 0.f;

    float* TT = sbuf;
    float* XT = sbuf + 32 * 68;

    for (int kt = 0; kt < 16; ++kt) {
        __syncthreads();
#pragma unroll
        for (int q = 0; q < 2; ++q) {
            const int idx = tid + q * 256;
            const int row = idx >> 3;
            const int c4  = (idx & 7) * 4;
            float4 v = *(const float4*)(TVRb + row * NTVR + kt * 32 + c4);
            TT[(c4 + 0) * 68 + row] = v.x; TT[(c4 + 1) * 68 + row] = v.y;
            TT[(c4 + 2) * 68 + row] = v.z; TT[(c4 + 3) * 68 + row] = v.w;
            float4 u = *(const float4*)(Xb + row * 512 + kt * 32 + c4);
            XT[(c4 + 0) * 68 + row] = u.x; XT[(c4 + 1) * 68 + row] = u.y;
            XT[(c4 + 2) * 68 + row] = u.z; XT[(c4 + 3) * 68 + row] = u.w;
        }
        __syncthreads();
#pragma unroll
        for (int k = 0; k < 32; ++k) {
            float4 av = *(const float4*)&TT[k * 68 + ty * 4];
            float4 bv = *(const float4*)&XT[k * 68 + tx * 4];
            float a[4]  = {av.x, av.y, av.z, av.w};
            float bb[4] = {bv.x, bv.y, bv.z, bv.w};
#pragma unroll
            for (int i = 0; i < 4; ++i)
#pragma unroll
                for (int j = 0; j < 4; ++j) acc[i][j] += a[i] * bb[j];
        }
    }
    __syncthreads();
    if (tid < 64)
        wsh[tid] = wpart[0][tid] + wpart[1][tid] + wpart[2][tid] + wpart[3][tid];
    __syncthreads();
#pragma unroll
    for (int i = 0; i < 4; ++i)
#pragma unroll
        for (int j = 0; j < 4; ++j)
            sc[ty * 4 + i][tx * 4 + j] = acc[i][j] + wsh[tx * 4 + j];
    __syncthreads();

    if (tid < 64) {
        float m = -1e30f;
#pragma unroll 8
        for (int c = 0; c < 64; ++c) m = fmaxf(m, sc[tid][c]);
        float s = 0.f;
#pragma unroll 8
        for (int c = 0; c < 64; ++c) { float e = expf(sc[tid][c] - m); sc[tid][c] = e; s += e; }
        const float inv = 1.f / s;
#pragma unroll 8
        for (int c = 0; c < 64; ++c) sc[tid][c] *= inv;
    }

    float* VOt = sbuf;
    for (int nt = 0; nt < 8; ++nt) {
        __syncthreads();
#pragma unroll
        for (int q = 0; q < 4; ++q) {
            const int idx = tid + q * 256;
            const int row = idx >> 4;
            const int c4  = (idx & 15) * 4;
            *(float4*)&VOt[row * 68 + c4] =
                *(const float4*)(TVRb + row * NTVR + 512 + nt * 64 + c4);
        }
        __syncthreads();

        float o[4][4];
#pragma unroll
        for (int i = 0; i < 4; ++i)
#pragma unroll
            for (int j = 0; j < 4; ++j) o[i][j] = 0.f;

#pragma unroll
        for (int k = 0; k < 64; ++k) {
            float a0 = sc[ty * 4 + 0][k];
            float a1 = sc[ty * 4 + 1][k];
            float a2 = sc[ty * 4 + 2][k];
            float a3 = sc[ty * 4 + 3][k];
            float4 bv = *(const float4*)&VOt[k * 68 + tx * 4];
            o[0][0] += a0 * bv.x; o[0][1] += a0 * bv.y; o[0][2] += a0 * bv.z; o[0][3] += a0 * bv.w;
            o[1][0] += a1 * bv.x; o[1][1] += a1 * bv.y; o[1][2] += a1 * bv.z; o[1][3] += a1 * bv.w;
            o[2][0] += a2 * bv.x; o[2][1] += a2 * bv.y; o[2][2] += a2 * bv.z; o[2][3] += a2 * bv.w;
            o[3][0] += a3 * bv.x; o[3][1] += a3 * bv.y; o[3][2] += a3 * bv.z; o[3][3] += a3 * bv.w;
        }
#pragma unroll
        for (int i = 0; i < 4; ++i) {
            const int row = ty * 4 + i;
            float4 rv = *(const float4*)(TVRb + row * NTVR + 1024 + nt * 64 + tx * 4);
            float4 ov;
            ov.x = fmaxf(o[i][0] + rv.x, 0.f);
            ov.y = fmaxf(o[i][1] + rv.y, 0.f);
            ov.z = fmaxf(o[i][2] + rv.z, 0.f);
            ov.w = fmaxf(o[i][3] + rv.w, 0.f);
            *(float4*)(Ob + row * 512 + nt * 64 + tx * 4) = ov;
        }
    }
}

// ---------------- launch ----------------
extern "C" void kernel_launch(void* const* d_in, const int* in_sizes, int n_in,
                              void* d_out, int out_size)
{
    const float* inp = (const float*)d_in[0];
    const float* Win = (const float*)d_in[1];
    const float* bin = (const float*)d_in[2];
    const float* Wq  = (const float*)d_in[3];
    const float* bq  = (const float*)d_in[4];
    const float* Wk  = (const float*)d_in[5];
    // d_in[6] = b_k : provably unused (row-constant, drops out of softmax)
    const float* Wv  = (const float*)d_in[7];
    const float* bv  = (const float*)d_in[8];
    const float* Wr  = (const float*)d_in[9];
    const float* br  = (const float*)d_in[10];
    const float* Wo  = (const float*)d_in[11];
    const float* bo  = (const float*)d_in[12];
    float* out = (float*)d_out;

    float *X, *TVR, *Wqk, *Wvo, *Wro, *gv, *bias2;
    __nv_bfloat16 *Ihi, *Ilo, *WinT_hi, *WinT_lo;
    __half *Xf16, *Wb_hi;
    cudaGetSymbolAddress((void**)&X,       g_X);
    cudaGetSymbolAddress((void**)&TVR,     g_TVR);
    cudaGetSymbolAddress((void**)&Wqk,     g_Wqk);
    cudaGetSymbolAddress((void**)&Wvo,     g_Wvo);
    cudaGetSymbolAddress((void**)&Wro,     g_Wro);
    cudaGetSymbolAddress((void**)&gv,      g_gv);
    cudaGetSymbolAddress((void**)&bias2,   g_bias2);
    cudaGetSymbolAddress((void**)&Xf16,    g_Xf16);
    cudaGetSymbolAddress((void**)&Ihi,     g_Ihi);
    cudaGetSymbolAddress((void**)&Ilo,     g_Ilo);
    cudaGetSymbolAddress((void**)&WinT_hi, g_WinT_hi);
    cudaGetSymbolAddress((void**)&WinT_lo, g_WinT_lo);
    cudaGetSymbolAddress((void**)&Wb_hi,   g_Wb_hi);

    cudaFuncSetAttribute(gemm_x,   cudaFuncAttributeMaxDynamicSharedMemorySize, MG_SMEM);
    cudaFuncSetAttribute(gemm_tvr, cudaFuncAttributeMaxDynamicSharedMemorySize, MG_SMEM);

    const dim3 bs(256);

    // weight-space precompute (fp32-exact, small)
    vec_pre_k<<<1, 512>>>(Wo, bv, br, bo, Wk, bq, gv, bias2);
    wpre_k<<<dim3(8, 8, 3), bs>>>(Wq, Wk, Wv, Wr, Wo, Wqk, Wvo, Wro);

    // transpose + convert weights
    dim3 tb32(32, 32), tg(16, 16);
    tsplit_bf_k<<<tg, tb32>>>(Win, WinT_hi, WinT_lo);
    t_f16_k<<<tg, tb32>>>(Wqk, Wb_hi, 0);
    t_f16_k<<<tg, tb32>>>(Wvo, Wb_hi, 512);
    t_f16_k<<<tg, tb32>>>(Wro, Wb_hi, 1024);

    // split activations (bf16 hi/lo)
    const int n4 = MTOT * D_DIM / 4;
    split_k<<<(n4 + 255) / 256, 256>>>(inp, Ihi, Ilo, n4);

    // big GEMMs on tensor cores
    gemm_x  <<<dim3(4, 256),  bs, MG_SMEM>>>(Ihi, Ilo, WinT_hi, WinT_lo, bin, X, Xf16);
    gemm_tvr<<<dim3(12, 256), bs, MG_SMEM>>>(Xf16, Wb_hi, bias2, TVR);

    // attention + epilogue
    attn_k<<<NBATCH, bs>>>(X, TVR, gv, out);
}

// round 7
// speedup vs baseline: 1.5432x; 1.0980x over previous
#include <cuda_runtime.h>
#include <cuda_fp16.h>
#include <cstdint>
#include <cstddef>

#define D_DIM 512
#define AGENTS 64
#define NBATCH 512
#define MTOT (NBATCH * AGENTS)   // 32768
#define NTVR 1536

// ---------------- scratch (device globals: allocation-free) ----------------
__device__ __align__(128) float   g_X   [MTOT * D_DIM];
__device__ __align__(128) __half  g_Xf16[MTOT * D_DIM];
__device__ __align__(128) __half  g_If16[MTOT * D_DIM];
__device__ __align__(128) float   g_TVR [MTOT * NTVR];
__device__ __align__(128) float   g_Wqk [D_DIM * D_DIM];
__device__ __align__(128) float   g_Wvo [D_DIM * D_DIM];
__device__ __align__(128) float   g_Wro [D_DIM * D_DIM];
__device__ __align__(128) __half  g_WinT[D_DIM * D_DIM];
__device__ __align__(128) __half  g_Wb  [NTVR * D_DIM];
__device__ __align__(128) float   g_gv  [D_DIM];
__device__ __align__(128) float   g_bias2[NTVR];

#define SWZ(o) ((o) ^ (((o) >> 3) & 0x70))

__device__ __forceinline__ uint32_t smem_u32(const void* p) {
    uint32_t a;
    asm("{ .reg .u64 t; cvta.to.shared.u64 t, %1; cvt.u32.u64 %0, t; }" : "=r"(a) : "l"(p));
    return a;
}
__device__ __forceinline__ void ldsm4(uint32_t* r, uint32_t addr) {
    asm volatile("ldmatrix.sync.aligned.m8n8.x4.shared.b16 {%0,%1,%2,%3}, [%4];"
                 : "=r"(r[0]), "=r"(r[1]), "=r"(r[2]), "=r"(r[3]) : "r"(addr));
}
__device__ __forceinline__ void mma_f16(float* d, const uint32_t* a, uint32_t b0, uint32_t b1) {
    asm volatile(
        "mma.sync.aligned.m16n8k16.row.col.f32.f16.f16.f32 "
        "{%0,%1,%2,%3}, {%4,%5,%6,%7}, {%8,%9}, {%0,%1,%2,%3};"
        : "+f"(d[0]), "+f"(d[1]), "+f"(d[2]), "+f"(d[3])
        : "r"(a[0]), "r"(a[1]), "r"(a[2]), "r"(a[3]), "r"(b0), "r"(b1));
}
__device__ __forceinline__ void cpasync16(uint32_t dst, const void* src) {
    asm volatile("cp.async.cg.shared.global [%0], [%1], 16;" :: "r"(dst), "l"(src));
}
#define CP_COMMIT() asm volatile("cp.async.commit_group;" ::: "memory")
#define CP_WAIT(N)  asm volatile("cp.async.wait_group " #N ";" ::: "memory")

// ---------------- convert inputs fp32 -> fp16 ----------------
__global__ void f16conv_k(const float* __restrict__ src, __half* __restrict__ dst, int n4) {
    int i = blockIdx.x * blockDim.x + threadIdx.x;
    if (i >= n4) return;
    float4 v = ((const float4*)src)[i];
    __half h0 = __float2half_rn(v.x), h1 = __float2half_rn(v.y);
    __half h2 = __float2half_rn(v.z), h3 = __float2half_rn(v.w);
    uint32_t a = (uint32_t)__half_as_ushort(h0) | ((uint32_t)__half_as_ushort(h1) << 16);
    uint32_t b = (uint32_t)__half_as_ushort(h2) | ((uint32_t)__half_as_ushort(h3) << 16);
    ((uint2*)dst)[i] = make_uint2(a, b);
}

// ---------------- transpose weights to fp16: W[K,N] -> Wt[n_off+n][k] ----------------
__global__ void t_f16_k(const float* __restrict__ W, __half* __restrict__ T, int n_off) {
    __shared__ float tle[32][33];
    int tx = threadIdx.x, ty = threadIdx.y;
    int n0 = blockIdx.x * 32, k0 = blockIdx.y * 32;
    tle[ty][tx] = W[(size_t)(k0 + ty) * 512 + n0 + tx];
    __syncthreads();
    T[(size_t)(n_off + n0 + ty) * 512 + k0 + tx] = __float2half_rn(tle[tx][ty]);
}

// ---------------- vector precompute: gv = Wk@bq ; bias2 = {0, bv@Wo, br@Wo+bo} ----------------
__global__ void vec_pre_k(const float* __restrict__ Wo,
                          const float* __restrict__ bv,
                          const float* __restrict__ br,
                          const float* __restrict__ bo,
                          const float* __restrict__ Wk,
                          const float* __restrict__ bq,
                          float* __restrict__ gv,
                          float* __restrict__ bias2) {
    int j = threadIdx.x;
    if (j < D_DIM) {
        float s1 = 0.f, s2 = 0.f;
        for (int d = 0; d < D_DIM; ++d) {
            float w = Wo[d * D_DIM + j];
            s1 += bv[d] * w;
            s2 += br[d] * w;
        }
        float s3 = 0.f;
        const float* wk = Wk + (size_t)j * D_DIM;
        for (int t = 0; t < D_DIM; ++t) s3 += wk[t] * bq[t];
        gv[j] = s3;
        bias2[j] = 0.f;
        bias2[512 + j] = s1;
        bias2[1024 + j] = s2 + bo[j];
    }
}

// ---------------- weight precompute: 3 fp32 512x512x512 GEMMs, 64x64 tiles ----------------
__global__ __launch_bounds__(256)
void wpre_k(const float* __restrict__ Wq, const float* __restrict__ Wk,
            const float* __restrict__ Wv, const float* __restrict__ Wr,
            const float* __restrict__ Wo,
            float* __restrict__ Wqk, float* __restrict__ Wvo, float* __restrict__ Wro) {
    const int z = blockIdx.z;
    const float* A = (z == 0) ? Wq : ((z == 1) ? Wv : Wr);
    const float* B = (z == 0) ? Wk : Wo;
    float* C = (z == 0) ? Wqk : ((z == 1) ? Wvo : Wro);
    const bool transb = (z == 0);

    __shared__ __align__(16) float As[32][72];
    __shared__ __align__(16) float Bs[32][72];
    const int t = threadIdx.x;
    const int tx = t & 15, ty = t >> 4;
    const int m0 = blockIdx.y * 64, n0 = blockIdx.x * 64;

    float acc[4][4];
#pragma unroll
    for (int i = 0; i < 4; ++i)
#pragma unroll
        for (int j = 0; j < 4; ++j) acc[i][j] = 0.f;

    for (int kt = 0; kt < 16; ++kt) {
        __syncthreads();
#pragma unroll
        for (int i = 0; i < 2; ++i) {
            const int idx = t + i * 256;
            const int row = idx >> 3, c4 = (idx & 7) * 4;
            float4 v = *(const float4*)(A + (size_t)(m0 + row) * 512 + kt * 32 + c4);
            As[c4 + 0][row] = v.x; As[c4 + 1][row] = v.y;
            As[c4 + 2][row] = v.z; As[c4 + 3][row] = v.w;
        }
        if (transb) {
#pragma unroll
            for (int i = 0; i < 2; ++i) {
                const int idx = t + i * 256;
                const int row = idx >> 3, c4 = (idx & 7) * 4;
                float4 v = *(const float4*)(B + (size_t)(n0 + row) * 512 + kt * 32 + c4);
                Bs[c4 + 0][row] = v.x; Bs[c4 + 1][row] = v.y;
                Bs[c4 + 2][row] = v.z; Bs[c4 + 3][row] = v.w;
            }
        } else {
#pragma unroll
            for (int i = 0; i < 2; ++i) {
                const int idx = t + i * 256;
                const int kr = idx >> 4, c4 = (idx & 15) * 4;
                float4 v = *(const float4*)(B + (size_t)(kt * 32 + kr) * 512 + n0 + c4);
                *(float4*)&Bs[kr][c4] = v;
            }
        }
        __syncthreads();
#pragma unroll
        for (int k = 0; k < 32; ++k) {
            float4 av = *(const float4*)&As[k][ty * 4];
            float4 bv = *(const float4*)&Bs[k][tx * 4];
            float a[4] = {av.x, av.y, av.z, av.w};
            float b[4] = {bv.x, bv.y, bv.z, bv.w};
#pragma unroll
            for (int i = 0; i < 4; ++i)
#pragma unroll
                for (int j = 0; j < 4; ++j) acc[i][j] += a[i] * b[j];
        }
    }
#pragma unroll
    for (int i = 0; i < 4; ++i) {
        float4 o = {acc[i][0], acc[i][1], acc[i][2], acc[i][3]};
        *(float4*)(C + (size_t)(m0 + ty * 4 + i) * 512 + n0 + tx * 4) = o;
    }
}

// ---------------- fp16 GEMM: C[M,Ntot] = A[M,512] @ B^T[Ntot,512] + bias ----------------
// CTA 128x128, BK=64, 8 chunks, 8 warps (4x2), warp tile 32x64, 2-stage cp.async.
#define MG_SMEM 65536

template<bool RELU, bool F16OUT>
__global__ __launch_bounds__(256)
void gemm_f16(const __half* __restrict__ A, const __half* __restrict__ B,
              const float* __restrict__ bias, float* __restrict__ C,
              __half* __restrict__ Cf16, int Ntot)
{
    extern __shared__ char sm[];
    const uint32_t smA = smem_u32(sm);
    const uint32_t smB = smA + 32768;

    const int t = threadIdx.x;
    const int wid = t >> 5, l = t & 31;
    const int wm = wid >> 1, wn = wid & 1;
    const int m0 = blockIdx.y * 128, n0 = blockIdx.x * 128;

    const int arow = l & 15, acol = l >> 4;
    const int brow = (l & 7) + ((l >> 4) & 1) * 8, bcol = (l >> 3) & 1;
    const int lrow = t >> 3, lcg = t & 7;

    float acc[2][8][4];
#pragma unroll
    for (int mi = 0; mi < 2; ++mi)
#pragma unroll
        for (int ni = 0; ni < 8; ++ni)
#pragma unroll
            for (int q = 0; q < 4; ++q) acc[mi][ni][q] = 0.f;

    auto load_chunk = [&](int c, int s) {
        const int kk = c * 64;
        const uint32_t ab = smA + s * 16384;
        const uint32_t bb = smB + s * 16384;
#pragma unroll
        for (int i = 0; i < 4; ++i) {
            const int row = lrow + i * 32;
            const uint32_t off = SWZ((uint32_t)(row * 128 + lcg * 16));
            cpasync16(ab + off, A + (size_t)(m0 + row) * 512 + kk + lcg * 8);
            cpasync16(bb + off, B + (size_t)(n0 + row) * 512 + kk + lcg * 8);
        }
        CP_COMMIT();
    };

    auto compute = [&](int s) {
        const uint32_t ab = smA + s * 16384;
        const uint32_t bb = smB + s * 16384;
#pragma unroll
        for (int ks = 0; ks < 4; ++ks) {
            uint32_t a[2][4];
#pragma unroll
            for (int mi = 0; mi < 2; ++mi) {
                const int row = wm * 32 + mi * 16 + arow;
                ldsm4(a[mi], ab + SWZ((uint32_t)(row * 128 + (ks * 2 + acol) * 16)));
            }
#pragma unroll
            for (int nb = 0; nb < 4; ++nb) {
                const int row = wn * 64 + nb * 16 + brow;
                uint32_t b[4];
                ldsm4(b, bb + SWZ((uint32_t)(row * 128 + (ks * 2 + bcol) * 16)));
                mma_f16(acc[0][nb * 2],     a[0], b[0], b[1]);
                mma_f16(acc[1][nb * 2],     a[1], b[0], b[1]);
                mma_f16(acc[0][nb * 2 + 1], a[0], b[2], b[3]);
                mma_f16(acc[1][nb * 2 + 1], a[1], b[2], b[3]);
            }
        }
    };

    load_chunk(0, 0);
    load_chunk(1, 1);
    CP_WAIT(1);
    __syncthreads();

    for (int c = 0; c < 8; ++c) {
        const int s = c & 1;
        compute(s);
        if (c == 7) break;
        __syncthreads();
        if (c + 2 < 8) { load_chunk(c + 2, s); CP_WAIT(1); }
        else           { CP_WAIT(0); }
        __syncthreads();
    }

    const int gid = l >> 2, tig = l & 3;
#pragma unroll
    for (int mi = 0; mi < 2; ++mi) {
#pragma unroll
        for (int ni = 0; ni < 8; ++ni) {
            const int row = m0 + wm * 32 + mi * 16 + gid;
            const int col = n0 + wn * 64 + ni * 8 + tig * 2;
            float2 bb = *(const float2*)(bias + col);
            float v0 = acc[mi][ni][0] + bb.x;
            float v1 = acc[mi][ni][1] + bb.y;
            float v2 = acc[mi][ni][2] + bb.x;
            float v3 = acc[mi][ni][3] + bb.y;
            if (RELU) {
                v0 = fmaxf(v0, 0.f); v1 = fmaxf(v1, 0.f);
                v2 = fmaxf(v2, 0.f); v3 = fmaxf(v3, 0.f);
            }
            *(float2*)(C + (size_t)row * Ntot + col)       = make_float2(v0, v1);
            *(float2*)(C + (size_t)(row + 8) * Ntot + col) = make_float2(v2, v3);
            if (F16OUT) {
                __half h0 = __float2half_rn(v0), h1 = __float2half_rn(v1);
                __half h2 = __float2half_rn(v2), h3 = __float2half_rn(v3);
                ushort2 u0 = {__half_as_ushort(h0), __half_as_ushort(h1)};
                ushort2 u1 = {__half_as_ushort(h2), __half_as_ushort(h3)};
                *(ushort2*)(Cf16 + (size_t)row * 512 + col)       = u0;
                *(ushort2*)(Cf16 + (size_t)(row + 8) * 512 + col) = u1;
            }
        }
    }
}

// ---------------- per-batch attention + epilogue ----------------
__global__ __launch_bounds__(256, 2)
void attn_k(const float* __restrict__ X, const float* __restrict__ TVR,
            const float* __restrict__ gv, float* __restrict__ OUT)
{
    __shared__ float sc[64][65];
    __shared__ __align__(16) float sbuf[64 * 68];
    __shared__ float gsh[512];
    __shared__ float wpart[4][64];
    __shared__ float wsh[64];

    const int b = blockIdx.x;
    const float* Xb   = X   + (size_t)b * 64 * 512;
    const float* TVRb = TVR + (size_t)b * 64 * NTVR;
    float*       Ob   = OUT + (size_t)b * 64 * 512;

    const int tid = threadIdx.x;
    const int tx = tid & 15, ty = tid >> 4;

    gsh[tid]       = gv[tid];
    gsh[tid + 256] = gv[tid + 256];
    __syncthreads();

    {
        const int r = tid & 63, p = tid >> 6;
        const float* xr = Xb + r * 512 + p * 128;
        const float* gp = gsh + p * 128;
        float s = 0.f;
#pragma unroll 8
        for (int d = 0; d < 128; ++d) s += xr[d] * gp[d];
        wpart[p][r] = s;
    }

    float acc[4][4];
#pragma unroll
    for (int i = 0; i < 4; ++i)
#pragma unroll
        for (int j = 0; j < 4; ++j) acc[i][j] = 0.f;

    float* TT = sbuf;
    float* XT = sbuf + 32 * 68;

    for (int kt = 0; kt < 16; ++kt) {
        __syncthreads();
#pragma unroll
        for (int q = 0; q < 2; ++q) {
            const int idx = tid + q * 256;
            const int row = idx >> 3;
            const int c4  = (idx & 7) * 4;
            float4 v = *(const float4*)(TVRb + row * NTVR + kt * 32 + c4);
            TT[(c4 + 0) * 68 + row] = v.x; TT[(c4 + 1) * 68 + row] = v.y;
            TT[(c4 + 2) * 68 + row] = v.z; TT[(c4 + 3) * 68 + row] = v.w;
            float4 u = *(const float4*)(Xb + row * 512 + kt * 32 + c4);
            XT[(c4 + 0) * 68 + row] = u.x; XT[(c4 + 1) * 68 + row] = u.y;
            XT[(c4 + 2) * 68 + row] = u.z; XT[(c4 + 3) * 68 + row] = u.w;
        }
        __syncthreads();
#pragma unroll
        for (int k = 0; k < 32; ++k) {
            float4 av = *(const float4*)&TT[k * 68 + ty * 4];
            float4 bv = *(const float4*)&XT[k * 68 + tx * 4];
            float a[4]  = {av.x, av.y, av.z, av.w};
            float bb[4] = {bv.x, bv.y, bv.z, bv.w};
#pragma unroll
            for (int i = 0; i < 4; ++i)
#pragma unroll
                for (int j = 0; j < 4; ++j) acc[i][j] += a[i] * bb[j];
        }
    }
    __syncthreads();
    if (tid < 64)
        wsh[tid] = wpart[0][tid] + wpart[1][tid] + wpart[2][tid] + wpart[3][tid];
    __syncthreads();
#pragma unroll
    for (int i = 0; i < 4; ++i)
#pragma unroll
        for (int j = 0; j < 4; ++j)
            sc[ty * 4 + i][tx * 4 + j] = acc[i][j] + wsh[tx * 4 + j];
    __syncthreads();

    if (tid < 64) {
        float m = -1e30f;
#pragma unroll 8
        for (int c = 0; c < 64; ++c) m = fmaxf(m, sc[tid][c]);
        float s = 0.f;
#pragma unroll 8
        for (int c = 0; c < 64; ++c) { float e = expf(sc[tid][c] - m); sc[tid][c] = e; s += e; }
        const float inv = 1.f / s;
#pragma unroll 8
        for (int c = 0; c < 64; ++c) sc[tid][c] *= inv;
    }

    float* VOt = sbuf;
    for (int nt = 0; nt < 8; ++nt) {
        __syncthreads();
#pragma unroll
        for (int q = 0; q < 4; ++q) {
            const int idx = tid + q * 256;
            const int row = idx >> 4;
            const int c4  = (idx & 15) * 4;
            *(float4*)&VOt[row * 68 + c4] =
                *(const float4*)(TVRb + row * NTVR + 512 + nt * 64 + c4);
        }
        __syncthreads();

        float o[4][4];
#pragma unroll
        for (int i = 0; i < 4; ++i)
#pragma unroll
            for (int j = 0; j < 4; ++j) o[i][j] = 0.f;

#pragma unroll
        for (int k = 0; k < 64; ++k) {
            float a0 = sc[ty * 4 + 0][k];
            float a1 = sc[ty * 4 + 1][k];
            float a2 = sc[ty * 4 + 2][k];
            float a3 = sc[ty * 4 + 3][k];
            float4 bv = *(const float4*)&VOt[k * 68 + tx * 4];
            o[0][0] += a0 * bv.x; o[0][1] += a0 * bv.y; o[0][2] += a0 * bv.z; o[0][3] += a0 * bv.w;
            o[1][0] += a1 * bv.x; o[1][1] += a1 * bv.y; o[1][2] += a1 * bv.z; o[1][3] += a1 * bv.w;
            o[2][0] += a2 * bv.x; o[2][1] += a2 * bv.y; o[2][2] += a2 * bv.z; o[2][3] += a2 * bv.w;
            o[3][0] += a3 * bv.x; o[3][1] += a3 * bv.y; o[3][2] += a3 * bv.z; o[3][3] += a3 * bv.w;
        }
#pragma unroll
        for (int i = 0; i < 4; ++i) {
            const int row = ty * 4 + i;
            float4 rv = *(const float4*)(TVRb + row * NTVR + 1024 + nt * 64 + tx * 4);
            float4 ov;
            ov.x = fmaxf(o[i][0] + rv.x, 0.f);
            ov.y = fmaxf(o[i][1] + rv.y, 0.f);
            ov.z = fmaxf(o[i][2] + rv.z, 0.f);
            ov.w = fmaxf(o[i][3] + rv.w, 0.f);
            *(float4*)(Ob + row * 512 + nt * 64 + tx * 4) = ov;
        }
    }
}

// ---------------- launch ----------------
extern "C" void kernel_launch(void* const* d_in, const int* in_sizes, int n_in,
                              void* d_out, int out_size)
{
    const float* inp = (const float*)d_in[0];
    const float* Win = (const float*)d_in[1];
    const float* bin = (const float*)d_in[2];
    const float* Wq  = (const float*)d_in[3];
    const float* bq  = (const float*)d_in[4];
    const float* Wk  = (const float*)d_in[5];
    // d_in[6] = b_k : provably unused (row-constant, drops out of softmax)
    const float* Wv  = (const float*)d_in[7];
    const float* bv  = (const float*)d_in[8];
    const float* Wr  = (const float*)d_in[9];
    const float* br  = (const float*)d_in[10];
    const float* Wo  = (const float*)d_in[11];
    const float* bo  = (const float*)d_in[12];
    float* out = (float*)d_out;

    float *X, *TVR, *Wqk, *Wvo, *Wro, *gv, *bias2;
    __half *Xf16, *If16, *WinT, *Wb;
    cudaGetSymbolAddress((void**)&X,     g_X);
    cudaGetSymbolAddress((void**)&TVR,   g_TVR);
    cudaGetSymbolAddress((void**)&Wqk,   g_Wqk);
    cudaGetSymbolAddress((void**)&Wvo,   g_Wvo);
    cudaGetSymbolAddress((void**)&Wro,   g_Wro);
    cudaGetSymbolAddress((void**)&gv,    g_gv);
    cudaGetSymbolAddress((void**)&bias2, g_bias2);
    cudaGetSymbolAddress((void**)&Xf16,  g_Xf16);
    cudaGetSymbolAddress((void**)&If16,  g_If16);
    cudaGetSymbolAddress((void**)&WinT,  g_WinT);
    cudaGetSymbolAddress((void**)&Wb,    g_Wb);

    cudaFuncSetAttribute(gemm_f16<true,  true >, cudaFuncAttributeMaxDynamicSharedMemorySize, MG_SMEM);
    cudaFuncSetAttribute(gemm_f16<false, false>, cudaFuncAttributeMaxDynamicSharedMemorySize, MG_SMEM);

    const dim3 bs(256);

    // weight-space precompute (fp32-exact, small)
    vec_pre_k<<<1, 512>>>(Wo, bv, br, bo, Wk, bq, gv, bias2);
    wpre_k<<<dim3(8, 8, 3), bs>>>(Wq, Wk, Wv, Wr, Wo, Wqk, Wvo, Wro);

    // transpose + convert weights to fp16
    dim3 tb32(32, 32), tg(16, 16);
    t_f16_k<<<tg, tb32>>>(Win, WinT, 0);
    t_f16_k<<<tg, tb32>>>(Wqk, Wb, 0);
    t_f16_k<<<tg, tb32>>>(Wvo, Wb, 512);
    t_f16_k<<<tg, tb32>>>(Wro, Wb, 1024);

    // convert activations to fp16
    const int n4 = MTOT * D_DIM / 4;
    f16conv_k<<<(n4 + 255) / 256, 256>>>(inp, If16, n4);

    // big GEMMs on tensor cores (fp16 single-term)
    gemm_f16<true,  true ><<<dim3(4, 256),  bs, MG_SMEM>>>(If16, WinT, bin, X, Xf16, 512);
    gemm_f16<false, false><<<dim3(12, 256), bs, MG_SMEM>>>(Xf16, Wb, bias2, TVR, nullptr, NTVR);

    // attention + epilogue
    attn_k<<<NBATCH, bs>>>(X, TVR, gv, out);
}

// round 8
// speedup vs baseline: 1.9317x; 1.2518x over previous
#include <cuda_runtime.h>
#include <cuda_fp16.h>
#include <cstdint>
#include <cstddef>

#define D_DIM 512
#define AGENTS 64
#define NBATCH 512
#define MTOT (NBATCH * AGENTS)   // 32768
#define NTVR 1536

// ---------------- scratch (device globals: allocation-free) ----------------
__device__ __align__(128) __half  g_Xf16[MTOT * D_DIM];
__device__ __align__(128) __half  g_If16[MTOT * D_DIM];
__device__ __align__(128) __half  g_TVR [MTOT * NTVR];
__device__ __align__(128) float   g_Wqk [D_DIM * D_DIM];
__device__ __align__(128) float   g_Wvo [D_DIM * D_DIM];
__device__ __align__(128) float   g_Wro [D_DIM * D_DIM];
__device__ __align__(128) __half  g_WinT[D_DIM * D_DIM];
__device__ __align__(128) __half  g_Wb  [NTVR * D_DIM];
__device__ __align__(128) float   g_gv  [D_DIM];
__device__ __align__(128) float   g_bias2[NTVR];

#define SWZ(o) ((o) ^ (((o) >> 3) & 0x70))

__device__ __forceinline__ uint32_t smem_u32(const void* p) {
    uint32_t a;
    asm("{ .reg .u64 t; cvta.to.shared.u64 t, %1; cvt.u32.u64 %0, t; }" : "=r"(a) : "l"(p));
    return a;
}
__device__ __forceinline__ void ldsm4(uint32_t* r, uint32_t addr) {
    asm volatile("ldmatrix.sync.aligned.m8n8.x4.shared.b16 {%0,%1,%2,%3}, [%4];"
                 : "=r"(r[0]), "=r"(r[1]), "=r"(r[2]), "=r"(r[3]) : "r"(addr));
}
__device__ __forceinline__ void ldsm4t(uint32_t* r, uint32_t addr) {
    asm volatile("ldmatrix.sync.aligned.m8n8.x4.trans.shared.b16 {%0,%1,%2,%3}, [%4];"
                 : "=r"(r[0]), "=r"(r[1]), "=r"(r[2]), "=r"(r[3]) : "r"(addr));
}
__device__ __forceinline__ void mma_f16(float* d, const uint32_t* a, uint32_t b0, uint32_t b1) {
    asm volatile(
        "mma.sync.aligned.m16n8k16.row.col.f32.f16.f16.f32 "
        "{%0,%1,%2,%3}, {%4,%5,%6,%7}, {%8,%9}, {%0,%1,%2,%3};"
        : "+f"(d[0]), "+f"(d[1]), "+f"(d[2]), "+f"(d[3])
        : "r"(a[0]), "r"(a[1]), "r"(a[2]), "r"(a[3]), "r"(b0), "r"(b1));
}
__device__ __forceinline__ void cpasync16(uint32_t dst, const void* src) {
    asm volatile("cp.async.cg.shared.global [%0], [%1], 16;" :: "r"(dst), "l"(src));
}
#define CP_COMMIT() asm volatile("cp.async.commit_group;" ::: "memory")
#define CP_WAIT(N)  asm volatile("cp.async.wait_group " #N ";" ::: "memory")

// ---------------- convert inputs fp32 -> fp16 ----------------
__global__ void f16conv_k(const float* __restrict__ src, __half* __restrict__ dst, int n4) {
    int i = blockIdx.x * blockDim.x + threadIdx.x;
    if (i >= n4) return;
    float4 v = ((const float4*)src)[i];
    __half h0 = __float2half_rn(v.x), h1 = __float2half_rn(v.y);
    __half h2 = __float2half_rn(v.z), h3 = __float2half_rn(v.w);
    uint32_t a = (uint32_t)__half_as_ushort(h0) | ((uint32_t)__half_as_ushort(h1) << 16);
    uint32_t b = (uint32_t)__half_as_ushort(h2) | ((uint32_t)__half_as_ushort(h3) << 16);
    ((uint2*)dst)[i] = make_uint2(a, b);
}

// ---------------- transpose weights to fp16: W[K,N] -> Wt[n_off+n][k] ----------------
__global__ void t_f16_k(const float* __restrict__ W, __half* __restrict__ T, int n_off) {
    __shared__ float tle[32][33];
    int tx = threadIdx.x, ty = threadIdx.y;
    int n0 = blockIdx.x * 32, k0 = blockIdx.y * 32;
    tle[ty][tx] = W[(size_t)(k0 + ty) * 512 + n0 + tx];
    __syncthreads();
    T[(size_t)(n_off + n0 + ty) * 512 + k0 + tx] = __float2half_rn(tle[tx][ty]);
}

// ---------------- vector precompute: gv = Wk@bq ; bias2 = {0, bv@Wo, br@Wo+bo} ----------------
__global__ void vec_pre_k(const float* __restrict__ Wo,
                          const float* __restrict__ bv,
                          const float* __restrict__ br,
                          const float* __restrict__ bo,
                          const float* __restrict__ Wk,
                          const float* __restrict__ bq,
                          float* __restrict__ gv,
                          float* __restrict__ bias2) {
    int j = threadIdx.x;
    if (j < D_DIM) {
        float s1 = 0.f, s2 = 0.f;
        for (int d = 0; d < D_DIM; ++d) {
            float w = Wo[d * D_DIM + j];
            s1 += bv[d] * w;
            s2 += br[d] * w;
        }
        float s3 = 0.f;
        const float* wk = Wk + (size_t)j * D_DIM;
        for (int t = 0; t < D_DIM; ++t) s3 += wk[t] * bq[t];
        gv[j] = s3;
        bias2[j] = 0.f;
        bias2[512 + j] = s1;
        bias2[1024 + j] = s2 + bo[j];
    }
}

// ---------------- weight precompute: 3 fp32 512x512x512 GEMMs, 64x64 tiles ----------------
__global__ __launch_bounds__(256)
void wpre_k(const float* __restrict__ Wq, const float* __restrict__ Wk,
            const float* __restrict__ Wv, const float* __restrict__ Wr,
            const float* __restrict__ Wo,
            float* __restrict__ Wqk, float* __restrict__ Wvo, float* __restrict__ Wro) {
    const int z = blockIdx.z;
    const float* A = (z == 0) ? Wq : ((z == 1) ? Wv : Wr);
    const float* B = (z == 0) ? Wk : Wo;
    float* C = (z == 0) ? Wqk : ((z == 1) ? Wvo : Wro);
    const bool transb = (z == 0);

    __shared__ __align__(16) float As[32][72];
    __shared__ __align__(16) float Bs[32][72];
    const int t = threadIdx.x;
    const int tx = t & 15, ty = t >> 4;
    const int m0 = blockIdx.y * 64, n0 = blockIdx.x * 64;

    float acc[4][4];
#pragma unroll
    for (int i = 0; i < 4; ++i)
#pragma unroll
        for (int j = 0; j < 4; ++j) acc[i][j] = 0.f;

    for (int kt = 0; kt < 16; ++kt) {
        __syncthreads();
#pragma unroll
        for (int i = 0; i < 2; ++i) {
            const int idx = t + i * 256;
            const int row = idx >> 3, c4 = (idx & 7) * 4;
            float4 v = *(const float4*)(A + (size_t)(m0 + row) * 512 + kt * 32 + c4);
            As[c4 + 0][row] = v.x; As[c4 + 1][row] = v.y;
            As[c4 + 2][row] = v.z; As[c4 + 3][row] = v.w;
        }
        if (transb) {
#pragma unroll
            for (int i = 0; i < 2; ++i) {
                const int idx = t + i * 256;
                const int row = idx >> 3, c4 = (idx & 7) * 4;
                float4 v = *(const float4*)(B + (size_t)(n0 + row) * 512 + kt * 32 + c4);
                Bs[c4 + 0][row] = v.x; Bs[c4 + 1][row] = v.y;
                Bs[c4 + 2][row] = v.z; Bs[c4 + 3][row] = v.w;
            }
        } else {
#pragma unroll
            for (int i = 0; i < 2; ++i) {
                const int idx = t + i * 256;
                const int kr = idx >> 4, c4 = (idx & 15) * 4;
                float4 v = *(const float4*)(B + (size_t)(kt * 32 + kr) * 512 + n0 + c4);
                *(float4*)&Bs[kr][c4] = v;
            }
        }
        __syncthreads();
#pragma unroll
        for (int k = 0; k < 32; ++k) {
            float4 av = *(const float4*)&As[k][ty * 4];
            float4 bv = *(const float4*)&Bs[k][tx * 4];
            float a[4] = {av.x, av.y, av.z, av.w};
            float b[4] = {bv.x, bv.y, bv.z, bv.w};
#pragma unroll
            for (int i = 0; i < 4; ++i)
#pragma unroll
                for (int j = 0; j < 4; ++j) acc[i][j] += a[i] * b[j];
        }
    }
#pragma unroll
    for (int i = 0; i < 4; ++i) {
        float4 o = {acc[i][0], acc[i][1], acc[i][2], acc[i][3]};
        *(float4*)(C + (size_t)(m0 + ty * 4 + i) * 512 + n0 + tx * 4) = o;
    }
}

// ---------------- fp16 GEMM: Cf16[M,Ntot] = A[M,512] @ B^T[Ntot,512] + bias ----------------
// CTA 128x128, BK=64, 8 chunks, 8 warps (4x2), warp tile 32x64, 2-stage cp.async.
#define MG_SMEM 65536

template<bool RELU>
__global__ __launch_bounds__(256)
void gemm_f16(const __half* __restrict__ A, const __half* __restrict__ B,
              const float* __restrict__ bias, __half* __restrict__ Cf16, int Ntot)
{
    extern __shared__ char sm[];
    const uint32_t smA = smem_u32(sm);
    const uint32_t smB = smA + 32768;

    const int t = threadIdx.x;
    const int wid = t >> 5, l = t & 31;
    const int wm = wid >> 1, wn = wid & 1;
    const int m0 = blockIdx.y * 128, n0 = blockIdx.x * 128;

    const int arow = l & 15, acol = l >> 4;
    const int brow = (l & 7) + ((l >> 4) & 1) * 8, bcol = (l >> 3) & 1;
    const int lrow = t >> 3, lcg = t & 7;

    float acc[2][8][4];
#pragma unroll
    for (int mi = 0; mi < 2; ++mi)
#pragma unroll
        for (int ni = 0; ni < 8; ++ni)
#pragma unroll
            for (int q = 0; q < 4; ++q) acc[mi][ni][q] = 0.f;

    auto load_chunk = [&](int c, int s) {
        const int kk = c * 64;
        const uint32_t ab = smA + s * 16384;
        const uint32_t bb = smB + s * 16384;
#pragma unroll
        for (int i = 0; i < 4; ++i) {
            const int row = lrow + i * 32;
            const uint32_t off = SWZ((uint32_t)(row * 128 + lcg * 16));
            cpasync16(ab + off, A + (size_t)(m0 + row) * 512 + kk + lcg * 8);
            cpasync16(bb + off, B + (size_t)(n0 + row) * 512 + kk + lcg * 8);
        }
        CP_COMMIT();
    };

    auto compute = [&](int s) {
        const uint32_t ab = smA + s * 16384;
        const uint32_t bb = smB + s * 16384;
#pragma unroll
        for (int ks = 0; ks < 4; ++ks) {
            uint32_t a[2][4];
#pragma unroll
            for (int mi = 0; mi < 2; ++mi) {
                const int row = wm * 32 + mi * 16 + arow;
                ldsm4(a[mi], ab + SWZ((uint32_t)(row * 128 + (ks * 2 + acol) * 16)));
            }
#pragma unroll
            for (int nb = 0; nb < 4; ++nb) {
                const int row = wn * 64 + nb * 16 + brow;
                uint32_t b[4];
                ldsm4(b, bb + SWZ((uint32_t)(row * 128 + (ks * 2 + bcol) * 16)));
                mma_f16(acc[0][nb * 2],     a[0], b[0], b[1]);
                mma_f16(acc[1][nb * 2],     a[1], b[0], b[1]);
                mma_f16(acc[0][nb * 2 + 1], a[0], b[2], b[3]);
                mma_f16(acc[1][nb * 2 + 1], a[1], b[2], b[3]);
            }
        }
    };

    load_chunk(0, 0);
    load_chunk(1, 1);
    CP_WAIT(1);
    __syncthreads();

    for (int c = 0; c < 8; ++c) {
        const int s = c & 1;
        compute(s);
        if (c == 7) break;
        __syncthreads();
        if (c + 2 < 8) { load_chunk(c + 2, s); CP_WAIT(1); }
        else           { CP_WAIT(0); }
        __syncthreads();
    }

    const int gid = l >> 2, tig = l & 3;
#pragma unroll
    for (int mi = 0; mi < 2; ++mi) {
#pragma unroll
        for (int ni = 0; ni < 8; ++ni) {
            const int row = m0 + wm * 32 + mi * 16 + gid;
            const int col = n0 + wn * 64 + ni * 8 + tig * 2;
            float2 bb = *(const float2*)(bias + col);
            float v0 = acc[mi][ni][0] + bb.x;
            float v1 = acc[mi][ni][1] + bb.y;
            float v2 = acc[mi][ni][2] + bb.x;
            float v3 = acc[mi][ni][3] + bb.y;
            if (RELU) {
                v0 = fmaxf(v0, 0.f); v1 = fmaxf(v1, 0.f);
                v2 = fmaxf(v2, 0.f); v3 = fmaxf(v3, 0.f);
            }
            __half h0 = __float2half_rn(v0), h1 = __float2half_rn(v1);
            __half h2 = __float2half_rn(v2), h3 = __float2half_rn(v3);
            ushort2 u0 = {__half_as_ushort(h0), __half_as_ushort(h1)};
            ushort2 u1 = {__half_as_ushort(h2), __half_as_ushort(h3)};
            *(ushort2*)(Cf16 + (size_t)row * Ntot + col)       = u0;
            *(ushort2*)(Cf16 + (size_t)(row + 8) * Ntot + col) = u1;
        }
    }
}

// ---------------- tensor-core attention ----------------
// Per batch: scores = Tf16 @ Xf16^T + w (w = X.gv) ; attn = softmax rows (fp32)
// OUT = relu(attnf16 @ VOf16 + RO)   — T/VO/RO packed in TVRf16 [64, 1536].
#define A_STAGE 0           // 2 stages x 16KB  (phase1: T @ +0, X @ +8KB ; phase3: VO @ +0)
#define A_SC    32768       // fp32 scores [64][68]
#define A_ATT   50176       // fp16 attn tile 64x64 (swizzled 128B rows)
#define A_GSH   58368       // gv fp32 [512]
#define A_WPART 60416       // fp32 [4][64]
#define A_WSH   61440       // fp32 [64]
#define ATTN_SMEM 61696

__global__ __launch_bounds__(256)
void attn_tc(const __half* __restrict__ Xf16, const __half* __restrict__ TVR,
             const float* __restrict__ gv, float* __restrict__ OUT)
{
    extern __shared__ char sm[];
    const uint32_t smS = smem_u32(sm);
    float* sc    = (float*)(sm + A_SC);
    float* gsh   = (float*)(sm + A_GSH);
    float* wpart = (float*)(sm + A_WPART);
    float* wsh   = (float*)(sm + A_WSH);

    const int b = blockIdx.x;
    const __half* Xb   = Xf16 + (size_t)b * 64 * 512;
    const __half* TVRb = TVR  + (size_t)b * 64 * NTVR;
    float*        Ob   = OUT  + (size_t)b * 64 * 512;

    const int t = threadIdx.x;
    const int wid = t >> 5, l = t & 31;
    const int wm = wid >> 1, wn = wid & 1;   // 4x2 warps: rows 16 each, cols 32 each
    const int arow = l & 15, acol = l >> 4;
    const int brow = (l & 7) + ((l >> 4) & 1) * 8, bcol = (l >> 3) & 1;
    const int gid = l >> 2, tig = l & 3;

    // phase-1 staging of chunks 0,1 (T at +0, X at +8KB per 16KB stage)
    auto load1 = [&](int kt, int s) {
#pragma unroll
        for (int i = 0; i < 2; ++i) {
            const int idx = t + i * 256;
            const int row = idx >> 3, cg = idx & 7;
            const uint32_t off = SWZ((uint32_t)(row * 128 + cg * 16));
            cpasync16(smS + s * 16384 + off,        TVRb + (size_t)row * NTVR + kt * 64 + cg * 8);
            cpasync16(smS + s * 16384 + 8192 + off, Xb   + (size_t)row * 512  + kt * 64 + cg * 8);
        }
        CP_COMMIT();
    };
    load1(0, 0);
    load1(1, 1);

    // gv to smem + w partials (reads Xf16 straight from gmem/L2)
    gsh[t]       = gv[t];
    gsh[t + 256] = gv[t + 256];
    __syncthreads();
    {
        const int r = t & 63, p = t >> 6;
        const __half* xr = Xb + r * 512 + p * 128;
        const float*  gp = gsh + p * 128;
        float s = 0.f;
#pragma unroll 8
        for (int d = 0; d < 64; ++d) {
            __half2 x2 = *(const __half2*)(xr + 2 * d);
            float2 xf = __half22float2(x2);
            s += xf.x * gp[2 * d] + xf.y * gp[2 * d + 1];
        }
        wpart[p * 64 + r] = s;
    }

    // phase 1: scores 64x64 over K=512 (8 chunks of 64)
    float acc1[4][4];
#pragma unroll
    for (int i = 0; i < 4; ++i)
#pragma unroll
        for (int j = 0; j < 4; ++j) acc1[i][j] = 0.f;

    auto compute1 = [&](int s) {
        const uint32_t tb = smS + s * 16384;
        const uint32_t xb = tb + 8192;
#pragma unroll
        for (int ks = 0; ks < 4; ++ks) {
            uint32_t a[4];
            ldsm4(a, tb + SWZ((uint32_t)((wm * 16 + arow) * 128 + (ks * 2 + acol) * 16)));
#pragma unroll
            for (int nb = 0; nb < 2; ++nb) {
                uint32_t bf[4];
                ldsm4(bf, xb + SWZ((uint32_t)((wn * 32 + nb * 16 + brow) * 128 + (ks * 2 + bcol) * 16)));
                mma_f16(acc1[nb * 2],     a, bf[0], bf[1]);
                mma_f16(acc1[nb * 2 + 1], a, bf[2], bf[3]);
            }
        }
    };

    CP_WAIT(1);
    __syncthreads();
    for (int c = 0; c < 8; ++c) {
        const int s = c & 1;
        compute1(s);
        if (c == 7) break;
        __syncthreads();
        if (c + 2 < 8) { load1(c + 2, s); CP_WAIT(1); }
        else           { CP_WAIT(0); }
        __syncthreads();
    }
    __syncthreads();

    if (t < 64)
        wsh[t] = wpart[t] + wpart[64 + t] + wpart[128 + t] + wpart[192 + t];
    __syncthreads();

    // frags -> sc (+ w)
#pragma unroll
    for (int nb = 0; nb < 4; ++nb) {
        const int col = wn * 32 + nb * 8 + tig * 2;
        const int r0 = wm * 16 + gid;
        sc[r0 * 68 + col]           = acc1[nb][0] + wsh[col];
        sc[r0 * 68 + col + 1]       = acc1[nb][1] + wsh[col + 1];
        sc[(r0 + 8) * 68 + col]     = acc1[nb][2] + wsh[col];
        sc[(r0 + 8) * 68 + col + 1] = acc1[nb][3] + wsh[col + 1];
    }
    __syncthreads();

    // softmax (row per thread)
    if (t < 64) {
        float m = -1e30f;
#pragma unroll 8
        for (int c = 0; c < 64; ++c) m = fmaxf(m, sc[t * 68 + c]);
        float s = 0.f;
#pragma unroll 8
        for (int c = 0; c < 64; ++c) { float e = expf(sc[t * 68 + c] - m); sc[t * 68 + c] = e; s += e; }
        const float inv = 1.f / s;
#pragma unroll 8
        for (int c = 0; c < 64; ++c) sc[t * 68 + c] *= inv;
    }
    __syncthreads();

    // attn -> fp16 swizzled tile (64 rows x 128B)
    {
        const int row = t >> 2, seg = t & 3;
#pragma unroll
        for (int j = 0; j < 8; ++j) {
            const int col = seg * 16 + j * 2;
            __half2 h = __floats2half2_rn(sc[row * 68 + col], sc[row * 68 + col + 1]);
            *(__half2*)(sm + A_ATT + SWZ((uint32_t)(row * 128 + col * 2))) = h;
        }
    }
    __syncthreads();

    // phase 3: OUT = relu(attn @ VO + RO), n-tiles of 64
    auto loadVO = [&](int nt, int s) {
#pragma unroll
        for (int i = 0; i < 2; ++i) {
            const int idx = t + i * 256;
            const int row = idx >> 3, cg = idx & 7;
            cpasync16(smS + s * 16384 + SWZ((uint32_t)(row * 128 + cg * 16)),
                      TVRb + (size_t)row * NTVR + 512 + nt * 64 + cg * 8);
        }
        CP_COMMIT();
    };
    loadVO(0, 0);
    loadVO(1, 1);

    // attn A-frags (K=64 -> 4 k16 steps), hoisted
    uint32_t a3[4][4];
    const uint32_t attb = smS + A_ATT;
#pragma unroll
    for (int ks = 0; ks < 4; ++ks)
        ldsm4(a3[ks], attb + SWZ((uint32_t)((wm * 16 + arow) * 128 + (ks * 2 + acol) * 16)));

    CP_WAIT(1);
    __syncthreads();

    const int trow = (l & 7) + ((l >> 3) & 1) * 8;
    const int tc8  = ((l >> 4) & 1) * 8;

    for (int nt = 0; nt < 8; ++nt) {
        const int s = nt & 1;
        const uint32_t vb = smS + s * 16384;
        float acc3[4][4];
#pragma unroll
        for (int i = 0; i < 4; ++i)
#pragma unroll
            for (int j = 0; j < 4; ++j) acc3[i][j] = 0.f;

#pragma unroll
        for (int ks = 0; ks < 4; ++ks) {
#pragma unroll
            for (int nb = 0; nb < 2; ++nb) {
                uint32_t bf[4];
                ldsm4t(bf, vb + SWZ((uint32_t)((ks * 16 + trow) * 128 +
                                               (wn * 32 + nb * 16 + tc8) * 2)));
                mma_f16(acc3[nb * 2],     a3[ks], bf[0], bf[1]);
                mma_f16(acc3[nb * 2 + 1], a3[ks], bf[2], bf[3]);
            }
        }

        // epilogue: + RO, relu, fp32 out
#pragma unroll
        for (int nb = 0; nb < 4; ++nb) {
            const int col = nt * 64 + wn * 32 + nb * 8 + tig * 2;
            const int r0 = wm * 16 + gid, r1 = r0 + 8;
            float2 ro0 = __half22float2(*(const __half2*)(TVRb + (size_t)r0 * NTVR + 1024 + col));
            float2 ro1 = __half22float2(*(const __half2*)(TVRb + (size_t)r1 * NTVR + 1024 + col));
            float2 o0 = {fmaxf(acc3[nb][0] + ro0.x, 0.f), fmaxf(acc3[nb][1] + ro0.y, 0.f)};
            float2 o1 = {fmaxf(acc3[nb][2] + ro1.x, 0.f), fmaxf(acc3[nb][3] + ro1.y, 0.f)};
            *(float2*)(Ob + (size_t)r0 * 512 + col) = o0;
            *(float2*)(Ob + (size_t)r1 * 512 + col) = o1;
        }

        if (nt == 7) break;
        __syncthreads();
        if (nt + 2 < 8) { loadVO(nt + 2, s); CP_WAIT(1); }
        else            { CP_WAIT(0); }
        __syncthreads();
    }
}

// ---------------- launch ----------------
extern "C" void kernel_launch(void* const* d_in, const int* in_sizes, int n_in,
                              void* d_out, int out_size)
{
    const float* inp = (const float*)d_in[0];
    const float* Win = (const float*)d_in[1];
    const float* bin = (const float*)d_in[2];
    const float* Wq  = (const float*)d_in[3];
    const float* bq  = (const float*)d_in[4];
    const float* Wk  = (const float*)d_in[5];
    // d_in[6] = b_k : provably unused (row-constant, drops out of softmax)
    const float* Wv  = (const float*)d_in[7];
    const float* bv  = (const float*)d_in[8];
    const float* Wr  = (const float*)d_in[9];
    const float* br  = (const float*)d_in[10];
    const float* Wo  = (const float*)d_in[11];
    const float* bo  = (const float*)d_in[12];
    float* out = (float*)d_out;

    float *Wqk, *Wvo, *Wro, *gv, *bias2;
    __half *Xf16, *If16, *WinT, *Wb, *TVR;
    cudaGetSymbolAddress((void**)&TVR,   g_TVR);
    cudaGetSymbolAddress((void**)&Wqk,   g_Wqk);
    cudaGetSymbolAddress((void**)&Wvo,   g_Wvo);
    cudaGetSymbolAddress((void**)&Wro,   g_Wro);
    cudaGetSymbolAddress((void**)&gv,    g_gv);
    cudaGetSymbolAddress((void**)&bias2, g_bias2);
    cudaGetSymbolAddress((void**)&Xf16,  g_Xf16);
    cudaGetSymbolAddress((void**)&If16,  g_If16);
    cudaGetSymbolAddress((void**)&WinT,  g_WinT);
    cudaGetSymbolAddress((void**)&Wb,    g_Wb);

    cudaFuncSetAttribute(gemm_f16<true >, cudaFuncAttributeMaxDynamicSharedMemorySize, MG_SMEM);
    cudaFuncSetAttribute(gemm_f16<false>, cudaFuncAttributeMaxDynamicSharedMemorySize, MG_SMEM);
    cudaFuncSetAttribute(attn_tc,         cudaFuncAttributeMaxDynamicSharedMemorySize, ATTN_SMEM);

    const dim3 bs(256);

    // weight-space precompute (fp32-exact, small)
    vec_pre_k<<<1, 512>>>(Wo, bv, br, bo, Wk, bq, gv, bias2);
    wpre_k<<<dim3(8, 8, 3), bs>>>(Wq, Wk, Wv, Wr, Wo, Wqk, Wvo, Wro);

    // transpose + convert weights to fp16
    dim3 tb32(32, 32), tg(16, 16);
    t_f16_k<<<tg, tb32>>>(Win, WinT, 0);
    t_f16_k<<<tg, tb32>>>(Wqk, Wb, 0);
    t_f16_k<<<tg, tb32>>>(Wvo, Wb, 512);
    t_f16_k<<<tg, tb32>>>(Wro, Wb, 1024);

    // convert activations to fp16
    const int n4 = MTOT * D_DIM / 4;
    f16conv_k<<<(n4 + 255) / 256, 256>>>(inp, If16, n4);

    // big GEMMs on tensor cores (fp16)
    gemm_f16<true ><<<dim3(4, 256),  bs, MG_SMEM>>>(If16, WinT, bin, Xf16, 512);
    gemm_f16<false><<<dim3(12, 256), bs, MG_SMEM>>>(Xf16, Wb, bias2, TVR, NTVR);

    // tensor-core attention + epilogue
    attn_tc<<<NBATCH, bs, ATTN_SMEM>>>(Xf16, TVR, gv, out);
}

// round 9
// speedup vs baseline: 2.1300x; 1.1027x over previous
#include <cuda_runtime.h>
#include <cuda_fp16.h>
#include <cstdint>
#include <cstddef>

#define D_DIM 512
#define AGENTS 64
#define NBATCH 512
#define MTOT (NBATCH * AGENTS)   // 32768
#define NTVR 1536

// ---------------- scratch (device globals: allocation-free) ----------------
__device__ __align__(128) __half  g_Xf16[MTOT * D_DIM];
__device__ __align__(128) __half  g_If16[MTOT * D_DIM];
__device__ __align__(128) __half  g_TVR [MTOT * NTVR];
__device__ __align__(128) float   g_W3  [3 * D_DIM * D_DIM];   // Wqk | Wvo | Wro
__device__ __align__(128) __half  g_WinT[D_DIM * D_DIM];
__device__ __align__(128) __half  g_Wb  [NTVR * D_DIM];
__device__ __align__(128) float   g_gv  [D_DIM];
__device__ __align__(128) float   g_bias2[NTVR];

#define SWZ(o) ((o) ^ (((o) >> 3) & 0x70))

__device__ __forceinline__ uint32_t smem_u32(const void* p) {
    uint32_t a;
    asm("{ .reg .u64 t; cvta.to.shared.u64 t, %1; cvt.u32.u64 %0, t; }" : "=r"(a) : "l"(p));
    return a;
}
__device__ __forceinline__ void ldsm4(uint32_t* r, uint32_t addr) {
    asm volatile("ldmatrix.sync.aligned.m8n8.x4.shared.b16 {%0,%1,%2,%3}, [%4];"
                 : "=r"(r[0]), "=r"(r[1]), "=r"(r[2]), "=r"(r[3]) : "r"(addr));
}
__device__ __forceinline__ void ldsm4t(uint32_t* r, uint32_t addr) {
    asm volatile("ldmatrix.sync.aligned.m8n8.x4.trans.shared.b16 {%0,%1,%2,%3}, [%4];"
                 : "=r"(r[0]), "=r"(r[1]), "=r"(r[2]), "=r"(r[3]) : "r"(addr));
}
__device__ __forceinline__ void mma_f16(float* d, const uint32_t* a, uint32_t b0, uint32_t b1) {
    asm volatile(
        "mma.sync.aligned.m16n8k16.row.col.f32.f16.f16.f32 "
        "{%0,%1,%2,%3}, {%4,%5,%6,%7}, {%8,%9}, {%0,%1,%2,%3};"
        : "+f"(d[0]), "+f"(d[1]), "+f"(d[2]), "+f"(d[3])
        : "r"(a[0]), "r"(a[1]), "r"(a[2]), "r"(a[3]), "r"(b0), "r"(b1));
}
__device__ __forceinline__ void cpasync16(uint32_t dst, const void* src) {
    asm volatile("cp.async.cg.shared.global [%0], [%1], 16;" :: "r"(dst), "l"(src));
}
#define CP_COMMIT() asm volatile("cp.async.commit_group;" ::: "memory")
#define CP_WAIT(N)  asm volatile("cp.async.wait_group " #N ";" ::: "memory")

// ---------------- convert inputs fp32 -> fp16 ----------------
__global__ void f16conv_k(const float* __restrict__ src, __half* __restrict__ dst, int n4) {
    int i = blockIdx.x * blockDim.x + threadIdx.x;
    if (i >= n4) return;
    float4 v = ((const float4*)src)[i];
    __half h0 = __float2half_rn(v.x), h1 = __float2half_rn(v.y);
    __half h2 = __float2half_rn(v.z), h3 = __float2half_rn(v.w);
    uint32_t a = (uint32_t)__half_as_ushort(h0) | ((uint32_t)__half_as_ushort(h1) << 16);
    uint32_t b = (uint32_t)__half_as_ushort(h2) | ((uint32_t)__half_as_ushort(h3) << 16);
    ((uint2*)dst)[i] = make_uint2(a, b);
}

// ---------------- merged transpose->fp16: z=0 Win->WinT ; z=1..3 W3[z-1]->Wb[z-1] ----------------
__global__ void t_f16m_k(const float* __restrict__ Win, const float* __restrict__ W3,
                         __half* __restrict__ WinT, __half* __restrict__ Wb) {
    __shared__ float tle[32][33];
    const int z = blockIdx.z;
    const float* src = (z == 0) ? Win : (W3 + (size_t)(z - 1) * D_DIM * D_DIM);
    __half* dst      = (z == 0) ? WinT : (Wb + (size_t)(z - 1) * D_DIM * D_DIM);
    int tx = threadIdx.x, ty = threadIdx.y;
    int n0 = blockIdx.x * 32, k0 = blockIdx.y * 32;
    tle[ty][tx] = src[(size_t)(k0 + ty) * 512 + n0 + tx];
    __syncthreads();
    dst[(size_t)(n0 + ty) * 512 + k0 + tx] = __float2half_rn(tle[tx][ty]);
}

// ---------------- vector precompute (2 blocks) ----------------
// block 0: bias2[512+j]=bv@Wo ; bias2[1024+j]=br@Wo+bo
// block 1: gv[j]=Wk[j,:]@bq ; bias2[j]=0
__global__ void vec_pre_k(const float* __restrict__ Wo,
                          const float* __restrict__ bv,
                          const float* __restrict__ br,
                          const float* __restrict__ bo,
                          const float* __restrict__ Wk,
                          const float* __restrict__ bq,
                          float* __restrict__ gv,
                          float* __restrict__ bias2) {
    int j = threadIdx.x;
    if (blockIdx.x == 0) {
        float s1 = 0.f, s2 = 0.f;
        for (int d = 0; d < D_DIM; ++d) {
            float w = Wo[d * D_DIM + j];
            s1 += bv[d] * w;
            s2 += br[d] * w;
        }
        bias2[512 + j]  = s1;
        bias2[1024 + j] = s2 + bo[j];
    } else {
        float s3 = 0.f;
        const float* wk = Wk + (size_t)j * D_DIM;
        for (int t = 0; t < D_DIM; ++t) s3 += wk[t] * bq[t];
        gv[j] = s3;
        bias2[j] = 0.f;
    }
}

// ---------------- weight precompute: 3 fp32 512x512x512 GEMMs into W3 ----------------
__global__ __launch_bounds__(256)
void wpre_k(const float* __restrict__ Wq, const float* __restrict__ Wk,
            const float* __restrict__ Wv, const float* __restrict__ Wr,
            const float* __restrict__ Wo, float* __restrict__ W3) {
    const int z = blockIdx.z;
    const float* A = (z == 0) ? Wq : ((z == 1) ? Wv : Wr);
    const float* B = (z == 0) ? Wk : Wo;
    float* C = W3 + (size_t)z * D_DIM * D_DIM;
    const bool transb = (z == 0);

    __shared__ __align__(16) float As[32][72];
    __shared__ __align__(16) float Bs[32][72];
    const int t = threadIdx.x;
    const int tx = t & 15, ty = t >> 4;
    const int m0 = blockIdx.y * 64, n0 = blockIdx.x * 64;

    float acc[4][4];
#pragma unroll
    for (int i = 0; i < 4; ++i)
#pragma unroll
        for (int j = 0; j < 4; ++j) acc[i][j] = 0.f;

    for (int kt = 0; kt < 16; ++kt) {
        __syncthreads();
#pragma unroll
        for (int i = 0; i < 2; ++i) {
            const int idx = t + i * 256;
            const int row = idx >> 3, c4 = (idx & 7) * 4;
            float4 v = *(const float4*)(A + (size_t)(m0 + row) * 512 + kt * 32 + c4);
            As[c4 + 0][row] = v.x; As[c4 + 1][row] = v.y;
            As[c4 + 2][row] = v.z; As[c4 + 3][row] = v.w;
        }
        if (transb) {
#pragma unroll
            for (int i = 0; i < 2; ++i) {
                const int idx = t + i * 256;
                const int row = idx >> 3, c4 = (idx & 7) * 4;
                float4 v = *(const float4*)(B + (size_t)(n0 + row) * 512 + kt * 32 + c4);
                Bs[c4 + 0][row] = v.x; Bs[c4 + 1][row] = v.y;
                Bs[c4 + 2][row] = v.z; Bs[c4 + 3][row] = v.w;
            }
        } else {
#pragma unroll
            for (int i = 0; i < 2; ++i) {
                const int idx = t + i * 256;
                const int kr = idx >> 4, c4 = (idx & 15) * 4;
                float4 v = *(const float4*)(B + (size_t)(kt * 32 + kr) * 512 + n0 + c4);
                *(float4*)&Bs[kr][c4] = v;
            }
        }
        __syncthreads();
#pragma unroll
        for (int k = 0; k < 32; ++k) {
            float4 av = *(const float4*)&As[k][ty * 4];
            float4 bv = *(const float4*)&Bs[k][tx * 4];
            float a[4] = {av.x, av.y, av.z, av.w};
            float b[4] = {bv.x, bv.y, bv.z, bv.w};
#pragma unroll
            for (int i = 0; i < 4; ++i)
#pragma unroll
                for (int j = 0; j < 4; ++j) acc[i][j] += a[i] * b[j];
        }
    }
#pragma unroll
    for (int i = 0; i < 4; ++i) {
        float4 o = {acc[i][0], acc[i][1], acc[i][2], acc[i][3]};
        *(float4*)(C + (size_t)(m0 + ty * 4 + i) * 512 + n0 + tx * 4) = o;
    }
}

// ---------------- fp16 GEMM: Cf16[M,Ntot] = A[M,512] @ B^T[Ntot,512] + bias ----------------
#define MG_SMEM 65536

template<bool RELU>
__global__ __launch_bounds__(256)
void gemm_f16(const __half* __restrict__ A, const __half* __restrict__ B,
              const float* __restrict__ bias, __half* __restrict__ Cf16, int Ntot)
{
    extern __shared__ char sm[];
    const uint32_t smA = smem_u32(sm);
    const uint32_t smB = smA + 32768;

    const int t = threadIdx.x;
    const int wid = t >> 5, l = t & 31;
    const int wm = wid >> 1, wn = wid & 1;
    const int m0 = blockIdx.y * 128, n0 = blockIdx.x * 128;

    const int arow = l & 15, acol = l >> 4;
    const int brow = (l & 7) + ((l >> 4) & 1) * 8, bcol = (l >> 3) & 1;
    const int lrow = t >> 3, lcg = t & 7;

    float acc[2][8][4];
#pragma unroll
    for (int mi = 0; mi < 2; ++mi)
#pragma unroll
        for (int ni = 0; ni < 8; ++ni)
#pragma unroll
            for (int q = 0; q < 4; ++q) acc[mi][ni][q] = 0.f;

    auto load_chunk = [&](int c, int s) {
        const int kk = c * 64;
        const uint32_t ab = smA + s * 16384;
        const uint32_t bb = smB + s * 16384;
#pragma unroll
        for (int i = 0; i < 4; ++i) {
            const int row = lrow + i * 32;
            const uint32_t off = SWZ((uint32_t)(row * 128 + lcg * 16));
            cpasync16(ab + off, A + (size_t)(m0 + row) * 512 + kk + lcg * 8);
            cpasync16(bb + off, B + (size_t)(n0 + row) * 512 + kk + lcg * 8);
        }
        CP_COMMIT();
    };

    auto compute = [&](int s) {
        const uint32_t ab = smA + s * 16384;
        const uint32_t bb = smB + s * 16384;
#pragma unroll
        for (int ks = 0; ks < 4; ++ks) {
            uint32_t a[2][4];
#pragma unroll
            for (int mi = 0; mi < 2; ++mi) {
                const int row = wm * 32 + mi * 16 + arow;
                ldsm4(a[mi], ab + SWZ((uint32_t)(row * 128 + (ks * 2 + acol) * 16)));
            }
#pragma unroll
            for (int nb = 0; nb < 4; ++nb) {
                const int row = wn * 64 + nb * 16 + brow;
                uint32_t b[4];
                ldsm4(b, bb + SWZ((uint32_t)(row * 128 + (ks * 2 + bcol) * 16)));
                mma_f16(acc[0][nb * 2],     a[0], b[0], b[1]);
                mma_f16(acc[1][nb * 2],     a[1], b[0], b[1]);
                mma_f16(acc[0][nb * 2 + 1], a[0], b[2], b[3]);
                mma_f16(acc[1][nb * 2 + 1], a[1], b[2], b[3]);
            }
        }
    };

    load_chunk(0, 0);
    load_chunk(1, 1);
    CP_WAIT(1);
    __syncthreads();

    for (int c = 0; c < 8; ++c) {
        const int s = c & 1;
        compute(s);
        if (c == 7) break;
        __syncthreads();
        if (c + 2 < 8) { load_chunk(c + 2, s); CP_WAIT(1); }
        else           { CP_WAIT(0); }
        __syncthreads();
    }

    const int gid = l >> 2, tig = l & 3;
#pragma unroll
    for (int mi = 0; mi < 2; ++mi) {
#pragma unroll
        for (int ni = 0; ni < 8; ++ni) {
            const int row = m0 + wm * 32 + mi * 16 + gid;
            const int col = n0 + wn * 64 + ni * 8 + tig * 2;
            float2 bb = *(const float2*)(bias + col);
            float v0 = acc[mi][ni][0] + bb.x;
            float v1 = acc[mi][ni][1] + bb.y;
            float v2 = acc[mi][ni][2] + bb.x;
            float v3 = acc[mi][ni][3] + bb.y;
            if (RELU) {
                v0 = fmaxf(v0, 0.f); v1 = fmaxf(v1, 0.f);
                v2 = fmaxf(v2, 0.f); v3 = fmaxf(v3, 0.f);
            }
            __half h0 = __float2half_rn(v0), h1 = __float2half_rn(v1);
            __half h2 = __float2half_rn(v2), h3 = __float2half_rn(v3);
            ushort2 u0 = {__half_as_ushort(h0), __half_as_ushort(h1)};
            ushort2 u1 = {__half_as_ushort(h2), __half_as_ushort(h3)};
            *(ushort2*)(Cf16 + (size_t)row * Ntot + col)       = u0;
            *(ushort2*)(Cf16 + (size_t)(row + 8) * Ntot + col) = u1;
        }
    }
}

// ---------------- tensor-core attention ----------------
#define A_SC    32768       // fp32 scores [64][68]
#define A_ATT   50176       // fp16 attn tile 64x64 (swizzled 128B rows)
#define A_GSH   58368       // gv fp32 [512]
#define A_WPART 60416       // fp32 [4][64]
#define A_WSH   61440       // fp32 [64]
#define ATTN_SMEM 61696

__global__ __launch_bounds__(256)
void attn_tc(const __half* __restrict__ Xf16, const __half* __restrict__ TVR,
             const float* __restrict__ gv, float* __restrict__ OUT)
{
    extern __shared__ char sm[];
    const uint32_t smS = smem_u32(sm);
    float* sc    = (float*)(sm + A_SC);
    float* gsh   = (float*)(sm + A_GSH);
    float* wpart = (float*)(sm + A_WPART);
    float* wsh   = (float*)(sm + A_WSH);

    const int b = blockIdx.x;
    const __half* Xb   = Xf16 + (size_t)b * 64 * 512;
    const __half* TVRb = TVR  + (size_t)b * 64 * NTVR;
    float*        Ob   = OUT  + (size_t)b * 64 * 512;

    const int t = threadIdx.x;
    const int wid = t >> 5, l = t & 31;
    const int wm = wid >> 1, wn = wid & 1;
    const int arow = l & 15, acol = l >> 4;
    const int brow = (l & 7) + ((l >> 4) & 1) * 8, bcol = (l >> 3) & 1;
    const int gid = l >> 2, tig = l & 3;

    auto load1 = [&](int kt, int s) {
#pragma unroll
        for (int i = 0; i < 2; ++i) {
            const int idx = t + i * 256;
            const int row = idx >> 3, cg = idx & 7;
            const uint32_t off = SWZ((uint32_t)(row * 128 + cg * 16));
            cpasync16(smS + s * 16384 + off,        TVRb + (size_t)row * NTVR + kt * 64 + cg * 8);
            cpasync16(smS + s * 16384 + 8192 + off, Xb   + (size_t)row * 512  + kt * 64 + cg * 8);
        }
        CP_COMMIT();
    };
    load1(0, 0);
    load1(1, 1);

    gsh[t]       = gv[t];
    gsh[t + 256] = gv[t + 256];
    __syncthreads();
    {
        const int r = t & 63, p = t >> 6;
        const __half* xr = Xb + r * 512 + p * 128;
        const float*  gp = gsh + p * 128;
        float s = 0.f;
#pragma unroll 8
        for (int d = 0; d < 64; ++d) {
            __half2 x2 = *(const __half2*)(xr + 2 * d);
            float2 xf = __half22float2(x2);
            s += xf.x * gp[2 * d] + xf.y * gp[2 * d + 1];
        }
        wpart[p * 64 + r] = s;
    }

    float acc1[4][4];
#pragma unroll
    for (int i = 0; i < 4; ++i)
#pragma unroll
        for (int j = 0; j < 4; ++j) acc1[i][j] = 0.f;

    auto compute1 = [&](int s) {
        const uint32_t tb = smS + s * 16384;
        const uint32_t xb = tb + 8192;
#pragma unroll
        for (int ks = 0; ks < 4; ++ks) {
            uint32_t a[4];
            ldsm4(a, tb + SWZ((uint32_t)((wm * 16 + arow) * 128 + (ks * 2 + acol) * 16)));
#pragma unroll
            for (int nb = 0; nb < 2; ++nb) {
                uint32_t bf[4];
                ldsm4(bf, xb + SWZ((uint32_t)((wn * 32 + nb * 16 + brow) * 128 + (ks * 2 + bcol) * 16)));
                mma_f16(acc1[nb * 2],     a, bf[0], bf[1]);
                mma_f16(acc1[nb * 2 + 1], a, bf[2], bf[3]);
            }
        }
    };

    CP_WAIT(1);
    __syncthreads();
    for (int c = 0; c < 8; ++c) {
        const int s = c & 1;
        compute1(s);
        if (c == 7) break;
        __syncthreads();
        if (c + 2 < 8) { load1(c + 2, s); CP_WAIT(1); }
        else           { CP_WAIT(0); }
        __syncthreads();
    }
    __syncthreads();

    if (t < 64)
        wsh[t] = wpart[t] + wpart[64 + t] + wpart[128 + t] + wpart[192 + t];
    __syncthreads();

#pragma unroll
    for (int nb = 0; nb < 4; ++nb) {
        const int col = wn * 32 + nb * 8 + tig * 2;
        const int r0 = wm * 16 + gid;
        sc[r0 * 68 + col]           = acc1[nb][0] + wsh[col];
        sc[r0 * 68 + col + 1]       = acc1[nb][1] + wsh[col + 1];
        sc[(r0 + 8) * 68 + col]     = acc1[nb][2] + wsh[col];
        sc[(r0 + 8) * 68 + col + 1] = acc1[nb][3] + wsh[col + 1];
    }
    __syncthreads();

    if (t < 64) {
        float m = -1e30f;
#pragma unroll 8
        for (int c = 0; c < 64; ++c) m = fmaxf(m, sc[t * 68 + c]);
        float s = 0.f;
#pragma unroll 8
        for (int c = 0; c < 64; ++c) { float e = expf(sc[t * 68 + c] - m); sc[t * 68 + c] = e; s += e; }
        const float inv = 1.f / s;
#pragma unroll 8
        for (int c = 0; c < 64; ++c) sc[t * 68 + c] *= inv;
    }
    __syncthreads();

    {
        const int row = t >> 2, seg = t & 3;
#pragma unroll
        for (int j = 0; j < 8; ++j) {
            const int col = seg * 16 + j * 2;
            __half2 h = __floats2half2_rn(sc[row * 68 + col], sc[row * 68 + col + 1]);
            *(__half2*)(sm + A_ATT + SWZ((uint32_t)(row * 128 + col * 2))) = h;
        }
    }
    __syncthreads();

    auto loadVO = [&](int nt, int s) {
#pragma unroll
        for (int i = 0; i < 2; ++i) {
            const int idx = t + i * 256;
            const int row = idx >> 3, cg = idx & 7;
            cpasync16(smS + s * 16384 + SWZ((uint32_t)(row * 128 + cg * 16)),
                      TVRb + (size_t)row * NTVR + 512 + nt * 64 + cg * 8);
        }
        CP_COMMIT();
    };
    loadVO(0, 0);
    loadVO(1, 1);

    uint32_t a3[4][4];
    const uint32_t attb = smS + A_ATT;
#pragma unroll
    for (int ks = 0; ks < 4; ++ks)
        ldsm4(a3[ks], attb + SWZ((uint32_t)((wm * 16 + arow) * 128 + (ks * 2 + acol) * 16)));

    CP_WAIT(1);
    __syncthreads();

    const int trow = (l & 7) + ((l >> 3) & 1) * 8;
    const int tc8  = ((l >> 4) & 1) * 8;

    for (int nt = 0; nt < 8; ++nt) {
        const int s = nt & 1;
        const uint32_t vb = smS + s * 16384;
        float acc3[4][4];
#pragma unroll
        for (int i = 0; i < 4; ++i)
#pragma unroll
            for (int j = 0; j < 4; ++j) acc3[i][j] = 0.f;

#pragma unroll
        for (int ks = 0; ks < 4; ++ks) {
#pragma unroll
            for (int nb = 0; nb < 2; ++nb) {
                uint32_t bf[4];
                ldsm4t(bf, vb + SWZ((uint32_t)((ks * 16 + trow) * 128 +
                                               (wn * 32 + nb * 16 + tc8) * 2)));
                mma_f16(acc3[nb * 2],     a3[ks], bf[0], bf[1]);
                mma_f16(acc3[nb * 2 + 1], a3[ks], bf[2], bf[3]);
            }
        }

#pragma unroll
        for (int nb = 0; nb < 4; ++nb) {
            const int col = nt * 64 + wn * 32 + nb * 8 + tig * 2;
            const int r0 = wm * 16 + gid, r1 = r0 + 8;
            float2 ro0 = __half22float2(*(const __half2*)(TVRb + (size_t)r0 * NTVR + 1024 + col));
            float2 ro1 = __half22float2(*(const __half2*)(TVRb + (size_t)r1 * NTVR + 1024 + col));
            float2 o0 = {fmaxf(acc3[nb][0] + ro0.x, 0.f), fmaxf(acc3[nb][1] + ro0.y, 0.f)};
            float2 o1 = {fmaxf(acc3[nb][2] + ro1.x, 0.f), fmaxf(acc3[nb][3] + ro1.y, 0.f)};
            *(float2*)(Ob + (size_t)r0 * 512 + col) = o0;
            *(float2*)(Ob + (size_t)r1 * 512 + col) = o1;
        }

        if (nt == 7) break;
        __syncthreads();
        if (nt + 2 < 8) { loadVO(nt + 2, s); CP_WAIT(1); }
        else            { CP_WAIT(0); }
        __syncthreads();
    }
}

// ---------------- launch ----------------
extern "C" void kernel_launch(void* const* d_in, const int* in_sizes, int n_in,
                              void* d_out, int out_size)
{
    const float* inp = (const float*)d_in[0];
    const float* Win = (const float*)d_in[1];
    const float* bin = (const float*)d_in[2];
    const float* Wq  = (const float*)d_in[3];
    const float* bq  = (const float*)d_in[4];
    const float* Wk  = (const float*)d_in[5];
    // d_in[6] = b_k : provably unused (row-constant, drops out of softmax)
    const float* Wv  = (const float*)d_in[7];
    const float* bv  = (const float*)d_in[8];
    const float* Wr  = (const float*)d_in[9];
    const float* br  = (const float*)d_in[10];
    const float* Wo  = (const float*)d_in[11];
    const float* bo  = (const float*)d_in[12];
    float* out = (float*)d_out;

    float *W3, *gv, *bias2;
    __half *Xf16, *If16, *WinT, *Wb, *TVR;
    cudaGetSymbolAddress((void**)&TVR,   g_TVR);
    cudaGetSymbolAddress((void**)&W3,    g_W3);
    cudaGetSymbolAddress((void**)&gv,    g_gv);
    cudaGetSymbolAddress((void**)&bias2, g_bias2);
    cudaGetSymbolAddress((void**)&Xf16,  g_Xf16);
    cudaGetSymbolAddress((void**)&If16,  g_If16);
    cudaGetSymbolAddress((void**)&WinT,  g_WinT);
    cudaGetSymbolAddress((void**)&Wb,    g_Wb);

    cudaFuncSetAttribute(gemm_f16<true >, cudaFuncAttributeMaxDynamicSharedMemorySize, MG_SMEM);
    cudaFuncSetAttribute(gemm_f16<false>, cudaFuncAttributeMaxDynamicSharedMemorySize, MG_SMEM);
    cudaFuncSetAttribute(attn_tc,         cudaFuncAttributeMaxDynamicSharedMemorySize, ATTN_SMEM);

    const dim3 bs(256);
    const int n4 = MTOT * D_DIM / 4;

    // 1: vector precompute (2 blocks)
    vec_pre_k<<<2, 512>>>(Wo, bv, br, bo, Wk, bq, gv, bias2);
    // 2: weight products Wqk/Wvo/Wro (fp32)
    wpre_k<<<dim3(8, 8, 3), bs>>>(Wq, Wk, Wv, Wr, Wo, W3);
    // 3: inputs -> fp16
    f16conv_k<<<(n4 + 255) / 256, 256>>>(inp, If16, n4);
    // 4: merged transpose->fp16 (Win + 3 derived)
    t_f16m_k<<<dim3(16, 16, 4), dim3(32, 32)>>>(Win, W3, WinT, Wb);
    // 5: gemm1
    gemm_f16<true ><<<dim3(4, 256),  bs, MG_SMEM>>>(If16, WinT, bin, Xf16, 512);
    // 6: gemm2  <-- ncu -s 5 -c 1 profiles THIS launch
    gemm_f16<false><<<dim3(12, 256), bs, MG_SMEM>>>(Xf16, Wb, bias2, TVR, NTVR);
    // 7: attention
    attn_tc<<<NBATCH, bs, ATTN_SMEM>>>(Xf16, TVR, gv, out);
}

// round 10
// speedup vs baseline: 2.1719x; 1.0197x over previous
#include <cuda_runtime.h>
#include <cuda_fp16.h>
#include <cstdint>
#include <cstddef>

#define D_DIM 512
#define AGENTS 64
#define NBATCH 512
#define MTOT (NBATCH * AGENTS)   // 32768
#define NTVR 1536

// ---------------- scratch (device globals: allocation-free) ----------------
__device__ __align__(128) __half  g_Xf16[MTOT * D_DIM];
__device__ __align__(128) __half  g_If16[MTOT * D_DIM];
__device__ __align__(128) __half  g_TVR [MTOT * NTVR];
__device__ __align__(128) float   g_W3  [3 * D_DIM * D_DIM];   // Wqk | Wvo | Wro
__device__ __align__(128) __half  g_WinT[D_DIM * D_DIM];
__device__ __align__(128) __half  g_Wb  [NTVR * D_DIM];
__device__ __align__(128) float   g_gv  [D_DIM];
__device__ __align__(128) float   g_bias2[NTVR];

#define SWZ(o) ((o) ^ (((o) >> 3) & 0x70))

__device__ __forceinline__ uint32_t smem_u32(const void* p) {
    uint32_t a;
    asm("{ .reg .u64 t; cvta.to.shared.u64 t, %1; cvt.u32.u64 %0, t; }" : "=r"(a) : "l"(p));
    return a;
}
__device__ __forceinline__ void ldsm4(uint32_t* r, uint32_t addr) {
    asm volatile("ldmatrix.sync.aligned.m8n8.x4.shared.b16 {%0,%1,%2,%3}, [%4];"
                 : "=r"(r[0]), "=r"(r[1]), "=r"(r[2]), "=r"(r[3]) : "r"(addr));
}
__device__ __forceinline__ void ldsm4t(uint32_t* r, uint32_t addr) {
    asm volatile("ldmatrix.sync.aligned.m8n8.x4.trans.shared.b16 {%0,%1,%2,%3}, [%4];"
                 : "=r"(r[0]), "=r"(r[1]), "=r"(r[2]), "=r"(r[3]) : "r"(addr));
}
__device__ __forceinline__ void mma_f16(float* d, const uint32_t* a, uint32_t b0, uint32_t b1) {
    asm volatile(
        "mma.sync.aligned.m16n8k16.row.col.f32.f16.f16.f32 "
        "{%0,%1,%2,%3}, {%4,%5,%6,%7}, {%8,%9}, {%0,%1,%2,%3};"
        : "+f"(d[0]), "+f"(d[1]), "+f"(d[2]), "+f"(d[3])
        : "r"(a[0]), "r"(a[1]), "r"(a[2]), "r"(a[3]), "r"(b0), "r"(b1));
}
__device__ __forceinline__ void cpasync16(uint32_t dst, const void* src) {
    asm volatile("cp.async.cg.shared.global [%0], [%1], 16;" :: "r"(dst), "l"(src));
}
#define CP_COMMIT() asm volatile("cp.async.commit_group;" ::: "memory")
#define CP_WAIT(N)  asm volatile("cp.async.wait_group " #N ";" ::: "memory")

// ---------------- convert inputs fp32 -> fp16 ----------------
__global__ void f16conv_k(const float* __restrict__ src, __half* __restrict__ dst, int n4) {
    int i = blockIdx.x * blockDim.x + threadIdx.x;
    if (i >= n4) return;
    float4 v = ((const float4*)src)[i];
    __half h0 = __float2half_rn(v.x), h1 = __float2half_rn(v.y);
    __half h2 = __float2half_rn(v.z), h3 = __float2half_rn(v.w);
    uint32_t a = (uint32_t)__half_as_ushort(h0) | ((uint32_t)__half_as_ushort(h1) << 16);
    uint32_t b = (uint32_t)__half_as_ushort(h2) | ((uint32_t)__half_as_ushort(h3) << 16);
    ((uint2*)dst)[i] = make_uint2(a, b);
}

// ---------------- merged transpose->fp16: z=0 Win->WinT ; z=1..3 W3[z-1]->Wb[z-1] ----------------
__global__ void t_f16m_k(const float* __restrict__ Win, const float* __restrict__ W3,
                         __half* __restrict__ WinT, __half* __restrict__ Wb) {
    __shared__ float tle[32][33];
    const int z = blockIdx.z;
    const float* src = (z == 0) ? Win : (W3 + (size_t)(z - 1) * D_DIM * D_DIM);
    __half* dst      = (z == 0) ? WinT : (Wb + (size_t)(z - 1) * D_DIM * D_DIM);
    int tx = threadIdx.x, ty = threadIdx.y;
    int n0 = blockIdx.x * 32, k0 = blockIdx.y * 32;
    tle[ty][tx] = src[(size_t)(k0 + ty) * 512 + n0 + tx];
    __syncthreads();
    dst[(size_t)(n0 + ty) * 512 + k0 + tx] = __float2half_rn(tle[tx][ty]);
}

// ---------------- vector precompute (2 blocks) ----------------
__global__ void vec_pre_k(const float* __restrict__ Wo,
                          const float* __restrict__ bv,
                          const float* __restrict__ br,
                          const float* __restrict__ bo,
                          const float* __restrict__ Wk,
                          const float* __restrict__ bq,
                          float* __restrict__ gv,
                          float* __restrict__ bias2) {
    int j = threadIdx.x;
    if (blockIdx.x == 0) {
        float s1 = 0.f, s2 = 0.f;
        for (int d = 0; d < D_DIM; ++d) {
            float w = Wo[d * D_DIM + j];
            s1 += bv[d] * w;
            s2 += br[d] * w;
        }
        bias2[512 + j]  = s1;
        bias2[1024 + j] = s2 + bo[j];
    } else {
        float s3 = 0.f;
        const float* wk = Wk + (size_t)j * D_DIM;
        for (int t = 0; t < D_DIM; ++t) s3 += wk[t] * bq[t];
        gv[j] = s3;
        bias2[j] = 0.f;
    }
}

// ---------------- weight precompute: 3 fp32 512x512x512 GEMMs into W3 ----------------
__global__ __launch_bounds__(256)
void wpre_k(const float* __restrict__ Wq, const float* __restrict__ Wk,
            const float* __restrict__ Wv, const float* __restrict__ Wr,
            const float* __restrict__ Wo, float* __restrict__ W3) {
    const int z = blockIdx.z;
    const float* A = (z == 0) ? Wq : ((z == 1) ? Wv : Wr);
    const float* B = (z == 0) ? Wk : Wo;
    float* C = W3 + (size_t)z * D_DIM * D_DIM;
    const bool transb = (z == 0);

    __shared__ __align__(16) float As[32][72];
    __shared__ __align__(16) float Bs[32][72];
    const int t = threadIdx.x;
    const int tx = t & 15, ty = t >> 4;
    const int m0 = blockIdx.y * 64, n0 = blockIdx.x * 64;

    float acc[4][4];
#pragma unroll
    for (int i = 0; i < 4; ++i)
#pragma unroll
        for (int j = 0; j < 4; ++j) acc[i][j] = 0.f;

    for (int kt = 0; kt < 16; ++kt) {
        __syncthreads();
#pragma unroll
        for (int i = 0; i < 2; ++i) {
            const int idx = t + i * 256;
            const int row = idx >> 3, c4 = (idx & 7) * 4;
            float4 v = *(const float4*)(A + (size_t)(m0 + row) * 512 + kt * 32 + c4);
            As[c4 + 0][row] = v.x; As[c4 + 1][row] = v.y;
            As[c4 + 2][row] = v.z; As[c4 + 3][row] = v.w;
        }
        if (transb) {
#pragma unroll
            for (int i = 0; i < 2; ++i) {
                const int idx = t + i * 256;
                const int row = idx >> 3, c4 = (idx & 7) * 4;
                float4 v = *(const float4*)(B + (size_t)(n0 + row) * 512 + kt * 32 + c4);
                Bs[c4 + 0][row] = v.x; Bs[c4 + 1][row] = v.y;
                Bs[c4 + 2][row] = v.z; Bs[c4 + 3][row] = v.w;
            }
        } else {
#pragma unroll
            for (int i = 0; i < 2; ++i) {
                const int idx = t + i * 256;
                const int kr = idx >> 4, c4 = (idx & 15) * 4;
                float4 v = *(const float4*)(B + (size_t)(kt * 32 + kr) * 512 + n0 + c4);
                *(float4*)&Bs[kr][c4] = v;
            }
        }
        __syncthreads();
#pragma unroll
        for (int k = 0; k < 32; ++k) {
            float4 av = *(const float4*)&As[k][ty * 4];
            float4 bv = *(const float4*)&Bs[k][tx * 4];
            float a[4] = {av.x, av.y, av.z, av.w};
            float b[4] = {bv.x, bv.y, bv.z, bv.w};
#pragma unroll
            for (int i = 0; i < 4; ++i)
#pragma unroll
                for (int j = 0; j < 4; ++j) acc[i][j] += a[i] * b[j];
        }
    }
#pragma unroll
    for (int i = 0; i < 4; ++i) {
        float4 o = {acc[i][0], acc[i][1], acc[i][2], acc[i][3]};
        *(float4*)(C + (size_t)(m0 + ty * 4 + i) * 512 + n0 + tx * 4) = o;
    }
}

// ---------------- fp16 GEMM: Cf16[M,Ntot] = A[M,512] @ B^T[Ntot,512] + bias ----------------
// CTA 128x128, BK=64, 8 chunks, 3-stage cp.async pipeline, smem-staged epilogue.
#define MG_SMEM 98304   // 3 stages x (16KB A + 16KB B)

template<bool RELU>
__global__ __launch_bounds__(256)
void gemm_f16(const __half* __restrict__ A, const __half* __restrict__ B,
              const float* __restrict__ bias, __half* __restrict__ Cf16, int Ntot)
{
    extern __shared__ char sm[];
    const uint32_t smS = smem_u32(sm);

    const int t = threadIdx.x;
    const int wid = t >> 5, l = t & 31;
    const int wm = wid >> 1, wn = wid & 1;
    const int m0 = blockIdx.y * 128, n0 = blockIdx.x * 128;

    const int arow = l & 15, acol = l >> 4;
    const int brow = (l & 7) + ((l >> 4) & 1) * 8, bcol = (l >> 3) & 1;
    const int lrow = t >> 3, lcg = t & 7;

    float acc[2][8][4];
#pragma unroll
    for (int mi = 0; mi < 2; ++mi)
#pragma unroll
        for (int ni = 0; ni < 8; ++ni)
#pragma unroll
            for (int q = 0; q < 4; ++q) acc[mi][ni][q] = 0.f;

    auto load_chunk = [&](int c, int s) {
        const int kk = c * 64;
        const uint32_t ab = smS + s * 32768;
        const uint32_t bb = ab + 16384;
#pragma unroll
        for (int i = 0; i < 4; ++i) {
            const int row = lrow + i * 32;
            const uint32_t off = SWZ((uint32_t)(row * 128 + lcg * 16));
            cpasync16(ab + off, A + (size_t)(m0 + row) * 512 + kk + lcg * 8);
            cpasync16(bb + off, B + (size_t)(n0 + row) * 512 + kk + lcg * 8);
        }
        CP_COMMIT();
    };

    auto compute = [&](int s) {
        const uint32_t ab = smS + s * 32768;
        const uint32_t bb = ab + 16384;
#pragma unroll
        for (int ks = 0; ks < 4; ++ks) {
            uint32_t a[2][4];
#pragma unroll
            for (int mi = 0; mi < 2; ++mi) {
                const int row = wm * 32 + mi * 16 + arow;
                ldsm4(a[mi], ab + SWZ((uint32_t)(row * 128 + (ks * 2 + acol) * 16)));
            }
#pragma unroll
            for (int nb = 0; nb < 4; ++nb) {
                const int row = wn * 64 + nb * 16 + brow;
                uint32_t b[4];
                ldsm4(b, bb + SWZ((uint32_t)(row * 128 + (ks * 2 + bcol) * 16)));
                mma_f16(acc[0][nb * 2],     a[0], b[0], b[1]);
                mma_f16(acc[1][nb * 2],     a[1], b[0], b[1]);
                mma_f16(acc[0][nb * 2 + 1], a[0], b[2], b[3]);
                mma_f16(acc[1][nb * 2 + 1], a[1], b[2], b[3]);
            }
        }
    };

    load_chunk(0, 0);
    load_chunk(1, 1);

    for (int c = 0; c < 8; ++c) {
        if (c < 6) { CP_WAIT(1); } else { CP_WAIT(0); }
        __syncthreads();
        if (c + 2 < 8) load_chunk(c + 2, (c + 2) % 3);
        compute(c % 3);
    }

    // epilogue: frags -> padded smem tile -> coalesced 16B stores
    const int gid = l >> 2, tig = l & 3;
    __syncthreads();
#pragma unroll
    for (int mi = 0; mi < 2; ++mi) {
#pragma unroll
        for (int ni = 0; ni < 8; ++ni) {
            const int row = wm * 32 + mi * 16 + gid;
            const int col = wn * 64 + ni * 8 + tig * 2;
            float2 bb = *(const float2*)(bias + n0 + col);
            float v0 = acc[mi][ni][0] + bb.x;
            float v1 = acc[mi][ni][1] + bb.y;
            float v2 = acc[mi][ni][2] + bb.x;
            float v3 = acc[mi][ni][3] + bb.y;
            if (RELU) {
                v0 = fmaxf(v0, 0.f); v1 = fmaxf(v1, 0.f);
                v2 = fmaxf(v2, 0.f); v3 = fmaxf(v3, 0.f);
            }
            __half2 u0 = __floats2half2_rn(v0, v1);
            __half2 u1 = __floats2half2_rn(v2, v3);
            *(__half2*)(sm + row * 272 + col * 2)       = u0;
            *(__half2*)(sm + (row + 8) * 272 + col * 2) = u1;
        }
    }
    __syncthreads();
#pragma unroll
    for (int i = 0; i < 8; ++i) {
        const int idx = t + i * 256;
        const int row = idx >> 4, seg = idx & 15;
        uint4 v = *(const uint4*)(sm + row * 272 + seg * 16);
        *(uint4*)(Cf16 + (size_t)(m0 + row) * Ntot + n0 + seg * 8) = v;
    }
}

// ---------------- tensor-core attention ----------------
#define A_SC    32768       // fp32 scores [64][68]
#define A_ATT   50176       // fp16 attn tile 64x64 (swizzled 128B rows)
#define A_GSH   58368       // gv fp32 [512]
#define A_WPART 60416       // fp32 [4][64]
#define A_WSH   61440       // fp32 [64]
#define ATTN_SMEM 61696

__global__ __launch_bounds__(256)
void attn_tc(const __half* __restrict__ Xf16, const __half* __restrict__ TVR,
             const float* __restrict__ gv, float* __restrict__ OUT)
{
    extern __shared__ char sm[];
    const uint32_t smS = smem_u32(sm);
    float* sc    = (float*)(sm + A_SC);
    float* gsh   = (float*)(sm + A_GSH);
    float* wpart = (float*)(sm + A_WPART);
    float* wsh   = (float*)(sm + A_WSH);

    const int b = blockIdx.x;
    const __half* Xb   = Xf16 + (size_t)b * 64 * 512;
    const __half* TVRb = TVR  + (size_t)b * 64 * NTVR;
    float*        Ob   = OUT  + (size_t)b * 64 * 512;

    const int t = threadIdx.x;
    const int wid = t >> 5, l = t & 31;
    const int wm = wid >> 1, wn = wid & 1;
    const int arow = l & 15, acol = l >> 4;
    const int brow = (l & 7) + ((l >> 4) & 1) * 8, bcol = (l >> 3) & 1;
    const int gid = l >> 2, tig = l & 3;

    auto load1 = [&](int kt, int s) {
#pragma unroll
        for (int i = 0; i < 2; ++i) {
            const int idx = t + i * 256;
            const int row = idx >> 3, cg = idx & 7;
            const uint32_t off = SWZ((uint32_t)(row * 128 + cg * 16));
            cpasync16(smS + s * 16384 + off,        TVRb + (size_t)row * NTVR + kt * 64 + cg * 8);
            cpasync16(smS + s * 16384 + 8192 + off, Xb   + (size_t)row * 512  + kt * 64 + cg * 8);
        }
        CP_COMMIT();
    };
    load1(0, 0);
    load1(1, 1);

    gsh[t]       = gv[t];
    gsh[t + 256] = gv[t + 256];
    __syncthreads();
    {
        const int r = t & 63, p = t >> 6;
        const __half* xr = Xb + r * 512 + p * 128;
        const float*  gp = gsh + p * 128;
        float s = 0.f;
#pragma unroll 8
        for (int d = 0; d < 64; ++d) {
            __half2 x2 = *(const __half2*)(xr + 2 * d);
            float2 xf = __half22float2(x2);
            s += xf.x * gp[2 * d] + xf.y * gp[2 * d + 1];
        }
        wpart[p * 64 + r] = s;
    }

    float acc1[4][4];
#pragma unroll
    for (int i = 0; i < 4; ++i)
#pragma unroll
        for (int j = 0; j < 4; ++j) acc1[i][j] = 0.f;

    auto compute1 = [&](int s) {
        const uint32_t tb = smS + s * 16384;
        const uint32_t xb = tb + 8192;
#pragma unroll
        for (int ks = 0; ks < 4; ++ks) {
            uint32_t a[4];
            ldsm4(a, tb + SWZ((uint32_t)((wm * 16 + arow) * 128 + (ks * 2 + acol) * 16)));
#pragma unroll
            for (int nb = 0; nb < 2; ++nb) {
                uint32_t bf[4];
                ldsm4(bf, xb + SWZ((uint32_t)((wn * 32 + nb * 16 + brow) * 128 + (ks * 2 + bcol) * 16)));
                mma_f16(acc1[nb * 2],     a, bf[0], bf[1]);
                mma_f16(acc1[nb * 2 + 1], a, bf[2], bf[3]);
            }
        }
    };

    CP_WAIT(1);
    __syncthreads();
    for (int c = 0; c < 8; ++c) {
        const int s = c & 1;
        compute1(s);
        if (c == 7) break;
        __syncthreads();
        if (c + 2 < 8) { load1(c + 2, s); CP_WAIT(1); }
        else           { CP_WAIT(0); }
        __syncthreads();
    }
    __syncthreads();

    if (t < 64)
        wsh[t] = wpart[t] + wpart[64 + t] + wpart[128 + t] + wpart[192 + t];
    __syncthreads();

#pragma unroll
    for (int nb = 0; nb < 4; ++nb) {
        const int col = wn * 32 + nb * 8 + tig * 2;
        const int r0 = wm * 16 + gid;
        sc[r0 * 68 + col]           = acc1[nb][0] + wsh[col];
        sc[r0 * 68 + col + 1]       = acc1[nb][1] + wsh[col + 1];
        sc[(r0 + 8) * 68 + col]     = acc1[nb][2] + wsh[col];
        sc[(r0 + 8) * 68 + col + 1] = acc1[nb][3] + wsh[col + 1];
    }
    __syncthreads();

    // parallel softmax: 4 threads per row, 16 cols each; writes attn fp16 tile directly
    {
        const int row = t >> 2, lane4 = t & 3;
        const float* scr = sc + row * 68 + lane4 * 16;
        float m = -1e30f;
#pragma unroll
        for (int j = 0; j < 16; ++j) m = fmaxf(m, scr[j]);
        m = fmaxf(m, __shfl_xor_sync(0xFFFFFFFFu, m, 1));
        m = fmaxf(m, __shfl_xor_sync(0xFFFFFFFFu, m, 2));
        float e[16];
        float s = 0.f;
#pragma unroll
        for (int j = 0; j < 16; ++j) { e[j] = __expf(scr[j] - m); s += e[j]; }
        s += __shfl_xor_sync(0xFFFFFFFFu, s, 1);
        s += __shfl_xor_sync(0xFFFFFFFFu, s, 2);
        const float inv = 1.f / s;
#pragma unroll
        for (int j = 0; j < 8; ++j) {
            const int col = lane4 * 16 + j * 2;
            __half2 h = __floats2half2_rn(e[2 * j] * inv, e[2 * j + 1] * inv);
            *(__half2*)(sm + A_ATT + SWZ((uint32_t)(row * 128 + col * 2))) = h;
        }
    }
    __syncthreads();

    auto loadVO = [&](int nt, int s) {
#pragma unroll
        for (int i = 0; i < 2; ++i) {
            const int idx = t + i * 256;
            const int row = idx >> 3, cg = idx & 7;
            cpasync16(smS + s * 16384 + SWZ((uint32_t)(row * 128 + cg * 16)),
                      TVRb + (size_t)row * NTVR + 512 + nt * 64 + cg * 8);
        }
        CP_COMMIT();
    };
    loadVO(0, 0);
    loadVO(1, 1);

    uint32_t a3[4][4];
    const uint32_t attb = smS + A_ATT;
#pragma unroll
    for (int ks = 0; ks < 4; ++ks)
        ldsm4(a3[ks], attb + SWZ((uint32_t)((wm * 16 + arow) * 128 + (ks * 2 + acol) * 16)));

    CP_WAIT(1);
    __syncthreads();

    const int trow = (l & 7) + ((l >> 3) & 1) * 8;
    const int tc8  = ((l >> 4) & 1) * 8;

    for (int nt = 0; nt < 8; ++nt) {
        const int s = nt & 1;
        const uint32_t vb = smS + s * 16384;
        float acc3[4][4];
#pragma unroll
        for (int i = 0; i < 4; ++i)
#pragma unroll
            for (int j = 0; j < 4; ++j) acc3[i][j] = 0.f;

#pragma unroll
        for (int ks = 0; ks < 4; ++ks) {
#pragma unroll
            for (int nb = 0; nb < 2; ++nb) {
                uint32_t bf[4];
                ldsm4t(bf, vb + SWZ((uint32_t)((ks * 16 + trow) * 128 +
                                               (wn * 32 + nb * 16 + tc8) * 2)));
                mma_f16(acc3[nb * 2],     a3[ks], bf[0], bf[1]);
                mma_f16(acc3[nb * 2 + 1], a3[ks], bf[2], bf[3]);
            }
        }

#pragma unroll
        for (int nb = 0; nb < 4; ++nb) {
            const int col = nt * 64 + wn * 32 + nb * 8 + tig * 2;
            const int r0 = wm * 16 + gid, r1 = r0 + 8;
            float2 ro0 = __half22float2(*(const __half2*)(TVRb + (size_t)r0 * NTVR + 1024 + col));
            float2 ro1 = __half22float2(*(const __half2*)(TVRb + (size_t)r1 * NTVR + 1024 + col));
            float2 o0 = {fmaxf(acc3[nb][0] + ro0.x, 0.f), fmaxf(acc3[nb][1] + ro0.y, 0.f)};
            float2 o1 = {fmaxf(acc3[nb][2] + ro1.x, 0.f), fmaxf(acc3[nb][3] + ro1.y, 0.f)};
            *(float2*)(Ob + (size_t)r0 * 512 + col) = o0;
            *(float2*)(Ob + (size_t)r1 * 512 + col) = o1;
        }

        if (nt == 7) break;
        __syncthreads();
        if (nt + 2 < 8) { loadVO(nt + 2, s); CP_WAIT(1); }
        else            { CP_WAIT(0); }
        __syncthreads();
    }
}

// ---------------- launch ----------------
extern "C" void kernel_launch(void* const* d_in, const int* in_sizes, int n_in,
                              void* d_out, int out_size)
{
    const float* inp = (const float*)d_in[0];
    const float* Win = (const float*)d_in[1];
    const float* bin = (const float*)d_in[2];
    const float* Wq  = (const float*)d_in[3];
    const float* bq  = (const float*)d_in[4];
    const float* Wk  = (const float*)d_in[5];
    // d_in[6] = b_k : provably unused (row-constant, drops out of softmax)
    const float* Wv  = (const float*)d_in[7];
    const float* bv  = (const float*)d_in[8];
    const float* Wr  = (const float*)d_in[9];
    const float* br  = (const float*)d_in[10];
    const float* Wo  = (const float*)d_in[11];
    const float* bo  = (const float*)d_in[12];
    float* out = (float*)d_out;

    float *W3, *gv, *bias2;
    __half *Xf16, *If16, *WinT, *Wb, *TVR;
    cudaGetSymbolAddress((void**)&TVR,   g_TVR);
    cudaGetSymbolAddress((void**)&W3,    g_W3);
    cudaGetSymbolAddress((void**)&gv,    g_gv);
    cudaGetSymbolAddress((void**)&bias2, g_bias2);
    cudaGetSymbolAddress((void**)&Xf16,  g_Xf16);
    cudaGetSymbolAddress((void**)&If16,  g_If16);
    cudaGetSymbolAddress((void**)&WinT,  g_WinT);
    cudaGetSymbolAddress((void**)&Wb,    g_Wb);

    cudaFuncSetAttribute(gemm_f16<true >, cudaFuncAttributeMaxDynamicSharedMemorySize, MG_SMEM);
    cudaFuncSetAttribute(gemm_f16<false>, cudaFuncAttributeMaxDynamicSharedMemorySize, MG_SMEM);
    cudaFuncSetAttribute(attn_tc,         cudaFuncAttributeMaxDynamicSharedMemorySize, ATTN_SMEM);

    const dim3 bs(256);
    const int n4 = MTOT * D_DIM / 4;

    // 1: vector precompute
    vec_pre_k<<<2, 512>>>(Wo, bv, br, bo, Wk, bq, gv, bias2);
    // 2: weight products Wqk/Wvo/Wro (fp32)
    wpre_k<<<dim3(8, 8, 3), bs>>>(Wq, Wk, Wv, Wr, Wo, W3);
    // 3: inputs -> fp16
    f16conv_k<<<(n4 + 255) / 256, 256>>>(inp, If16, n4);
    // 4: merged transpose->fp16 (Win + 3 derived)
    t_f16m_k<<<dim3(16, 16, 4), dim3(32, 32)>>>(Win, W3, WinT, Wb);
    // 5: gemm1
    gemm_f16<true ><<<dim3(4, 256),  bs, MG_SMEM>>>(If16, WinT, bin, Xf16, 512);
    // 6: gemm2
    gemm_f16<false><<<dim3(12, 256), bs, MG_SMEM>>>(Xf16, Wb, bias2, TVR, NTVR);
    // 7: attention
    attn_tc<<<NBATCH, bs, ATTN_SMEM>>>(Xf16, TVR, gv, out);
}

// round 11
// speedup vs baseline: 2.7157x; 1.2504x over previous
#include <cuda_runtime.h>
#include <cuda_fp16.h>
#include <cstdint>
#include <cstddef>

#define D_DIM 512
#define AGENTS 64
#define NBATCH 512
#define MTOT (NBATCH * AGENTS)   // 32768
#define NTVR 1536

// ---------------- scratch (device globals: allocation-free) ----------------
__device__ __align__(128) __half  g_Xf16[MTOT * D_DIM];
__device__ __align__(128) __half  g_If16[MTOT * D_DIM];
__device__ __align__(128) __half  g_TVR [MTOT * NTVR];
__device__ __align__(128) float   g_W3  [3 * D_DIM * D_DIM];   // Wqk | Wvo | Wro
__device__ __align__(128) __half  g_WinT[D_DIM * D_DIM];
__device__ __align__(128) __half  g_Wb  [NTVR * D_DIM];
__device__ __align__(128) float   g_gv  [D_DIM];
__device__ __align__(128) float   g_bias2[NTVR];

#define SWZ(o) ((o) ^ (((o) >> 3) & 0x70))

__device__ __forceinline__ uint32_t smem_u32(const void* p) {
    uint32_t a;
    asm("{ .reg .u64 t; cvta.to.shared.u64 t, %1; cvt.u32.u64 %0, t; }" : "=r"(a) : "l"(p));
    return a;
}
__device__ __forceinline__ void ldsm4(uint32_t* r, uint32_t addr) {
    asm volatile("ldmatrix.sync.aligned.m8n8.x4.shared.b16 {%0,%1,%2,%3}, [%4];"
                 : "=r"(r[0]), "=r"(r[1]), "=r"(r[2]), "=r"(r[3]) : "r"(addr));
}
__device__ __forceinline__ void ldsm4t(uint32_t* r, uint32_t addr) {
    asm volatile("ldmatrix.sync.aligned.m8n8.x4.trans.shared.b16 {%0,%1,%2,%3}, [%4];"
                 : "=r"(r[0]), "=r"(r[1]), "=r"(r[2]), "=r"(r[3]) : "r"(addr));
}
__device__ __forceinline__ void mma_f16(float* d, const uint32_t* a, uint32_t b0, uint32_t b1) {
    asm volatile(
        "mma.sync.aligned.m16n8k16.row.col.f32.f16.f16.f32 "
        "{%0,%1,%2,%3}, {%4,%5,%6,%7}, {%8,%9}, {%0,%1,%2,%3};"
        : "+f"(d[0]), "+f"(d[1]), "+f"(d[2]), "+f"(d[3])
        : "r"(a[0]), "r"(a[1]), "r"(a[2]), "r"(a[3]), "r"(b0), "r"(b1));
}
__device__ __forceinline__ void cpasync16(uint32_t dst, const void* src) {
    asm volatile("cp.async.cg.shared.global [%0], [%1], 16;" :: "r"(dst), "l"(src));
}
#define CP_COMMIT() asm volatile("cp.async.commit_group;" ::: "memory")
#define CP_WAIT(N)  asm volatile("cp.async.wait_group " #N ";" ::: "memory")

// ---------------- launch 1: weight products + vector precompute ----------------
// z=0..2: W3[z] fp32 GEMMs (Wqk = Wq@Wk^T ; Wvo = Wv@Wo ; Wro = Wr@Wo), 64x64 tiles
// z=3 (first 4 x-blocks, y==0): gv = Wk@bq ; bias2 = {0, bv@Wo, br@Wo+bo}
__global__ __launch_bounds__(256)
void wpre_k(const float* __restrict__ Wq, const float* __restrict__ Wk,
            const float* __restrict__ Wv, const float* __restrict__ Wr,
            const float* __restrict__ Wo,
            const float* __restrict__ bv, const float* __restrict__ br,
            const float* __restrict__ bo, const float* __restrict__ bq,
            float* __restrict__ W3, float* __restrict__ gv, float* __restrict__ bias2) {
    const int z = blockIdx.z;
    const int t = threadIdx.x;

    if (z == 3) {
        if (blockIdx.y != 0 || blockIdx.x >= 4) return;
        const int j = ((int)blockIdx.x & 1) * 256 + t;
        if (blockIdx.x < 2) {
            float s1 = 0.f, s2 = 0.f;
            for (int d = 0; d < D_DIM; ++d) {
                float w = Wo[d * D_DIM + j];
                s1 += bv[d] * w;
                s2 += br[d] * w;
            }
            bias2[512 + j]  = s1;
            bias2[1024 + j] = s2 + bo[j];
        } else {
            float s3 = 0.f;
            const float* wk = Wk + (size_t)j * D_DIM;
            for (int d = 0; d < D_DIM; ++d) s3 += wk[d] * bq[d];
            gv[j] = s3;
            bias2[j] = 0.f;
        }
        return;
    }

    const float* A = (z == 0) ? Wq : ((z == 1) ? Wv : Wr);
    const float* B = (z == 0) ? Wk : Wo;
    float* C = W3 + (size_t)z * D_DIM * D_DIM;
    const bool transb = (z == 0);

    __shared__ __align__(16) float As[32][72];
    __shared__ __align__(16) float Bs[32][72];
    const int tx = t & 15, ty = t >> 4;
    const int m0 = blockIdx.y * 64, n0 = blockIdx.x * 64;

    float acc[4][4];
#pragma unroll
    for (int i = 0; i < 4; ++i)
#pragma unroll
        for (int j = 0; j < 4; ++j) acc[i][j] = 0.f;

    for (int kt = 0; kt < 16; ++kt) {
        __syncthreads();
#pragma unroll
        for (int i = 0; i < 2; ++i) {
            const int idx = t + i * 256;
            const int row = idx >> 3, c4 = (idx & 7) * 4;
            float4 v = *(const float4*)(A + (size_t)(m0 + row) * 512 + kt * 32 + c4);
            As[c4 + 0][row] = v.x; As[c4 + 1][row] = v.y;
            As[c4 + 2][row] = v.z; As[c4 + 3][row] = v.w;
        }
        if (transb) {
#pragma unroll
            for (int i = 0; i < 2; ++i) {
                const int idx = t + i * 256;
                const int row = idx >> 3, c4 = (idx & 7) * 4;
                float4 v = *(const float4*)(B + (size_t)(n0 + row) * 512 + kt * 32 + c4);
                Bs[c4 + 0][row] = v.x; Bs[c4 + 1][row] = v.y;
                Bs[c4 + 2][row] = v.z; Bs[c4 + 3][row] = v.w;
            }
        } else {
#pragma unroll
            for (int i = 0; i < 2; ++i) {
                const int idx = t + i * 256;
                const int kr = idx >> 4, c4 = (idx & 15) * 4;
                float4 v = *(const float4*)(B + (size_t)(kt * 32 + kr) * 512 + n0 + c4);
                *(float4*)&Bs[kr][c4] = v;
            }
        }
        __syncthreads();
#pragma unroll
        for (int k = 0; k < 32; ++k) {
            float4 av = *(const float4*)&As[k][ty * 4];
            float4 bv2 = *(const float4*)&Bs[k][tx * 4];
            float a[4] = {av.x, av.y, av.z, av.w};
            float b[4] = {bv2.x, bv2.y, bv2.z, bv2.w};
#pragma unroll
            for (int i = 0; i < 4; ++i)
#pragma unroll
                for (int j = 0; j < 4; ++j) acc[i][j] += a[i] * b[j];
        }
    }
#pragma unroll
    for (int i = 0; i < 4; ++i) {
        float4 o = {acc[i][0], acc[i][1], acc[i][2], acc[i][3]};
        *(float4*)(C + (size_t)(m0 + ty * 4 + i) * 512 + n0 + tx * 4) = o;
    }
}

// ---------------- launch 2: input fp32->fp16 conversion + weight transposes ----------------
// blocks [0, 16384): convert inp -> If16 (float4 granularity)
// blocks [16384, 17408): transpose tile; z = idx/256 (0: Win->WinT, 1..3: W3->Wb)
#define PREP_CONV_BLOCKS 16384

__global__ __launch_bounds__(256)
void prep2_k(const float* __restrict__ inp, __half* __restrict__ If16,
             const float* __restrict__ Win, const float* __restrict__ W3,
             __half* __restrict__ WinT, __half* __restrict__ Wb) {
    __shared__ float tle[32][33];
    const int t = threadIdx.x;
    const int bid = blockIdx.x;

    if (bid < PREP_CONV_BLOCKS) {
        const int i = bid * 256 + t;
        float4 v = ((const float4*)inp)[i];
        __half h0 = __float2half_rn(v.x), h1 = __float2half_rn(v.y);
        __half h2 = __float2half_rn(v.z), h3 = __float2half_rn(v.w);
        uint32_t a = (uint32_t)__half_as_ushort(h0) | ((uint32_t)__half_as_ushort(h1) << 16);
        uint32_t b = (uint32_t)__half_as_ushort(h2) | ((uint32_t)__half_as_ushort(h3) << 16);
        ((uint2*)If16)[i] = make_uint2(a, b);
        return;
    }

    const int idx = bid - PREP_CONV_BLOCKS;       // 0..1023
    const int z = idx >> 8;                       // 0..3
    const int rem = idx & 255;
    const int bx = rem & 15, by = rem >> 4;
    const float* src = (z == 0) ? Win : (W3 + (size_t)(z - 1) * D_DIM * D_DIM);
    __half* dst      = (z == 0) ? WinT : (Wb + (size_t)(z - 1) * D_DIM * D_DIM);
    const int n0 = bx * 32, k0 = by * 32;
    const int tx = t & 31, tyg = t >> 5;          // 8 groups of 4 rows
#pragma unroll
    for (int r = 0; r < 4; ++r) {
        const int ty = tyg * 4 + r;
        tle[ty][tx] = src[(size_t)(k0 + ty) * 512 + n0 + tx];
    }
    __syncthreads();
#pragma unroll
    for (int r = 0; r < 4; ++r) {
        const int ty = tyg * 4 + r;
        dst[(size_t)(n0 + ty) * 512 + k0 + tx] = __float2half_rn(tle[tx][ty]);
    }
}

// ---------------- fp16 GEMM: Cf16[M,Ntot] = A[M,512] @ B^T[Ntot,512] + bias ----------------
// CTA 128x128, BK=64, 8 chunks, 3-stage cp.async pipeline, smem-staged epilogue.
#define MG_SMEM 98304   // 3 stages x (16KB A + 16KB B)

template<bool RELU>
__global__ __launch_bounds__(256)
void gemm_f16(const __half* __restrict__ A, const __half* __restrict__ B,
              const float* __restrict__ bias, __half* __restrict__ Cf16, int Ntot)
{
    extern __shared__ char sm[];
    const uint32_t smS = smem_u32(sm);

    const int t = threadIdx.x;
    const int wid = t >> 5, l = t & 31;
    const int wm = wid >> 1, wn = wid & 1;
    const int m0 = blockIdx.y * 128, n0 = blockIdx.x * 128;

    const int arow = l & 15, acol = l >> 4;
    const int brow = (l & 7) + ((l >> 4) & 1) * 8, bcol = (l >> 3) & 1;
    const int lrow = t >> 3, lcg = t & 7;

    float acc[2][8][4];
#pragma unroll
    for (int mi = 0; mi < 2; ++mi)
#pragma unroll
        for (int ni = 0; ni < 8; ++ni)
#pragma unroll
            for (int q = 0; q < 4; ++q) acc[mi][ni][q] = 0.f;

    auto load_chunk = [&](int c, int s) {
        const int kk = c * 64;
        const uint32_t ab = smS + s * 32768;
        const uint32_t bb = ab + 16384;
#pragma unroll
        for (int i = 0; i < 4; ++i) {
            const int row = lrow + i * 32;
            const uint32_t off = SWZ((uint32_t)(row * 128 + lcg * 16));
            cpasync16(ab + off, A + (size_t)(m0 + row) * 512 + kk + lcg * 8);
            cpasync16(bb + off, B + (size_t)(n0 + row) * 512 + kk + lcg * 8);
        }
        CP_COMMIT();
    };

    auto compute = [&](int s) {
        const uint32_t ab = smS + s * 32768;
        const uint32_t bb = ab + 16384;
#pragma unroll
        for (int ks = 0; ks < 4; ++ks) {
            uint32_t a[2][4];
#pragma unroll
            for (int mi = 0; mi < 2; ++mi) {
                const int row = wm * 32 + mi * 16 + arow;
                ldsm4(a[mi], ab + SWZ((uint32_t)(row * 128 + (ks * 2 + acol) * 16)));
            }
#pragma unroll
            for (int nb = 0; nb < 4; ++nb) {
                const int row = wn * 64 + nb * 16 + brow;
                uint32_t b[4];
                ldsm4(b, bb + SWZ((uint32_t)(row * 128 + (ks * 2 + bcol) * 16)));
                mma_f16(acc[0][nb * 2],     a[0], b[0], b[1]);
                mma_f16(acc[1][nb * 2],     a[1], b[0], b[1]);
                mma_f16(acc[0][nb * 2 + 1], a[0], b[2], b[3]);
                mma_f16(acc[1][nb * 2 + 1], a[1], b[2], b[3]);
            }
        }
    };

    load_chunk(0, 0);
    load_chunk(1, 1);

    for (int c = 0; c < 8; ++c) {
        if (c < 6) { CP_WAIT(1); } else { CP_WAIT(0); }
        __syncthreads();
        if (c + 2 < 8) load_chunk(c + 2, (c + 2) % 3);
        compute(c % 3);
    }

    // epilogue: frags -> padded smem tile -> coalesced 16B stores
    const int gid = l >> 2, tig = l & 3;
    __syncthreads();
#pragma unroll
    for (int mi = 0; mi < 2; ++mi) {
#pragma unroll
        for (int ni = 0; ni < 8; ++ni) {
            const int row = wm * 32 + mi * 16 + gid;
            const int col = wn * 64 + ni * 8 + tig * 2;
            float2 bb = *(const float2*)(bias + n0 + col);
            float v0 = acc[mi][ni][0] + bb.x;
            float v1 = acc[mi][ni][1] + bb.y;
            float v2 = acc[mi][ni][2] + bb.x;
            float v3 = acc[mi][ni][3] + bb.y;
            if (RELU) {
                v0 = fmaxf(v0, 0.f); v1 = fmaxf(v1, 0.f);
                v2 = fmaxf(v2, 0.f); v3 = fmaxf(v3, 0.f);
            }
            __half2 u0 = __floats2half2_rn(v0, v1);
            __half2 u1 = __floats2half2_rn(v2, v3);
            *(__half2*)(sm + row * 272 + col * 2)       = u0;
            *(__half2*)(sm + (row + 8) * 272 + col * 2) = u1;
        }
    }
    __syncthreads();
#pragma unroll
    for (int i = 0; i < 8; ++i) {
        const int idx = t + i * 256;
        const int row = idx >> 4, seg = idx & 15;
        uint4 v = *(const uint4*)(sm + row * 272 + seg * 16);
        *(uint4*)(Cf16 + (size_t)(m0 + row) * Ntot + n0 + seg * 8) = v;
    }
}

// ---------------- tensor-core attention ----------------
#define A_SC    32768       // fp32 scores [64][68]
#define A_ATT   50176       // fp16 attn tile 64x64 (swizzled 128B rows)
#define A_GSH   58368       // gv fp32 [512]
#define A_WPART 60416       // fp32 [4][64]
#define A_WSH   61440       // fp32 [64]
#define ATTN_SMEM 61696

__global__ __launch_bounds__(256)
void attn_tc(const __half* __restrict__ Xf16, const __half* __restrict__ TVR,
             const float* __restrict__ gv, float* __restrict__ OUT)
{
    extern __shared__ char sm[];
    const uint32_t smS = smem_u32(sm);
    float* sc    = (float*)(sm + A_SC);
    float* gsh   = (float*)(sm + A_GSH);
    float* wpart = (float*)(sm + A_WPART);
    float* wsh   = (float*)(sm + A_WSH);

    const int b = blockIdx.x;
    const __half* Xb   = Xf16 + (size_t)b * 64 * 512;
    const __half* TVRb = TVR  + (size_t)b * 64 * NTVR;
    float*        Ob   = OUT  + (size_t)b * 64 * 512;

    const int t = threadIdx.x;
    const int wid = t >> 5, l = t & 31;
    const int wm = wid >> 1, wn = wid & 1;
    const int arow = l & 15, acol = l >> 4;
    const int brow = (l & 7) + ((l >> 4) & 1) * 8, bcol = (l >> 3) & 1;
    const int gid = l >> 2, tig = l & 3;

    auto load1 = [&](int kt, int s) {
#pragma unroll
        for (int i = 0; i < 2; ++i) {
            const int idx = t + i * 256;
            const int row = idx >> 3, cg = idx & 7;
            const uint32_t off = SWZ((uint32_t)(row * 128 + cg * 16));
            cpasync16(smS + s * 16384 + off,        TVRb + (size_t)row * NTVR + kt * 64 + cg * 8);
            cpasync16(smS + s * 16384 + 8192 + off, Xb   + (size_t)row * 512  + kt * 64 + cg * 8);
        }
        CP_COMMIT();
    };
    load1(0, 0);
    load1(1, 1);

    gsh[t]       = gv[t];
    gsh[t + 256] = gv[t + 256];
    __syncthreads();
    {
        const int r = t & 63, p = t >> 6;
        const __half* xr = Xb + r * 512 + p * 128;
        const float*  gp = gsh + p * 128;
        float s = 0.f;
#pragma unroll 8
        for (int d = 0; d < 64; ++d) {
            __half2 x2 = *(const __half2*)(xr + 2 * d);
            float2 xf = __half22float2(x2);
            s += xf.x * gp[2 * d] + xf.y * gp[2 * d + 1];
        }
        wpart[p * 64 + r] = s;
    }

    float acc1[4][4];
#pragma unroll
    for (int i = 0; i < 4; ++i)
#pragma unroll
        for (int j = 0; j < 4; ++j) acc1[i][j] = 0.f;

    auto compute1 = [&](int s) {
        const uint32_t tb = smS + s * 16384;
        const uint32_t xb = tb + 8192;
#pragma unroll
        for (int ks = 0; ks < 4; ++ks) {
            uint32_t a[4];
            ldsm4(a, tb + SWZ((uint32_t)((wm * 16 + arow) * 128 + (ks * 2 + acol) * 16)));
#pragma unroll
            for (int nb = 0; nb < 2; ++nb) {
                uint32_t bf[4];
                ldsm4(bf, xb + SWZ((uint32_t)((wn * 32 + nb * 16 + brow) * 128 + (ks * 2 + bcol) * 16)));
                mma_f16(acc1[nb * 2],     a, bf[0], bf[1]);
                mma_f16(acc1[nb * 2 + 1], a, bf[2], bf[3]);
            }
        }
    };

    CP_WAIT(1);
    __syncthreads();
    for (int c = 0; c < 8; ++c) {
        const int s = c & 1;
        compute1(s);
        if (c == 7) break;
        __syncthreads();
        if (c + 2 < 8) { load1(c + 2, s); CP_WAIT(1); }
        else           { CP_WAIT(0); }
        __syncthreads();
    }
    __syncthreads();

    if (t < 64)
        wsh[t] = wpart[t] + wpart[64 + t] + wpart[128 + t] + wpart[192 + t];
    __syncthreads();

#pragma unroll
    for (int nb = 0; nb < 4; ++nb) {
        const int col = wn * 32 + nb * 8 + tig * 2;
        const int r0 = wm * 16 + gid;
        sc[r0 * 68 + col]           = acc1[nb][0] + wsh[col];
        sc[r0 * 68 + col + 1]       = acc1[nb][1] + wsh[col + 1];
        sc[(r0 + 8) * 68 + col]     = acc1[nb][2] + wsh[col];
        sc[(r0 + 8) * 68 + col + 1] = acc1[nb][3] + wsh[col + 1];
    }
    __syncthreads();

    // parallel softmax: 4 threads per row, 16 cols each; writes attn fp16 tile directly
    {
        const int row = t >> 2, lane4 = t & 3;
        const float* scr = sc + row * 68 + lane4 * 16;
        float m = -1e30f;
#pragma unroll
        for (int j = 0; j < 16; ++j) m = fmaxf(m, scr[j]);
        m = fmaxf(m, __shfl_xor_sync(0xFFFFFFFFu, m, 1));
        m = fmaxf(m, __shfl_xor_sync(0xFFFFFFFFu, m, 2));
        float e[16];
        float s = 0.f;
#pragma unroll
        for (int j = 0; j < 16; ++j) { e[j] = __expf(scr[j] - m); s += e[j]; }
        s += __shfl_xor_sync(0xFFFFFFFFu, s, 1);
        s += __shfl_xor_sync(0xFFFFFFFFu, s, 2);
        const float inv = 1.f / s;
#pragma unroll
        for (int j = 0; j < 8; ++j) {
            const int col = lane4 * 16 + j * 2;
            __half2 h = __floats2half2_rn(e[2 * j] * inv, e[2 * j + 1] * inv);
            *(__half2*)(sm + A_ATT + SWZ((uint32_t)(row * 128 + col * 2))) = h;
        }
    }
    __syncthreads();

    auto loadVO = [&](int nt, int s) {
#pragma unroll
        for (int i = 0; i < 2; ++i) {
            const int idx = t + i * 256;
            const int row = idx >> 3, cg = idx & 7;
            cpasync16(smS + s * 16384 + SWZ((uint32_t)(row * 128 + cg * 16)),
                      TVRb + (size_t)row * NTVR + 512 + nt * 64 + cg * 8);
        }
        CP_COMMIT();
    };
    loadVO(0, 0);
    loadVO(1, 1);

    uint32_t a3[4][4];
    const uint32_t attb = smS + A_ATT;
#pragma unroll
    for (int ks = 0; ks < 4; ++ks)
        ldsm4(a3[ks], attb + SWZ((uint32_t)((wm * 16 + arow) * 128 + (ks * 2 + acol) * 16)));

    CP_WAIT(1);
    __syncthreads();

    const int trow = (l & 7) + ((l >> 3) & 1) * 8;
    const int tc8  = ((l >> 4) & 1) * 8;

    for (int nt = 0; nt < 8; ++nt) {
        const int s = nt & 1;
        const uint32_t vb = smS + s * 16384;
        float acc3[4][4];
#pragma unroll
        for (int i = 0; i < 4; ++i)
#pragma unroll
            for (int j = 0; j < 4; ++j) acc3[i][j] = 0.f;

#pragma unroll
        for (int ks = 0; ks < 4; ++ks) {
#pragma unroll
            for (int nb = 0; nb < 2; ++nb) {
                uint32_t bf[4];
                ldsm4t(bf, vb + SWZ((uint32_t)((ks * 16 + trow) * 128 +
                                               (wn * 32 + nb * 16 + tc8) * 2)));
                mma_f16(acc3[nb * 2],     a3[ks], bf[0], bf[1]);
                mma_f16(acc3[nb * 2 + 1], a3[ks], bf[2], bf[3]);
            }
        }

#pragma unroll
        for (int nb = 0; nb < 4; ++nb) {
            const int col = nt * 64 + wn * 32 + nb * 8 + tig * 2;
            const int r0 = wm * 16 + gid, r1 = r0 + 8;
            float2 ro0 = __half22float2(*(const __half2*)(TVRb + (size_t)r0 * NTVR + 1024 + col));
            float2 ro1 = __half22float2(*(const __half2*)(TVRb + (size_t)r1 * NTVR + 1024 + col));
            float2 o0 = {fmaxf(acc3[nb][0] + ro0.x, 0.f), fmaxf(acc3[nb][1] + ro0.y, 0.f)};
            float2 o1 = {fmaxf(acc3[nb][2] + ro1.x, 0.f), fmaxf(acc3[nb][3] + ro1.y, 0.f)};
            *(float2*)(Ob + (size_t)r0 * 512 + col) = o0;
            *(float2*)(Ob + (size_t)r1 * 512 + col) = o1;
        }

        if (nt == 7) break;
        __syncthreads();
        if (nt + 2 < 8) { loadVO(nt + 2, s); CP_WAIT(1); }
        else            { CP_WAIT(0); }
        __syncthreads();
    }
}

// ---------------- launch ----------------
extern "C" void kernel_launch(void* const* d_in, const int* in_sizes, int n_in,
                              void* d_out, int out_size)
{
    const float* inp = (const float*)d_in[0];
    const float* Win = (const float*)d_in[1];
    const float* bin = (const float*)d_in[2];
    const float* Wq  = (const float*)d_in[3];
    const float* bq  = (const float*)d_in[4];
    const float* Wk  = (const float*)d_in[5];
    // d_in[6] = b_k : provably unused (row-constant, drops out of softmax)
    const float* Wv  = (const float*)d_in[7];
    const float* bv  = (const float*)d_in[8];
    const float* Wr  = (const float*)d_in[9];
    const float* br  = (const float*)d_in[10];
    const float* Wo  = (const float*)d_in[11];
    const float* bo  = (const float*)d_in[12];
    float* out = (float*)d_out;

    float *W3, *gv, *bias2;
    __half *Xf16, *If16, *WinT, *Wb, *TVR;
    cudaGetSymbolAddress((void**)&TVR,   g_TVR);
    cudaGetSymbolAddress((void**)&W3,    g_W3);
    cudaGetSymbolAddress((void**)&gv,    g_gv);
    cudaGetSymbolAddress((void**)&bias2, g_bias2);
    cudaGetSymbolAddress((void**)&Xf16,  g_Xf16);
    cudaGetSymbolAddress((void**)&If16,  g_If16);
    cudaGetSymbolAddress((void**)&WinT,  g_WinT);
    cudaGetSymbolAddress((void**)&Wb,    g_Wb);

    cudaFuncSetAttribute(gemm_f16<true >, cudaFuncAttributeMaxDynamicSharedMemorySize, MG_SMEM);
    cudaFuncSetAttribute(gemm_f16<false>, cudaFuncAttributeMaxDynamicSharedMemorySize, MG_SMEM);
    cudaFuncSetAttribute(attn_tc,         cudaFuncAttributeMaxDynamicSharedMemorySize, ATTN_SMEM);

    const dim3 bs(256);

    // 1: weight products + vectors
    wpre_k<<<dim3(8, 8, 4), bs>>>(Wq, Wk, Wv, Wr, Wo, bv, br, bo, bq, W3, gv, bias2);
    // 2: input conversion + weight transposes
    prep2_k<<<PREP_CONV_BLOCKS + 1024, bs>>>(inp, If16, Win, W3, WinT, Wb);
    // 3: gemm1
    gemm_f16<true ><<<dim3(4, 256),  bs, MG_SMEM>>>(If16, WinT, bin, Xf16, 512);
    // 4: gemm2  <-- expected ncu capture slot (our 4th launch)
    gemm_f16<false><<<dim3(12, 256), bs, MG_SMEM>>>(Xf16, Wb, bias2, TVR, NTVR);
    // 5: attention
    attn_tc<<<NBATCH, bs, ATTN_SMEM>>>(Xf16, TVR, gv, out);
}

// round 12
// speedup vs baseline: 2.8511x; 1.0499x over previous
#include <cuda_runtime.h>
#include <cuda_fp16.h>
#include <cstdint>
#include <cstddef>

#define D_DIM 512
#define AGENTS 64
#define NBATCH 512
#define MTOT (NBATCH * AGENTS)   // 32768
#define NTVR 1536

// ---------------- scratch (device globals: allocation-free) ----------------
__device__ __align__(128) __half  g_Xf16[MTOT * D_DIM];
__device__ __align__(128) __half  g_If16[MTOT * D_DIM];
__device__ __align__(128) __half  g_TVR [MTOT * NTVR];
__device__ __align__(128) float   g_W3  [3 * D_DIM * D_DIM];   // Wqk | Wvo | Wro
__device__ __align__(128) __half  g_WinT[D_DIM * D_DIM];
__device__ __align__(128) __half  g_Wb  [NTVR * D_DIM];
__device__ __align__(128) float   g_bias2[NTVR];

#define SWZ(o) ((o) ^ (((o) >> 3) & 0x70))

__device__ __forceinline__ uint32_t smem_u32(const void* p) {
    uint32_t a;
    asm("{ .reg .u64 t; cvta.to.shared.u64 t, %1; cvt.u32.u64 %0, t; }" : "=r"(a) : "l"(p));
    return a;
}
__device__ __forceinline__ void ldsm4(uint32_t* r, uint32_t addr) {
    asm volatile("ldmatrix.sync.aligned.m8n8.x4.shared.b16 {%0,%1,%2,%3}, [%4];"
                 : "=r"(r[0]), "=r"(r[1]), "=r"(r[2]), "=r"(r[3]) : "r"(addr));
}
__device__ __forceinline__ void ldsm4t(uint32_t* r, uint32_t addr) {
    asm volatile("ldmatrix.sync.aligned.m8n8.x4.trans.shared.b16 {%0,%1,%2,%3}, [%4];"
                 : "=r"(r[0]), "=r"(r[1]), "=r"(r[2]), "=r"(r[3]) : "r"(addr));
}
__device__ __forceinline__ void mma_f16(float* d, const uint32_t* a, uint32_t b0, uint32_t b1) {
    asm volatile(
        "mma.sync.aligned.m16n8k16.row.col.f32.f16.f16.f32 "
        "{%0,%1,%2,%3}, {%4,%5,%6,%7}, {%8,%9}, {%0,%1,%2,%3};"
        : "+f"(d[0]), "+f"(d[1]), "+f"(d[2]), "+f"(d[3])
        : "r"(a[0]), "r"(a[1]), "r"(a[2]), "r"(a[3]), "r"(b0), "r"(b1));
}
__device__ __forceinline__ void cpasync16(uint32_t dst, const void* src) {
    asm volatile("cp.async.cg.shared.global [%0], [%1], 16;" :: "r"(dst), "l"(src));
}
#define CP_COMMIT() asm volatile("cp.async.commit_group;" ::: "memory")
#define CP_WAIT(N)  asm volatile("cp.async.wait_group " #N ";" ::: "memory")

// ---------------- launch 1: weight products + vector precompute ----------------
// z=0..2: W3[z] fp32 GEMMs ; z=3: bias2 = {gv = Wk@bq, bv@Wo, br@Wo+bo}
__global__ __launch_bounds__(256)
void wpre_k(const float* __restrict__ Wq, const float* __restrict__ Wk,
            const float* __restrict__ Wv, const float* __restrict__ Wr,
            const float* __restrict__ Wo,
            const float* __restrict__ bv, const float* __restrict__ br,
            const float* __restrict__ bo, const float* __restrict__ bq,
            float* __restrict__ W3, float* __restrict__ bias2) {
    const int z = blockIdx.z;
    const int t = threadIdx.x;

    if (z == 3) {
        if (blockIdx.y != 0 || blockIdx.x >= 4) return;
        const int j = ((int)blockIdx.x & 1) * 256 + t;
        if (blockIdx.x < 2) {
            float s1 = 0.f, s2 = 0.f;
            for (int d = 0; d < D_DIM; ++d) {
                float w = Wo[d * D_DIM + j];
                s1 += bv[d] * w;
                s2 += br[d] * w;
            }
            bias2[512 + j]  = s1;
            bias2[1024 + j] = s2 + bo[j];
        } else {
            // bias2[0:512] = gv = Wk @ bq  (folds the score row-bias into T via gemm2)
            float s3 = 0.f;
            const float* wk = Wk + (size_t)j * D_DIM;
            for (int d = 0; d < D_DIM; ++d) s3 += wk[d] * bq[d];
            bias2[j] = s3;
        }
        return;
    }

    const float* A = (z == 0) ? Wq : ((z == 1) ? Wv : Wr);
    const float* B = (z == 0) ? Wk : Wo;
    float* C = W3 + (size_t)z * D_DIM * D_DIM;
    const bool transb = (z == 0);

    __shared__ __align__(16) float As[32][72];
    __shared__ __align__(16) float Bs[32][72];
    const int tx = t & 15, ty = t >> 4;
    const int m0 = blockIdx.y * 64, n0 = blockIdx.x * 64;

    float acc[4][4];
#pragma unroll
    for (int i = 0; i < 4; ++i)
#pragma unroll
        for (int j = 0; j < 4; ++j) acc[i][j] = 0.f;

    for (int kt = 0; kt < 16; ++kt) {
        __syncthreads();
#pragma unroll
        for (int i = 0; i < 2; ++i) {
            const int idx = t + i * 256;
            const int row = idx >> 3, c4 = (idx & 7) * 4;
            float4 v = *(const float4*)(A + (size_t)(m0 + row) * 512 + kt * 32 + c4);
            As[c4 + 0][row] = v.x; As[c4 + 1][row] = v.y;
            As[c4 + 2][row] = v.z; As[c4 + 3][row] = v.w;
        }
        if (transb) {
#pragma unroll
            for (int i = 0; i < 2; ++i) {
                const int idx = t + i * 256;
                const int row = idx >> 3, c4 = (idx & 7) * 4;
                float4 v = *(const float4*)(B + (size_t)(n0 + row) * 512 + kt * 32 + c4);
                Bs[c4 + 0][row] = v.x; Bs[c4 + 1][row] = v.y;
                Bs[c4 + 2][row] = v.z; Bs[c4 + 3][row] = v.w;
            }
        } else {
#pragma unroll
            for (int i = 0; i < 2; ++i) {
                const int idx = t + i * 256;
                const int kr = idx >> 4, c4 = (idx & 15) * 4;
                float4 v = *(const float4*)(B + (size_t)(kt * 32 + kr) * 512 + n0 + c4);
                *(float4*)&Bs[kr][c4] = v;
            }
        }
        __syncthreads();
#pragma unroll
        for (int k = 0; k < 32; ++k) {
            float4 av = *(const float4*)&As[k][ty * 4];
            float4 bv2 = *(const float4*)&Bs[k][tx * 4];
            float a[4] = {av.x, av.y, av.z, av.w};
            float b[4] = {bv2.x, bv2.y, bv2.z, bv2.w};
#pragma unroll
            for (int i = 0; i < 4; ++i)
#pragma unroll
                for (int j = 0; j < 4; ++j) acc[i][j] += a[i] * b[j];
        }
    }
#pragma unroll
    for (int i = 0; i < 4; ++i) {
        float4 o = {acc[i][0], acc[i][1], acc[i][2], acc[i][3]};
        *(float4*)(C + (size_t)(m0 + ty * 4 + i) * 512 + n0 + tx * 4) = o;
    }
}

// ---------------- launch 2: input fp32->fp16 conversion + weight transposes ----------------
#define PREP_CONV_BLOCKS 16384

__global__ __launch_bounds__(256)
void prep2_k(const float* __restrict__ inp, __half* __restrict__ If16,
             const float* __restrict__ Win, const float* __restrict__ W3,
             __half* __restrict__ WinT, __half* __restrict__ Wb) {
    __shared__ float tle[32][33];
    const int t = threadIdx.x;
    const int bid = blockIdx.x;

    if (bid < PREP_CONV_BLOCKS) {
        const int i = bid * 256 + t;
        float4 v = ((const float4*)inp)[i];
        __half h0 = __float2half_rn(v.x), h1 = __float2half_rn(v.y);
        __half h2 = __float2half_rn(v.z), h3 = __float2half_rn(v.w);
        uint32_t a = (uint32_t)__half_as_ushort(h0) | ((uint32_t)__half_as_ushort(h1) << 16);
        uint32_t b = (uint32_t)__half_as_ushort(h2) | ((uint32_t)__half_as_ushort(h3) << 16);
        ((uint2*)If16)[i] = make_uint2(a, b);
        return;
    }

    const int idx = bid - PREP_CONV_BLOCKS;       // 0..1023
    const int z = idx >> 8;                       // 0..3
    const int rem = idx & 255;
    const int bx = rem & 15, by = rem >> 4;
    const float* src = (z == 0) ? Win : (W3 + (size_t)(z - 1) * D_DIM * D_DIM);
    __half* dst      = (z == 0) ? WinT : (Wb + (size_t)(z - 1) * D_DIM * D_DIM);
    const int n0 = bx * 32, k0 = by * 32;
    const int tx = t & 31, tyg = t >> 5;
#pragma unroll
    for (int r = 0; r < 4; ++r) {
        const int ty = tyg * 4 + r;
        tle[ty][tx] = src[(size_t)(k0 + ty) * 512 + n0 + tx];
    }
    __syncthreads();
#pragma unroll
    for (int r = 0; r < 4; ++r) {
        const int ty = tyg * 4 + r;
        dst[(size_t)(n0 + ty) * 512 + k0 + tx] = __float2half_rn(tle[tx][ty]);
    }
}

// ---------------- fp16 GEMM: Cf16[M,Ntot] = A[M,512] @ B^T[Ntot,512] + bias ----------------
#define MG_SMEM 98304   // 3 stages x (16KB A + 16KB B)

template<bool RELU>
__global__ __launch_bounds__(256)
void gemm_f16(const __half* __restrict__ A, const __half* __restrict__ B,
              const float* __restrict__ bias, __half* __restrict__ Cf16, int Ntot)
{
    extern __shared__ char sm[];
    const uint32_t smS = smem_u32(sm);

    const int t = threadIdx.x;
    const int wid = t >> 5, l = t & 31;
    const int wm = wid >> 1, wn = wid & 1;
    const int m0 = blockIdx.y * 128, n0 = blockIdx.x * 128;

    const int arow = l & 15, acol = l >> 4;
    const int brow = (l & 7) + ((l >> 4) & 1) * 8, bcol = (l >> 3) & 1;
    const int lrow = t >> 3, lcg = t & 7;

    float acc[2][8][4];
#pragma unroll
    for (int mi = 0; mi < 2; ++mi)
#pragma unroll
        for (int ni = 0; ni < 8; ++ni)
#pragma unroll
            for (int q = 0; q < 4; ++q) acc[mi][ni][q] = 0.f;

    auto load_chunk = [&](int c, int s) {
        const int kk = c * 64;
        const uint32_t ab = smS + s * 32768;
        const uint32_t bb = ab + 16384;
#pragma unroll
        for (int i = 0; i < 4; ++i) {
            const int row = lrow + i * 32;
            const uint32_t off = SWZ((uint32_t)(row * 128 + lcg * 16));
            cpasync16(ab + off, A + (size_t)(m0 + row) * 512 + kk + lcg * 8);
            cpasync16(bb + off, B + (size_t)(n0 + row) * 512 + kk + lcg * 8);
        }
        CP_COMMIT();
    };

    auto compute = [&](int s) {
        const uint32_t ab = smS + s * 32768;
        const uint32_t bb = ab + 16384;
#pragma unroll
        for (int ks = 0; ks < 4; ++ks) {
            uint32_t a[2][4];
#pragma unroll
            for (int mi = 0; mi < 2; ++mi) {
                const int row = wm * 32 + mi * 16 + arow;
                ldsm4(a[mi], ab + SWZ((uint32_t)(row * 128 + (ks * 2 + acol) * 16)));
            }
#pragma unroll
            for (int nb = 0; nb < 4; ++nb) {
                const int row = wn * 64 + nb * 16 + brow;
                uint32_t b[4];
                ldsm4(b, bb + SWZ((uint32_t)(row * 128 + (ks * 2 + bcol) * 16)));
                mma_f16(acc[0][nb * 2],     a[0], b[0], b[1]);
                mma_f16(acc[1][nb * 2],     a[1], b[0], b[1]);
                mma_f16(acc[0][nb * 2 + 1], a[0], b[2], b[3]);
                mma_f16(acc[1][nb * 2 + 1], a[1], b[2], b[3]);
            }
        }
    };

    load_chunk(0, 0);
    load_chunk(1, 1);

    for (int c = 0; c < 8; ++c) {
        if (c < 6) { CP_WAIT(1); } else { CP_WAIT(0); }
        __syncthreads();
        if (c + 2 < 8) load_chunk(c + 2, (c + 2) % 3);
        compute(c % 3);
    }

    const int gid = l >> 2, tig = l & 3;
    __syncthreads();
#pragma unroll
    for (int mi = 0; mi < 2; ++mi) {
#pragma unroll
        for (int ni = 0; ni < 8; ++ni) {
            const int row = wm * 32 + mi * 16 + gid;
            const int col = wn * 64 + ni * 8 + tig * 2;
            float2 bb = *(const float2*)(bias + n0 + col);
            float v0 = acc[mi][ni][0] + bb.x;
            float v1 = acc[mi][ni][1] + bb.y;
            float v2 = acc[mi][ni][2] + bb.x;
            float v3 = acc[mi][ni][3] + bb.y;
            if (RELU) {
                v0 = fmaxf(v0, 0.f); v1 = fmaxf(v1, 0.f);
                v2 = fmaxf(v2, 0.f); v3 = fmaxf(v3, 0.f);
            }
            __half2 u0 = __floats2half2_rn(v0, v1);
            __half2 u1 = __floats2half2_rn(v2, v3);
            *(__half2*)(sm + row * 272 + col * 2)       = u0;
            *(__half2*)(sm + (row + 8) * 272 + col * 2) = u1;
        }
    }
    __syncthreads();
#pragma unroll
    for (int i = 0; i < 8; ++i) {
        const int idx = t + i * 256;
        const int row = idx >> 4, seg = idx & 15;
        uint4 v = *(const uint4*)(sm + row * 272 + seg * 16);
        *(uint4*)(Cf16 + (size_t)(m0 + row) * Ntot + n0 + seg * 8) = v;
    }
}

// ---------------- tensor-core attention ----------------
// scores = T'f16 @ Xf16^T  (gv pre-folded into T' via gemm2 bias)
// attn = softmax rows (fp32); OUT = relu(attnf16 @ VOf16 + RO).
#define A_SC    49152                    // after 3 x 16KB stages
#define A_ATT   (A_SC + 17408)           // fp16 attn tile, swizzled 128B rows
#define ATTN_SMEM (A_ATT + 8192)         // 74752

__global__ __launch_bounds__(256)
void attn_tc(const __half* __restrict__ Xf16, const __half* __restrict__ TVR,
             float* __restrict__ OUT)
{
    extern __shared__ char sm[];
    const uint32_t smS = smem_u32(sm);
    float* sc = (float*)(sm + A_SC);

    const int b = blockIdx.x;
    const __half* Xb   = Xf16 + (size_t)b * 64 * 512;
    const __half* TVRb = TVR  + (size_t)b * 64 * NTVR;
    float*        Ob   = OUT  + (size_t)b * 64 * 512;

    const int t = threadIdx.x;
    const int wid = t >> 5, l = t & 31;
    const int wm = wid >> 1, wn = wid & 1;
    const int arow = l & 15, acol = l >> 4;
    const int brow = (l & 7) + ((l >> 4) & 1) * 8, bcol = (l >> 3) & 1;
    const int gid = l >> 2, tig = l & 3;

    // ---- phase 1: scores over K=512, 8 chunks of 64, 3-stage pipeline ----
    auto load1 = [&](int kt, int s) {
#pragma unroll
        for (int i = 0; i < 2; ++i) {
            const int idx = t + i * 256;
            const int row = idx >> 3, cg = idx & 7;
            const uint32_t off = SWZ((uint32_t)(row * 128 + cg * 16));
            cpasync16(smS + s * 16384 + off,        TVRb + (size_t)row * NTVR + kt * 64 + cg * 8);
            cpasync16(smS + s * 16384 + 8192 + off, Xb   + (size_t)row * 512  + kt * 64 + cg * 8);
        }
        CP_COMMIT();
    };

    float acc1[4][4];
#pragma unroll
    for (int i = 0; i < 4; ++i)
#pragma unroll
        for (int j = 0; j < 4; ++j) acc1[i][j] = 0.f;

    auto compute1 = [&](int s) {
        const uint32_t tb = smS + s * 16384;
        const uint32_t xb = tb + 8192;
#pragma unroll
        for (int ks = 0; ks < 4; ++ks) {
            uint32_t a[4];
            ldsm4(a, tb + SWZ((uint32_t)((wm * 16 + arow) * 128 + (ks * 2 + acol) * 16)));
#pragma unroll
            for (int nb = 0; nb < 2; ++nb) {
                uint32_t bf[4];
                ldsm4(bf, xb + SWZ((uint32_t)((wn * 32 + nb * 16 + brow) * 128 + (ks * 2 + bcol) * 16)));
                mma_f16(acc1[nb * 2],     a, bf[0], bf[1]);
                mma_f16(acc1[nb * 2 + 1], a, bf[2], bf[3]);
            }
        }
    };

    load1(0, 0);
    load1(1, 1);
    for (int c = 0; c < 8; ++c) {
        if (c < 6) { CP_WAIT(1); } else { CP_WAIT(0); }
        __syncthreads();
        if (c + 2 < 8) load1(c + 2, (c + 2) % 3);
        compute1(c % 3);
    }

    // ---- prefetch VO tiles 0,1 (hidden behind score write + softmax) ----
    auto loadVO = [&](int nt, int s) {
#pragma unroll
        for (int i = 0; i < 2; ++i) {
            const int idx = t + i * 256;
            const int row = idx >> 3, cg = idx & 7;
            cpasync16(smS + s * 16384 + SWZ((uint32_t)(row * 128 + cg * 16)),
                      TVRb + (size_t)row * NTVR + 512 + nt * 64 + cg * 8);
        }
        CP_COMMIT();
    };
    __syncthreads();           // all phase-1 computes done; stages reusable
    loadVO(0, 0);
    loadVO(1, 1);

    // ---- scores -> smem ----
#pragma unroll
    for (int nb = 0; nb < 4; ++nb) {
        const int col = wn * 32 + nb * 8 + tig * 2;
        const int r0 = wm * 16 + gid;
        sc[r0 * 68 + col]           = acc1[nb][0];
        sc[r0 * 68 + col + 1]       = acc1[nb][1];
        sc[(r0 + 8) * 68 + col]     = acc1[nb][2];
        sc[(r0 + 8) * 68 + col + 1] = acc1[nb][3];
    }
    __syncthreads();

    // ---- parallel softmax: 4 threads per row, writes fp16 attn tile ----
    {
        const int row = t >> 2, lane4 = t & 3;
        const float* scr = sc + row * 68 + lane4 * 16;
        float m = -1e30f;
#pragma unroll
        for (int j = 0; j < 16; ++j) m = fmaxf(m, scr[j]);
        m = fmaxf(m, __shfl_xor_sync(0xFFFFFFFFu, m, 1));
        m = fmaxf(m, __shfl_xor_sync(0xFFFFFFFFu, m, 2));
        float e[16];
        float s = 0.f;
#pragma unroll
        for (int j = 0; j < 16; ++j) { e[j] = __expf(scr[j] - m); s += e[j]; }
        s += __shfl_xor_sync(0xFFFFFFFFu, s, 1);
        s += __shfl_xor_sync(0xFFFFFFFFu, s, 2);
        const float inv = 1.f / s;
#pragma unroll
        for (int j = 0; j < 8; ++j) {
            const int col = lane4 * 16 + j * 2;
            __half2 h = __floats2half2_rn(e[2 * j] * inv, e[2 * j + 1] * inv);
            *(__half2*)(sm + A_ATT + SWZ((uint32_t)(row * 128 + col * 2))) = h;
        }
    }
    __syncthreads();

    // ---- attn A-frags (K=64 -> 4 k16 steps) ----
    uint32_t a3[4][4];
    const uint32_t attb = smS + A_ATT;
#pragma unroll
    for (int ks = 0; ks < 4; ++ks)
        ldsm4(a3[ks], attb + SWZ((uint32_t)((wm * 16 + arow) * 128 + (ks * 2 + acol) * 16)));

    // ---- phase 3: OUT = relu(attn @ VO + RO), 3-stage over 8 n-tiles ----
    const int trow = (l & 7) + ((l >> 3) & 1) * 8;
    const int tc8  = ((l >> 4) & 1) * 8;

    for (int nt = 0; nt < 8; ++nt) {
        if (nt < 6) { CP_WAIT(1); } else { CP_WAIT(0); }
        __syncthreads();
        if (nt + 2 < 8) loadVO(nt + 2, (nt + 2) % 3);

        const uint32_t vb = smS + (nt % 3) * 16384;
        float acc3[4][4];
#pragma unroll
        for (int i = 0; i < 4; ++i)
#pragma unroll
            for (int j = 0; j < 4; ++j) acc3[i][j] = 0.f;

#pragma unroll
        for (int ks = 0; ks < 4; ++ks) {
#pragma unroll
            for (int nb = 0; nb < 2; ++nb) {
                uint32_t bf[4];
                ldsm4t(bf, vb + SWZ((uint32_t)((ks * 16 + trow) * 128 +
                                               (wn * 32 + nb * 16 + tc8) * 2)));
                mma_f16(acc3[nb * 2],     a3[ks], bf[0], bf[1]);
                mma_f16(acc3[nb * 2 + 1], a3[ks], bf[2], bf[3]);
            }
        }

#pragma unroll
        for (int nb = 0; nb < 4; ++nb) {
            const int col = nt * 64 + wn * 32 + nb * 8 + tig * 2;
            const int r0 = wm * 16 + gid, r1 = r0 + 8;
            float2 ro0 = __half22float2(*(const __half2*)(TVRb + (size_t)r0 * NTVR + 1024 + col));
            float2 ro1 = __half22float2(*(const __half2*)(TVRb + (size_t)r1 * NTVR + 1024 + col));
            float2 o0 = {fmaxf(acc3[nb][0] + ro0.x, 0.f), fmaxf(acc3[nb][1] + ro0.y, 0.f)};
            float2 o1 = {fmaxf(acc3[nb][2] + ro1.x, 0.f), fmaxf(acc3[nb][3] + ro1.y, 0.f)};
            *(float2*)(Ob + (size_t)r0 * 512 + col) = o0;
            *(float2*)(Ob + (size_t)r1 * 512 + col) = o1;
        }
    }
}

// ---------------- launch ----------------
extern "C" void kernel_launch(void* const* d_in, const int* in_sizes, int n_in,
                              void* d_out, int out_size)
{
    const float* inp = (const float*)d_in[0];
    const float* Win = (const float*)d_in[1];
    const float* bin = (const float*)d_in[2];
    const float* Wq  = (const float*)d_in[3];
    const float* bq  = (const float*)d_in[4];
    const float* Wk  = (const float*)d_in[5];
    // d_in[6] = b_k : provably unused (row-constant, drops out of softmax)
    const float* Wv  = (const float*)d_in[7];
    const float* bv  = (const float*)d_in[8];
    const float* Wr  = (const float*)d_in[9];
    const float* br  = (const float*)d_in[10];
    const float* Wo  = (const float*)d_in[11];
    const float* bo  = (const float*)d_in[12];
    float* out = (float*)d_out;

    float *W3, *bias2;
    __half *Xf16, *If16, *WinT, *Wb, *TVR;
    cudaGetSymbolAddress((void**)&TVR,   g_TVR);
    cudaGetSymbolAddress((void**)&W3,    g_W3);
    cudaGetSymbolAddress((void**)&bias2, g_bias2);
    cudaGetSymbolAddress((void**)&Xf16,  g_Xf16);
    cudaGetSymbolAddress((void**)&If16,  g_If16);
    cudaGetSymbolAddress((void**)&WinT,  g_WinT);
    cudaGetSymbolAddress((void**)&Wb,    g_Wb);

    cudaFuncSetAttribute(gemm_f16<true >, cudaFuncAttributeMaxDynamicSharedMemorySize, MG_SMEM);
    cudaFuncSetAttribute(gemm_f16<false>, cudaFuncAttributeMaxDynamicSharedMemorySize, MG_SMEM);
    cudaFuncSetAttribute(attn_tc,         cudaFuncAttributeMaxDynamicSharedMemorySize, ATTN_SMEM);

    const dim3 bs(256);

    // 1: weight products + vectors (gv folded into bias2[0:512])
    wpre_k<<<dim3(8, 8, 4), bs>>>(Wq, Wk, Wv, Wr, Wo, bv, br, bo, bq, W3, bias2);
    // 2: input conversion + weight transposes
    prep2_k<<<PREP_CONV_BLOCKS + 1024, bs>>>(inp, If16, Win, W3, WinT, Wb);
    // 3: gemm1
    gemm_f16<true ><<<dim3(4, 256),  bs, MG_SMEM>>>(If16, WinT, bin, Xf16, 512);
    // 4: gemm2 (T block now carries +gv bias)
    gemm_f16<false><<<dim3(12, 256), bs, MG_SMEM>>>(Xf16, Wb, bias2, TVR, NTVR);
    // 5: attention
    attn_tc<<<NBATCH, bs, ATTN_SMEM>>>(Xf16, TVR, out);
}

// round 13
// speedup vs baseline: 2.9310x; 1.0280x over previous
#include <cuda_runtime.h>
#include <cuda_fp16.h>
#include <cstdint>
#include <cstddef>

#define D_DIM 512
#define AGENTS 64
#define NBATCH 512
#define MTOT (NBATCH * AGENTS)   // 32768
#define NTVR 1536

// ---------------- scratch (device globals: allocation-free) ----------------
__device__ __align__(128) __half  g_Xf16[MTOT * D_DIM];
__device__ __align__(128) __half  g_If16[MTOT * D_DIM];
__device__ __align__(128) __half  g_TVR [MTOT * NTVR];
__device__ __align__(128) float   g_W3  [3 * D_DIM * D_DIM];   // Wqk | Wvo | Wro
__device__ __align__(128) __half  g_WinT[D_DIM * D_DIM];
__device__ __align__(128) __half  g_Wb  [NTVR * D_DIM];
__device__ __align__(128) float   g_bias2[NTVR];

#define SWZ(o) ((o) ^ (((o) >> 3) & 0x70))

__device__ __forceinline__ uint32_t smem_u32(const void* p) {
    uint32_t a;
    asm("{ .reg .u64 t; cvta.to.shared.u64 t, %1; cvt.u32.u64 %0, t; }" : "=r"(a) : "l"(p));
    return a;
}
__device__ __forceinline__ void ldsm4(uint32_t* r, uint32_t addr) {
    asm volatile("ldmatrix.sync.aligned.m8n8.x4.shared.b16 {%0,%1,%2,%3}, [%4];"
                 : "=r"(r[0]), "=r"(r[1]), "=r"(r[2]), "=r"(r[3]) : "r"(addr));
}
__device__ __forceinline__ void ldsm4t(uint32_t* r, uint32_t addr) {
    asm volatile("ldmatrix.sync.aligned.m8n8.x4.trans.shared.b16 {%0,%1,%2,%3}, [%4];"
                 : "=r"(r[0]), "=r"(r[1]), "=r"(r[2]), "=r"(r[3]) : "r"(addr));
}
__device__ __forceinline__ void mma_f16(float* d, const uint32_t* a, uint32_t b0, uint32_t b1) {
    asm volatile(
        "mma.sync.aligned.m16n8k16.row.col.f32.f16.f16.f32 "
        "{%0,%1,%2,%3}, {%4,%5,%6,%7}, {%8,%9}, {%0,%1,%2,%3};"
        : "+f"(d[0]), "+f"(d[1]), "+f"(d[2]), "+f"(d[3])
        : "r"(a[0]), "r"(a[1]), "r"(a[2]), "r"(a[3]), "r"(b0), "r"(b1));
}
__device__ __forceinline__ void cpasync16(uint32_t dst, const void* src) {
    asm volatile("cp.async.cg.shared.global [%0], [%1], 16;" :: "r"(dst), "l"(src));
}
#define CP_COMMIT() asm volatile("cp.async.commit_group;" ::: "memory")
#define CP_WAIT(N)  asm volatile("cp.async.wait_group " #N ";" ::: "memory")

// ---------------- launch 1: weight products + vector precompute ----------------
__global__ __launch_bounds__(256)
void wpre_k(const float* __restrict__ Wq, const float* __restrict__ Wk,
            const float* __restrict__ Wv, const float* __restrict__ Wr,
            const float* __restrict__ Wo,
            const float* __restrict__ bv, const float* __restrict__ br,
            const float* __restrict__ bo, const float* __restrict__ bq,
            float* __restrict__ W3, float* __restrict__ bias2) {
    const int z = blockIdx.z;
    const int t = threadIdx.x;

    if (z == 3) {
        if (blockIdx.y != 0 || blockIdx.x >= 4) return;
        const int j = ((int)blockIdx.x & 1) * 256 + t;
        if (blockIdx.x < 2) {
            float s1 = 0.f, s2 = 0.f;
            for (int d = 0; d < D_DIM; ++d) {
                float w = Wo[d * D_DIM + j];
                s1 += bv[d] * w;
                s2 += br[d] * w;
            }
            bias2[512 + j]  = s1;
            bias2[1024 + j] = s2 + bo[j];
        } else {
            float s3 = 0.f;
            const float* wk = Wk + (size_t)j * D_DIM;
            for (int d = 0; d < D_DIM; ++d) s3 += wk[d] * bq[d];
            bias2[j] = s3;
        }
        return;
    }

    const float* A = (z == 0) ? Wq : ((z == 1) ? Wv : Wr);
    const float* B = (z == 0) ? Wk : Wo;
    float* C = W3 + (size_t)z * D_DIM * D_DIM;
    const bool transb = (z == 0);

    __shared__ __align__(16) float As[32][72];
    __shared__ __align__(16) float Bs[32][72];
    const int tx = t & 15, ty = t >> 4;
    const int m0 = blockIdx.y * 64, n0 = blockIdx.x * 64;

    float acc[4][4];
#pragma unroll
    for (int i = 0; i < 4; ++i)
#pragma unroll
        for (int j = 0; j < 4; ++j) acc[i][j] = 0.f;

    for (int kt = 0; kt < 16; ++kt) {
        __syncthreads();
#pragma unroll
        for (int i = 0; i < 2; ++i) {
            const int idx = t + i * 256;
            const int row = idx >> 3, c4 = (idx & 7) * 4;
            float4 v = *(const float4*)(A + (size_t)(m0 + row) * 512 + kt * 32 + c4);
            As[c4 + 0][row] = v.x; As[c4 + 1][row] = v.y;
            As[c4 + 2][row] = v.z; As[c4 + 3][row] = v.w;
        }
        if (transb) {
#pragma unroll
            for (int i = 0; i < 2; ++i) {
                const int idx = t + i * 256;
                const int row = idx >> 3, c4 = (idx & 7) * 4;
                float4 v = *(const float4*)(B + (size_t)(n0 + row) * 512 + kt * 32 + c4);
                Bs[c4 + 0][row] = v.x; Bs[c4 + 1][row] = v.y;
                Bs[c4 + 2][row] = v.z; Bs[c4 + 3][row] = v.w;
            }
        } else {
#pragma unroll
            for (int i = 0; i < 2; ++i) {
                const int idx = t + i * 256;
                const int kr = idx >> 4, c4 = (idx & 15) * 4;
                float4 v = *(const float4*)(B + (size_t)(kt * 32 + kr) * 512 + n0 + c4);
                *(float4*)&Bs[kr][c4] = v;
            }
        }
        __syncthreads();
#pragma unroll
        for (int k = 0; k < 32; ++k) {
            float4 av = *(const float4*)&As[k][ty * 4];
            float4 bv2 = *(const float4*)&Bs[k][tx * 4];
            float a[4] = {av.x, av.y, av.z, av.w};
            float b[4] = {bv2.x, bv2.y, bv2.z, bv2.w};
#pragma unroll
            for (int i = 0; i < 4; ++i)
#pragma unroll
                for (int j = 0; j < 4; ++j) acc[i][j] += a[i] * b[j];
        }
    }
#pragma unroll
    for (int i = 0; i < 4; ++i) {
        float4 o = {acc[i][0], acc[i][1], acc[i][2], acc[i][3]};
        *(float4*)(C + (size_t)(m0 + ty * 4 + i) * 512 + n0 + tx * 4) = o;
    }
}

// ---------------- launch 2: input fp32->fp16 conversion + weight transposes ----------------
#define PREP_CONV_BLOCKS 16384

__global__ __launch_bounds__(256)
void prep2_k(const float* __restrict__ inp, __half* __restrict__ If16,
             const float* __restrict__ Win, const float* __restrict__ W3,
             __half* __restrict__ WinT, __half* __restrict__ Wb) {
    __shared__ float tle[32][33];
    const int t = threadIdx.x;
    const int bid = blockIdx.x;

    if (bid < PREP_CONV_BLOCKS) {
        const int i = bid * 256 + t;
        float4 v = ((const float4*)inp)[i];
        __half h0 = __float2half_rn(v.x), h1 = __float2half_rn(v.y);
        __half h2 = __float2half_rn(v.z), h3 = __float2half_rn(v.w);
        uint32_t a = (uint32_t)__half_as_ushort(h0) | ((uint32_t)__half_as_ushort(h1) << 16);
        uint32_t b = (uint32_t)__half_as_ushort(h2) | ((uint32_t)__half_as_ushort(h3) << 16);
        ((uint2*)If16)[i] = make_uint2(a, b);
        return;
    }

    const int idx = bid - PREP_CONV_BLOCKS;
    const int z = idx >> 8;
    const int rem = idx & 255;
    const int bx = rem & 15, by = rem >> 4;
    const float* src = (z == 0) ? Win : (W3 + (size_t)(z - 1) * D_DIM * D_DIM);
    __half* dst      = (z == 0) ? WinT : (Wb + (size_t)(z - 1) * D_DIM * D_DIM);
    const int n0 = bx * 32, k0 = by * 32;
    const int tx = t & 31, tyg = t >> 5;
#pragma unroll
    for (int r = 0; r < 4; ++r) {
        const int ty = tyg * 4 + r;
        tle[ty][tx] = src[(size_t)(k0 + ty) * 512 + n0 + tx];
    }
    __syncthreads();
#pragma unroll
    for (int r = 0; r < 4; ++r) {
        const int ty = tyg * 4 + r;
        dst[(size_t)(n0 + ty) * 512 + k0 + tx] = __float2half_rn(tle[tx][ty]);
    }
}

// ---------------- fp16 GEMM: Cf16[M,Ntot] = A[M,512] @ B^T[Ntot,512] + bias ----------------
#define MG_SMEM 98304   // 3 stages x (16KB A + 16KB B)

template<bool RELU>
__global__ __launch_bounds__(256)
void gemm_f16(const __half* __restrict__ A, const __half* __restrict__ B,
              const float* __restrict__ bias, __half* __restrict__ Cf16, int Ntot)
{
    extern __shared__ char sm[];
    const uint32_t smS = smem_u32(sm);

    const int t = threadIdx.x;
    const int wid = t >> 5, l = t & 31;
    const int wm = wid >> 1, wn = wid & 1;
    const int m0 = blockIdx.y * 128, n0 = blockIdx.x * 128;

    const int arow = l & 15, acol = l >> 4;
    const int brow = (l & 7) + ((l >> 4) & 1) * 8, bcol = (l >> 3) & 1;
    const int lrow = t >> 3, lcg = t & 7;

    float acc[2][8][4];
#pragma unroll
    for (int mi = 0; mi < 2; ++mi)
#pragma unroll
        for (int ni = 0; ni < 8; ++ni)
#pragma unroll
            for (int q = 0; q < 4; ++q) acc[mi][ni][q] = 0.f;

    auto load_chunk = [&](int c, int s) {
        const int kk = c * 64;
        const uint32_t ab = smS + s * 32768;
        const uint32_t bb = ab + 16384;
#pragma unroll
        for (int i = 0; i < 4; ++i) {
            const int row = lrow + i * 32;
            const uint32_t off = SWZ((uint32_t)(row * 128 + lcg * 16));
            cpasync16(ab + off, A + (size_t)(m0 + row) * 512 + kk + lcg * 8);
            cpasync16(bb + off, B + (size_t)(n0 + row) * 512 + kk + lcg * 8);
        }
        CP_COMMIT();
    };

    auto compute = [&](int s) {
        const uint32_t ab = smS + s * 32768;
        const uint32_t bb = ab + 16384;
#pragma unroll
        for (int ks = 0; ks < 4; ++ks) {
            uint32_t a[2][4];
#pragma unroll
            for (int mi = 0; mi < 2; ++mi) {
                const int row = wm * 32 + mi * 16 + arow;
                ldsm4(a[mi], ab + SWZ((uint32_t)(row * 128 + (ks * 2 + acol) * 16)));
            }
#pragma unroll
            for (int nb = 0; nb < 4; ++nb) {
                const int row = wn * 64 + nb * 16 + brow;
                uint32_t b[4];
                ldsm4(b, bb + SWZ((uint32_t)(row * 128 + (ks * 2 + bcol) * 16)));
                mma_f16(acc[0][nb * 2],     a[0], b[0], b[1]);
                mma_f16(acc[1][nb * 2],     a[1], b[0], b[1]);
                mma_f16(acc[0][nb * 2 + 1], a[0], b[2], b[3]);
                mma_f16(acc[1][nb * 2 + 1], a[1], b[2], b[3]);
            }
        }
    };

    load_chunk(0, 0);
    load_chunk(1, 1);

    for (int c = 0; c < 8; ++c) {
        if (c < 6) { CP_WAIT(1); } else { CP_WAIT(0); }
        __syncthreads();
        if (c + 2 < 8) load_chunk(c + 2, (c + 2) % 3);
        compute(c % 3);
    }

    const int gid = l >> 2, tig = l & 3;
    __syncthreads();
#pragma unroll
    for (int mi = 0; mi < 2; ++mi) {
#pragma unroll
        for (int ni = 0; ni < 8; ++ni) {
            const int row = wm * 32 + mi * 16 + gid;
            const int col = wn * 64 + ni * 8 + tig * 2;
            float2 bb = *(const float2*)(bias + n0 + col);
            float v0 = acc[mi][ni][0] + bb.x;
            float v1 = acc[mi][ni][1] + bb.y;
            float v2 = acc[mi][ni][2] + bb.x;
            float v3 = acc[mi][ni][3] + bb.y;
            if (RELU) {
                v0 = fmaxf(v0, 0.f); v1 = fmaxf(v1, 0.f);
                v2 = fmaxf(v2, 0.f); v3 = fmaxf(v3, 0.f);
            }
            __half2 u0 = __floats2half2_rn(v0, v1);
            __half2 u1 = __floats2half2_rn(v2, v3);
            *(__half2*)(sm + row * 272 + col * 2)       = u0;
            *(__half2*)(sm + (row + 8) * 272 + col * 2) = u1;
        }
    }
    __syncthreads();
#pragma unroll
    for (int i = 0; i < 8; ++i) {
        const int idx = t + i * 256;
        const int row = idx >> 4, seg = idx & 15;
        uint4 v = *(const uint4*)(sm + row * 272 + seg * 16);
        *(uint4*)(Cf16 + (size_t)(m0 + row) * Ntot + n0 + seg * 8) = v;
    }
}

// ---------------- tensor-core attention: 2 CTAs per batch (32 query rows each) ----------------
#define AT_STAGE  12288                 // phase1: T 4KB + X 8KB ; phase3: VO 8KB
#define AT_SC     (3 * AT_STAGE)        // fp32 [32][68] = 8704
#define AT_ATT    (AT_SC + 8704)        // fp16 attn 32x128B = 4096
#define ATTN_SMEM (AT_ATT + 4096)       // 49664

__global__ __launch_bounds__(256)
void attn_tc(const __half* __restrict__ Xf16, const __half* __restrict__ TVR,
             float* __restrict__ OUT)
{
    extern __shared__ char sm[];
    const uint32_t smS = smem_u32(sm);
    float* sc = (float*)(sm + AT_SC);

    const int b     = blockIdx.x >> 1;
    const int mrow0 = (blockIdx.x & 1) * 32;

    const __half* Xb   = Xf16 + (size_t)b * 64 * 512;
    const __half* TVRb = TVR  + (size_t)b * 64 * NTVR;
    float*        Ob   = OUT  + (size_t)b * 64 * 512;

    const int t = threadIdx.x;
    const int wid = t >> 5, l = t & 31;
    const int wm = wid & 1, wn = wid >> 1;      // 2 x 4 warp grid, tile 16x16
    const int arow = l & 15, acol = l >> 4;
    const int brow = (l & 7) + ((l >> 4) & 1) * 8, bcol = (l >> 3) & 1;
    const int gid = l >> 2, tig = l & 3;

    // ---- phase 1: scores[32][64] over K=512, 8 chunks, 3-stage ----
    auto load1 = [&](int kt, int s) {
        const uint32_t base = smS + s * AT_STAGE;
        {
            const int row = t >> 3, cg = t & 7;   // T: 32 rows
            cpasync16(base + SWZ((uint32_t)(row * 128 + cg * 16)),
                      TVRb + (size_t)(mrow0 + row) * NTVR + kt * 64 + cg * 8);
        }
#pragma unroll
        for (int i = 0; i < 2; ++i) {             // X: 64 rows
            const int idx = t + i * 256;
            const int row = idx >> 3, cg = idx & 7;
            cpasync16(base + 4096 + SWZ((uint32_t)(row * 128 + cg * 16)),
                      Xb + (size_t)row * 512 + kt * 64 + cg * 8);
        }
        CP_COMMIT();
    };

    float acc1[2][4];
#pragma unroll
    for (int i = 0; i < 2; ++i)
#pragma unroll
        for (int j = 0; j < 4; ++j) acc1[i][j] = 0.f;

    auto compute1 = [&](int s) {
        const uint32_t tb = smS + s * AT_STAGE;
        const uint32_t xb = tb + 4096;
#pragma unroll
        for (int ks = 0; ks < 4; ++ks) {
            uint32_t a[4];
            ldsm4(a, tb + SWZ((uint32_t)((wm * 16 + arow) * 128 + (ks * 2 + acol) * 16)));
            uint32_t bf[4];
            ldsm4(bf, xb + SWZ((uint32_t)((wn * 16 + brow) * 128 + (ks * 2 + bcol) * 16)));
            mma_f16(acc1[0], a, bf[0], bf[1]);
            mma_f16(acc1[1], a, bf[2], bf[3]);
        }
    };

    load1(0, 0);
    load1(1, 1);
    for (int c = 0; c < 8; ++c) {
        if (c < 6) { CP_WAIT(1); } else { CP_WAIT(0); }
        __syncthreads();
        if (c + 2 < 8) load1(c + 2, (c + 2) % 3);
        compute1(c % 3);
    }

    // ---- prefetch VO tiles 0,1 (hidden behind score write + softmax) ----
    auto loadVO = [&](int nt, int s) {
#pragma unroll
        for (int i = 0; i < 2; ++i) {
            const int idx = t + i * 256;
            const int row = idx >> 3, cg = idx & 7;
            cpasync16(smS + s * AT_STAGE + SWZ((uint32_t)(row * 128 + cg * 16)),
                      TVRb + (size_t)row * NTVR + 512 + nt * 64 + cg * 8);
        }
        CP_COMMIT();
    };
    __syncthreads();
    loadVO(0, 0);
    loadVO(1, 1);

    // ---- scores -> sc ----
#pragma unroll
    for (int nb = 0; nb < 2; ++nb) {
        const int col = wn * 16 + nb * 8 + tig * 2;
        const int r0 = wm * 16 + gid;
        sc[r0 * 68 + col]           = acc1[nb][0];
        sc[r0 * 68 + col + 1]       = acc1[nb][1];
        sc[(r0 + 8) * 68 + col]     = acc1[nb][2];
        sc[(r0 + 8) * 68 + col + 1] = acc1[nb][3];
    }
    __syncthreads();

    // ---- softmax: 8 threads per row, writes fp16 attn tile ----
    {
        const int row = t >> 3, lane8 = t & 7;
        const float* scr = sc + row * 68 + lane8 * 8;
        float m = -1e30f;
#pragma unroll
        for (int j = 0; j < 8; ++j) m = fmaxf(m, scr[j]);
        m = fmaxf(m, __shfl_xor_sync(0xFFFFFFFFu, m, 1));
        m = fmaxf(m, __shfl_xor_sync(0xFFFFFFFFu, m, 2));
        m = fmaxf(m, __shfl_xor_sync(0xFFFFFFFFu, m, 4));
        float e[8];
        float s = 0.f;
#pragma unroll
        for (int j = 0; j < 8; ++j) { e[j] = __expf(scr[j] - m); s += e[j]; }
        s += __shfl_xor_sync(0xFFFFFFFFu, s, 1);
        s += __shfl_xor_sync(0xFFFFFFFFu, s, 2);
        s += __shfl_xor_sync(0xFFFFFFFFu, s, 4);
        const float inv = 1.f / s;
#pragma unroll
        for (int j = 0; j < 4; ++j) {
            const int col = lane8 * 8 + j * 2;
            __half2 h = __floats2half2_rn(e[2 * j] * inv, e[2 * j + 1] * inv);
            *(__half2*)(sm + AT_ATT + SWZ((uint32_t)(row * 128 + col * 2))) = h;
        }
    }
    __syncthreads();

    // ---- attn A-frags (32x64 tile, K=64 -> 4 k16 steps) ----
    uint32_t a3[4][4];
    const uint32_t attb = smS + AT_ATT;
#pragma unroll
    for (int ks = 0; ks < 4; ++ks)
        ldsm4(a3[ks], attb + SWZ((uint32_t)((wm * 16 + arow) * 128 + (ks * 2 + acol) * 16)));

    // ---- phase 3: OUT[32][512] = relu(attn @ VO + RO), 3-stage over 8 n-tiles ----
    const int trow = (l & 7) + ((l >> 3) & 1) * 8;
    const int tc8  = ((l >> 4) & 1) * 8;

    for (int nt = 0; nt < 8; ++nt) {
        if (nt < 6) { CP_WAIT(1); } else { CP_WAIT(0); }
        __syncthreads();
        if (nt + 2 < 8) loadVO(nt + 2, (nt + 2) % 3);

        const uint32_t vb = smS + (nt % 3) * AT_STAGE;
        float acc3[2][4];
#pragma unroll
        for (int i = 0; i < 2; ++i)
#pragma unroll
            for (int j = 0; j < 4; ++j) acc3[i][j] = 0.f;

#pragma unroll
        for (int ks = 0; ks < 4; ++ks) {
            uint32_t bf[4];
            ldsm4t(bf, vb + SWZ((uint32_t)((ks * 16 + trow) * 128 + (wn * 16 + tc8) * 2)));
            mma_f16(acc3[0], a3[ks], bf[0], bf[1]);
            mma_f16(acc3[1], a3[ks], bf[2], bf[3]);
        }

#pragma unroll
        for (int nb = 0; nb < 2; ++nb) {
            const int col = nt * 64 + wn * 16 + nb * 8 + tig * 2;
            const int r0 = mrow0 + wm * 16 + gid, r1 = r0 + 8;
            float2 ro0 = __half22float2(*(const __half2*)(TVRb + (size_t)r0 * NTVR + 1024 + col));
            float2 ro1 = __half22float2(*(const __half2*)(TVRb + (size_t)r1 * NTVR + 1024 + col));
            float2 o0 = {fmaxf(acc3[nb][0] + ro0.x, 0.f), fmaxf(acc3[nb][1] + ro0.y, 0.f)};
            float2 o1 = {fmaxf(acc3[nb][2] + ro1.x, 0.f), fmaxf(acc3[nb][3] + ro1.y, 0.f)};
            *(float2*)(Ob + (size_t)r0 * 512 + col) = o0;
            *(float2*)(Ob + (size_t)r1 * 512 + col) = o1;
        }
    }
}

// ---------------- launch ----------------
extern "C" void kernel_launch(void* const* d_in, const int* in_sizes, int n_in,
                              void* d_out, int out_size)
{
    const float* inp = (const float*)d_in[0];
    const float* Win = (const float*)d_in[1];
    const float* bin = (const float*)d_in[2];
    const float* Wq  = (const float*)d_in[3];
    const float* bq  = (const float*)d_in[4];
    const float* Wk  = (const float*)d_in[5];
    // d_in[6] = b_k : provably unused (row-constant, drops out of softmax)
    const float* Wv  = (const float*)d_in[7];
    const float* bv  = (const float*)d_in[8];
    const float* Wr  = (const float*)d_in[9];
    const float* br  = (const float*)d_in[10];
    const float* Wo  = (const float*)d_in[11];
    const float* bo  = (const float*)d_in[12];
    float* out = (float*)d_out;

    float *W3, *bias2;
    __half *Xf16, *If16, *WinT, *Wb, *TVR;
    cudaGetSymbolAddress((void**)&TVR,   g_TVR);
    cudaGetSymbolAddress((void**)&W3,    g_W3);
    cudaGetSymbolAddress((void**)&bias2, g_bias2);
    cudaGetSymbolAddress((void**)&Xf16,  g_Xf16);
    cudaGetSymbolAddress((void**)&If16,  g_If16);
    cudaGetSymbolAddress((void**)&WinT,  g_WinT);
    cudaGetSymbolAddress((void**)&Wb,    g_Wb);

    cudaFuncSetAttribute(gemm_f16<true >, cudaFuncAttributeMaxDynamicSharedMemorySize, MG_SMEM);
    cudaFuncSetAttribute(gemm_f16<false>, cudaFuncAttributeMaxDynamicSharedMemorySize, MG_SMEM);
    cudaFuncSetAttribute(attn_tc,         cudaFuncAttributeMaxDynamicSharedMemorySize, ATTN_SMEM);

    const dim3 bs(256);

    // 1: weight products + vectors (gv folded into bias2[0:512])
    wpre_k<<<dim3(8, 8, 4), bs>>>(Wq, Wk, Wv, Wr, Wo, bv, br, bo, bq, W3, bias2);
    // 2: input conversion + weight transposes
    prep2_k<<<PREP_CONV_BLOCKS + 1024, bs>>>(inp, If16, Win, W3, WinT, Wb);
    // 3: gemm1
    gemm_f16<true ><<<dim3(4, 256),  bs, MG_SMEM>>>(If16, WinT, bin, Xf16, 512);
    // 4: gemm2 (T block carries +gv bias)
    gemm_f16<false><<<dim3(12, 256), bs, MG_SMEM>>>(Xf16, Wb, bias2, TVR, NTVR);
    // 5: attention (2 CTAs per batch)
    attn_tc<<<NBATCH * 2, bs, ATTN_SMEM>>>(Xf16, TVR, out);
}

// round 15
// speedup vs baseline: 2.9782x; 1.0161x over previous
#include <cuda_runtime.h>
#include <cuda_fp16.h>
#include <cstdint>
#include <cstddef>

#define D_DIM 512
#define AGENTS 64
#define NBATCH 512
#define MTOT (NBATCH * AGENTS)   // 32768
#define NTVR 1536

// ---------------- scratch (device globals: allocation-free) ----------------
__device__ __align__(128) __half  g_Xf16[MTOT * D_DIM];
__device__ __align__(128) __half  g_If16[MTOT * D_DIM];
__device__ __align__(128) __half  g_TVR [MTOT * NTVR];
__device__ __align__(128) float   g_W3  [3 * D_DIM * D_DIM];   // Wqk | Wvo | Wro
__device__ __align__(128) __half  g_WinT[D_DIM * D_DIM];
__device__ __align__(128) __half  g_Wb  [NTVR * D_DIM];
__device__ __align__(128) float   g_bias2[NTVR];

#define SWZ(o) ((o) ^ (((o) >> 3) & 0x70))

__device__ __forceinline__ uint32_t smem_u32(const void* p) {
    uint32_t a;
    asm("{ .reg .u64 t; cvta.to.shared.u64 t, %1; cvt.u32.u64 %0, t; }" : "=r"(a) : "l"(p));
    return a;
}
__device__ __forceinline__ void ldsm4(uint32_t* r, uint32_t addr) {
    asm volatile("ldmatrix.sync.aligned.m8n8.x4.shared.b16 {%0,%1,%2,%3}, [%4];"
                 : "=r"(r[0]), "=r"(r[1]), "=r"(r[2]), "=r"(r[3]) : "r"(addr));
}
__device__ __forceinline__ void ldsm4t(uint32_t* r, uint32_t addr) {
    asm volatile("ldmatrix.sync.aligned.m8n8.x4.trans.shared.b16 {%0,%1,%2,%3}, [%4];"
                 : "=r"(r[0]), "=r"(r[1]), "=r"(r[2]), "=r"(r[3]) : "r"(addr));
}
__device__ __forceinline__ void mma_f16(float* d, const uint32_t* a, uint32_t b0, uint32_t b1) {
    asm volatile(
        "mma.sync.aligned.m16n8k16.row.col.f32.f16.f16.f32 "
        "{%0,%1,%2,%3}, {%4,%5,%6,%7}, {%8,%9}, {%0,%1,%2,%3};"
        : "+f"(d[0]), "+f"(d[1]), "+f"(d[2]), "+f"(d[3])
        : "r"(a[0]), "r"(a[1]), "r"(a[2]), "r"(a[3]), "r"(b0), "r"(b1));
}
__device__ __forceinline__ void cpasync16(uint32_t dst, const void* src) {
    asm volatile("cp.async.cg.shared.global [%0], [%1], 16;" :: "r"(dst), "l"(src));
}
#define CP_COMMIT() asm volatile("cp.async.commit_group;" ::: "memory")
#define CP_WAIT(N)  asm volatile("cp.async.wait_group " #N ";" ::: "memory")

// ---------------- launch 1: weight products + vector precompute ----------------
__global__ __launch_bounds__(256)
void wpre_k(const float* __restrict__ Wq, const float* __restrict__ Wk,
            const float* __restrict__ Wv, const float* __restrict__ Wr,
            const float* __restrict__ Wo,
            const float* __restrict__ bv, const float* __restrict__ br,
            const float* __restrict__ bo, const float* __restrict__ bq,
            float* __restrict__ W3, float* __restrict__ bias2) {
    const int z = blockIdx.z;
    const int t = threadIdx.x;

    if (z == 3) {
        if (blockIdx.y != 0 || blockIdx.x >= 4) return;
        const int j = ((int)blockIdx.x & 1) * 256 + t;
        if (blockIdx.x < 2) {
            float s1 = 0.f, s2 = 0.f;
            for (int d = 0; d < D_DIM; ++d) {
                float w = Wo[d * D_DIM + j];
                s1 += bv[d] * w;
                s2 += br[d] * w;
            }
            bias2[512 + j]  = s1;
            bias2[1024 + j] = s2 + bo[j];
        } else {
            float s3 = 0.f;
            const float* wk = Wk + (size_t)j * D_DIM;
            for (int d = 0; d < D_DIM; ++d) s3 += wk[d] * bq[d];
            bias2[j] = s3;
        }
        return;
    }

    const float* A = (z == 0) ? Wq : ((z == 1) ? Wv : Wr);
    const float* B = (z == 0) ? Wk : Wo;
    float* C = W3 + (size_t)z * D_DIM * D_DIM;
    const bool transb = (z == 0);

    __shared__ __align__(16) float As[32][72];
    __shared__ __align__(16) float Bs[32][72];
    const int tx = t & 15, ty = t >> 4;
    const int m0 = blockIdx.y * 64, n0 = blockIdx.x * 64;

    float acc[4][4];
#pragma unroll
    for (int i = 0; i < 4; ++i)
#pragma unroll
        for (int j = 0; j < 4; ++j) acc[i][j] = 0.f;

    for (int kt = 0; kt < 16; ++kt) {
        __syncthreads();
#pragma unroll
        for (int i = 0; i < 2; ++i) {
            const int idx = t + i * 256;
            const int row = idx >> 3, c4 = (idx & 7) * 4;
            float4 v = *(const float4*)(A + (size_t)(m0 + row) * 512 + kt * 32 + c4);
            As[c4 + 0][row] = v.x; As[c4 + 1][row] = v.y;
            As[c4 + 2][row] = v.z; As[c4 + 3][row] = v.w;
        }
        if (transb) {
#pragma unroll
            for (int i = 0; i < 2; ++i) {
                const int idx = t + i * 256;
                const int row = idx >> 3, c4 = (idx & 7) * 4;
                float4 v = *(const float4*)(B + (size_t)(n0 + row) * 512 + kt * 32 + c4);
                Bs[c4 + 0][row] = v.x; Bs[c4 + 1][row] = v.y;
                Bs[c4 + 2][row] = v.z; Bs[c4 + 3][row] = v.w;
            }
        } else {
#pragma unroll
            for (int i = 0; i < 2; ++i) {
                const int idx = t + i * 256;
                const int kr = idx >> 4, c4 = (idx & 15) * 4;
                float4 v = *(const float4*)(B + (size_t)(kt * 32 + kr) * 512 + n0 + c4);
                *(float4*)&Bs[kr][c4] = v;
            }
        }
        __syncthreads();
#pragma unroll
        for (int k = 0; k < 32; ++k) {
            float4 av = *(const float4*)&As[k][ty * 4];
            float4 bv2 = *(const float4*)&Bs[k][tx * 4];
            float a[4] = {av.x, av.y, av.z, av.w};
            float b[4] = {bv2.x, bv2.y, bv2.z, bv2.w};
#pragma unroll
            for (int i = 0; i < 4; ++i)
#pragma unroll
                for (int j = 0; j < 4; ++j) acc[i][j] += a[i] * b[j];
        }
    }
#pragma unroll
    for (int i = 0; i < 4; ++i) {
        float4 o = {acc[i][0], acc[i][1], acc[i][2], acc[i][3]};
        *(float4*)(C + (size_t)(m0 + ty * 4 + i) * 512 + n0 + tx * 4) = o;
    }
}

// ---------------- launch 2: input fp32->fp16 conversion + weight transposes ----------------
#define PREP_CONV_BLOCKS 16384

__global__ __launch_bounds__(256)
void prep2_k(const float* __restrict__ inp, __half* __restrict__ If16,
             const float* __restrict__ Win, const float* __restrict__ W3,
             __half* __restrict__ WinT, __half* __restrict__ Wb) {
    __shared__ float tle[32][33];
    const int t = threadIdx.x;
    const int bid = blockIdx.x;

    if (bid < PREP_CONV_BLOCKS) {
        const int i = bid * 256 + t;
        float4 v = ((const float4*)inp)[i];
        __half h0 = __float2half_rn(v.x), h1 = __float2half_rn(v.y);
        __half h2 = __float2half_rn(v.z), h3 = __float2half_rn(v.w);
        uint32_t a = (uint32_t)__half_as_ushort(h0) | ((uint32_t)__half_as_ushort(h1) << 16);
        uint32_t b = (uint32_t)__half_as_ushort(h2) | ((uint32_t)__half_as_ushort(h3) << 16);
        ((uint2*)If16)[i] = make_uint2(a, b);
        return;
    }

    const int idx = bid - PREP_CONV_BLOCKS;
    const int z = idx >> 8;
    const int rem = idx & 255;
    const int bx = rem & 15, by = rem >> 4;
    const float* src = (z == 0) ? Win : (W3 + (size_t)(z - 1) * D_DIM * D_DIM);
    __half* dst      = (z == 0) ? WinT : (Wb + (size_t)(z - 1) * D_DIM * D_DIM);
    const int n0 = bx * 32, k0 = by * 32;
    const int tx = t & 31, tyg = t >> 5;
#pragma unroll
    for (int r = 0; r < 4; ++r) {
        const int ty = tyg * 4 + r;
        tle[ty][tx] = src[(size_t)(k0 + ty) * 512 + n0 + tx];
    }
    __syncthreads();
#pragma unroll
    for (int r = 0; r < 4; ++r) {
        const int ty = tyg * 4 + r;
        dst[(size_t)(n0 + ty) * 512 + k0 + tx] = __float2half_rn(tle[tx][ty]);
    }
}

// ---------------- fp16 GEMM: Cf16[M,Ntot] = A[M,512] @ B^T[Ntot,512] + bias ----------------
// CTA 128x128, 4 warps (2x2), warp tile 64x64 (mma:ldsm ratio 4:1),
// BK=64, 8 chunks, 3-stage cp.async pipeline, smem-staged epilogue. 2 CTAs/SM.
#define MG_SMEM 98304   // 3 stages x (16KB A + 16KB B)

template<bool RELU>
__global__ __launch_bounds__(128)
void gemm_f16(const __half* __restrict__ A, const __half* __restrict__ B,
              const float* __restrict__ bias, __half* __restrict__ Cf16, int Ntot)
{
    extern __shared__ char sm[];
    const uint32_t smS = smem_u32(sm);

    const int t = threadIdx.x;
    const int wid = t >> 5, l = t & 31;
    const int wm = wid >> 1, wn = wid & 1;     // 2x2 warp grid, warp tile 64x64
    const int m0 = blockIdx.y * 128, n0 = blockIdx.x * 128;

    const int arow = l & 15, acol = l >> 4;
    const int brow = (l & 7) + ((l >> 4) & 1) * 8, bcol = (l >> 3) & 1;
    const int lrow = t >> 3, lcg = t & 7;      // lrow 0..15

    float acc[4][8][4];
#pragma unroll
    for (int mi = 0; mi < 4; ++mi)
#pragma unroll
        for (int ni = 0; ni < 8; ++ni)
#pragma unroll
            for (int q = 0; q < 4; ++q) acc[mi][ni][q] = 0.f;

    auto load_chunk = [&](int c, int s) {
        const int kk = c * 64;
        const uint32_t ab = smS + s * 32768;
        const uint32_t bb = ab + 16384;
#pragma unroll
        for (int i = 0; i < 8; ++i) {
            const int row = lrow + i * 16;
            const uint32_t off = SWZ((uint32_t)(row * 128 + lcg * 16));
            cpasync16(ab + off, A + (size_t)(m0 + row) * 512 + kk + lcg * 8);
            cpasync16(bb + off, B + (size_t)(n0 + row) * 512 + kk + lcg * 8);
        }
        CP_COMMIT();
    };

    auto compute = [&](int s) {
        const uint32_t ab = smS + s * 32768;
        const uint32_t bb = ab + 16384;
#pragma unroll
        for (int ks = 0; ks < 4; ++ks) {
            uint32_t a[4][4];
#pragma unroll
            for (int mi = 0; mi < 4; ++mi) {
                const int row = wm * 64 + mi * 16 + arow;
                ldsm4(a[mi], ab + SWZ((uint32_t)(row * 128 + (ks * 2 + acol) * 16)));
            }
#pragma unroll
            for (int nb = 0; nb < 4; ++nb) {
                const int row = wn * 64 + nb * 16 + brow;
                uint32_t b[4];
                ldsm4(b, bb + SWZ((uint32_t)(row * 128 + (ks * 2 + bcol) * 16)));
#pragma unroll
                for (int mi = 0; mi < 4; ++mi) {
                    mma_f16(acc[mi][nb * 2],     a[mi], b[0], b[1]);
                    mma_f16(acc[mi][nb * 2 + 1], a[mi], b[2], b[3]);
                }
            }
        }
    };

    load_chunk(0, 0);
    load_chunk(1, 1);

    for (int c = 0; c < 8; ++c) {
        if (c < 6) { CP_WAIT(1); } else { CP_WAIT(0); }
        __syncthreads();
        if (c + 2 < 8) load_chunk(c + 2, (c + 2) % 3);
        compute(c % 3);
    }

    // epilogue: frags -> padded smem tile -> coalesced 16B stores
    const int gid = l >> 2, tig = l & 3;
    __syncthreads();
#pragma unroll
    for (int mi = 0; mi < 4; ++mi) {
#pragma unroll
        for (int ni = 0; ni < 8; ++ni) {
            const int row = wm * 64 + mi * 16 + gid;
            const int col = wn * 64 + ni * 8 + tig * 2;
            float2 bb = *(const float2*)(bias + n0 + col);
            float v0 = acc[mi][ni][0] + bb.x;
            float v1 = acc[mi][ni][1] + bb.y;
            float v2 = acc[mi][ni][2] + bb.x;
            float v3 = acc[mi][ni][3] + bb.y;
            if (RELU) {
                v0 = fmaxf(v0, 0.f); v1 = fmaxf(v1, 0.f);
                v2 = fmaxf(v2, 0.f); v3 = fmaxf(v3, 0.f);
            }
            __half2 u0 = __floats2half2_rn(v0, v1);
            __half2 u1 = __floats2half2_rn(v2, v3);
            *(__half2*)(sm + row * 272 + col * 2)       = u0;
            *(__half2*)(sm + (row + 8) * 272 + col * 2) = u1;
        }
    }
    __syncthreads();
#pragma unroll
    for (int i = 0; i < 16; ++i) {
        const int idx = t + i * 128;
        const int row = idx >> 4, seg = idx & 15;
        uint4 v = *(const uint4*)(sm + row * 272 + seg * 16);
        *(uint4*)(Cf16 + (size_t)(m0 + row) * Ntot + n0 + seg * 8) = v;
    }
}

// ---------------- tensor-core attention: 2 CTAs per batch (32 query rows each) ----------------
#define AT_STAGE  12288                 // phase1: T 4KB + X 8KB ; phase3: VO 8KB
#define AT_SC     (3 * AT_STAGE)        // fp32 [32][68] = 8704
#define AT_ATT    (AT_SC + 8704)        // fp16 attn 32x128B = 4096
#define ATTN_SMEM (AT_ATT + 4096)       // 49664

__global__ __launch_bounds__(256)
void attn_tc(const __half* __restrict__ Xf16, const __half* __restrict__ TVR,
             float* __restrict__ OUT)
{
    extern __shared__ char sm[];
    const uint32_t smS = smem_u32(sm);
    float* sc = (float*)(sm + AT_SC);

    const int b     = blockIdx.x >> 1;
    const int mrow0 = (blockIdx.x & 1) * 32;

    const __half* Xb   = Xf16 + (size_t)b * 64 * 512;
    const __half* TVRb = TVR  + (size_t)b * 64 * NTVR;
    float*        Ob   = OUT  + (size_t)b * 64 * 512;

    const int t = threadIdx.x;
    const int wid = t >> 5, l = t & 31;
    const int wm = wid & 1, wn = wid >> 1;      // 2 x 4 warp grid, tile 16x16
    const int arow = l & 15, acol = l >> 4;
    const int brow = (l & 7) + ((l >> 4) & 1) * 8, bcol = (l >> 3) & 1;
    const int gid = l >> 2, tig = l & 3;

    auto load1 = [&](int kt, int s) {
        const uint32_t base = smS + s * AT_STAGE;
        {
            const int row = t >> 3, cg = t & 7;
            cpasync16(base + SWZ((uint32_t)(row * 128 + cg * 16)),
                      TVRb + (size_t)(mrow0 + row) * NTVR + kt * 64 + cg * 8);
        }
#pragma unroll
        for (int i = 0; i < 2; ++i) {
            const int idx = t + i * 256;
            const int row = idx >> 3, cg = idx & 7;
            cpasync16(base + 4096 + SWZ((uint32_t)(row * 128 + cg * 16)),
                      Xb + (size_t)row * 512 + kt * 64 + cg * 8);
        }
        CP_COMMIT();
    };

    float acc1[2][4];
#pragma unroll
    for (int i = 0; i < 2; ++i)
#pragma unroll
        for (int j = 0; j < 4; ++j) acc1[i][j] = 0.f;

    auto compute1 = [&](int s) {
        const uint32_t tb = smS + s * AT_STAGE;
        const uint32_t xb = tb + 4096;
#pragma unroll
        for (int ks = 0; ks < 4; ++ks) {
            uint32_t a[4];
            ldsm4(a, tb + SWZ((uint32_t)((wm * 16 + arow) * 128 + (ks * 2 + acol) * 16)));
            uint32_t bf[4];
            ldsm4(bf, xb + SWZ((uint32_t)((wn * 16 + brow) * 128 + (ks * 2 + bcol) * 16)));
            mma_f16(acc1[0], a, bf[0], bf[1]);
            mma_f16(acc1[1], a, bf[2], bf[3]);
        }
    };

    load1(0, 0);
    load1(1, 1);
    for (int c = 0; c < 8; ++c) {
        if (c < 6) { CP_WAIT(1); } else { CP_WAIT(0); }
        __syncthreads();
        if (c + 2 < 8) load1(c + 2, (c + 2) % 3);
        compute1(c % 3);
    }

    auto loadVO = [&](int nt, int s) {
#pragma unroll
        for (int i = 0; i < 2; ++i) {
            const int idx = t + i * 256;
            const int row = idx >> 3, cg = idx & 7;
            cpasync16(smS + s * AT_STAGE + SWZ((uint32_t)(row * 128 + cg * 16)),
                      TVRb + (size_t)row * NTVR + 512 + nt * 64 + cg * 8);
        }
        CP_COMMIT();
    };
    __syncthreads();
    loadVO(0, 0);
    loadVO(1, 1);

#pragma unroll
    for (int nb = 0; nb < 2; ++nb) {
        const int col = wn * 16 + nb * 8 + tig * 2;
        const int r0 = wm * 16 + gid;
        sc[r0 * 68 + col]           = acc1[nb][0];
        sc[r0 * 68 + col + 1]       = acc1[nb][1];
        sc[(r0 + 8) * 68 + col]     = acc1[nb][2];
        sc[(r0 + 8) * 68 + col + 1] = acc1[nb][3];
    }
    __syncthreads();

    {
        const int row = t >> 3, lane8 = t & 7;
        const float* scr = sc + row * 68 + lane8 * 8;
        float m = -1e30f;
#pragma unroll
        for (int j = 0; j < 8; ++j) m = fmaxf(m, scr[j]);
        m = fmaxf(m, __shfl_xor_sync(0xFFFFFFFFu, m, 1));
        m = fmaxf(m, __shfl_xor_sync(0xFFFFFFFFu, m, 2));
        m = fmaxf(m, __shfl_xor_sync(0xFFFFFFFFu, m, 4));
        float e[8];
        float s = 0.f;
#pragma unroll
        for (int j = 0; j < 8; ++j) { e[j] = __expf(scr[j] - m); s += e[j]; }
        s += __shfl_xor_sync(0xFFFFFFFFu, s, 1);
        s += __shfl_xor_sync(0xFFFFFFFFu, s, 2);
        s += __shfl_xor_sync(0xFFFFFFFFu, s, 4);
        const float inv = 1.f / s;
#pragma unroll
        for (int j = 0; j < 4; ++j) {
            const int col = lane8 * 8 + j * 2;
            __half2 h = __floats2half2_rn(e[2 * j] * inv, e[2 * j + 1] * inv);
            *(__half2*)(sm + AT_ATT + SWZ((uint32_t)(row * 128 + col * 2))) = h;
        }
    }
    __syncthreads();

    uint32_t a3[4][4];
    const uint32_t attb = smS + AT_ATT;
#pragma unroll
    for (int ks = 0; ks < 4; ++ks)
        ldsm4(a3[ks], attb + SWZ((uint32_t)((wm * 16 + arow) * 128 + (ks * 2 + acol) * 16)));

    const int trow = (l & 7) + ((l >> 3) & 1) * 8;
    const int tc8  = ((l >> 4) & 1) * 8;

    for (int nt = 0; nt < 8; ++nt) {
        if (nt < 6) { CP_WAIT(1); } else { CP_WAIT(0); }
        __syncthreads();
        if (nt + 2 < 8) loadVO(nt + 2, (nt + 2) % 3);

        const uint32_t vb = smS + (nt % 3) * AT_STAGE;
        float acc3[2][4];
#pragma unroll
        for (int i = 0; i < 2; ++i)
#pragma unroll
            for (int j = 0; j < 4; ++j) acc3[i][j] = 0.f;

#pragma unroll
        for (int ks = 0; ks < 4; ++ks) {
            uint32_t bf[4];
            ldsm4t(bf, vb + SWZ((uint32_t)((ks * 16 + trow) * 128 + (wn * 16 + tc8) * 2)));
            mma_f16(acc3[0], a3[ks], bf[0], bf[1]);
            mma_f16(acc3[1], a3[ks], bf[2], bf[3]);
        }

#pragma unroll
        for (int nb = 0; nb < 2; ++nb) {
            const int col = nt * 64 + wn * 16 + nb * 8 + tig * 2;
            const int r0 = mrow0 + wm * 16 + gid, r1 = r0 + 8;
            float2 ro0 = __half22float2(*(const __half2*)(TVRb + (size_t)r0 * NTVR + 1024 + col));
            float2 ro1 = __half22float2(*(const __half2*)(TVRb + (size_t)r1 * NTVR + 1024 + col));
            float2 o0 = {fmaxf(acc3[nb][0] + ro0.x, 0.f), fmaxf(acc3[nb][1] + ro0.y, 0.f)};
            float2 o1 = {fmaxf(acc3[nb][2] + ro1.x, 0.f), fmaxf(acc3[nb][3] + ro1.y, 0.f)};
            *(float2*)(Ob + (size_t)r0 * 512 + col) = o0;
            *(float2*)(Ob + (size_t)r1 * 512 + col) = o1;
        }
    }
}

// ---------------- launch ----------------
extern "C" void kernel_launch(void* const* d_in, const int* in_sizes, int n_in,
                              void* d_out, int out_size)
{
    const float* inp = (const float*)d_in[0];
    const float* Win = (const float*)d_in[1];
    const float* bin = (const float*)d_in[2];
    const float* Wq  = (const float*)d_in[3];
    const float* bq  = (const float*)d_in[4];
    const float* Wk  = (const float*)d_in[5];
    // d_in[6] = b_k : provably unused (row-constant, drops out of softmax)
    const float* Wv  = (const float*)d_in[7];
    const float* bv  = (const float*)d_in[8];
    const float* Wr  = (const float*)d_in[9];
    const float* br  = (const float*)d_in[10];
    const float* Wo  = (const float*)d_in[11];
    const float* bo  = (const float*)d_in[12];
    float* out = (float*)d_out;

    float *W3, *bias2;
    __half *Xf16, *If16, *WinT, *Wb, *TVR;
    cudaGetSymbolAddress((void**)&TVR,   g_TVR);
    cudaGetSymbolAddress((void**)&W3,    g_W3);
    cudaGetSymbolAddress((void**)&bias2, g_bias2);
    cudaGetSymbolAddress((void**)&Xf16,  g_Xf16);
    cudaGetSymbolAddress((void**)&If16,  g_If16);
    cudaGetSymbolAddress((void**)&WinT,  g_WinT);
    cudaGetSymbolAddress((void**)&Wb,    g_Wb);

    cudaFuncSetAttribute(gemm_f16<true >, cudaFuncAttributeMaxDynamicSharedMemorySize, MG_SMEM);
    cudaFuncSetAttribute(gemm_f16<false>, cudaFuncAttributeMaxDynamicSharedMemorySize, MG_SMEM);
    cudaFuncSetAttribute(attn_tc,         cudaFuncAttributeMaxDynamicSharedMemorySize, ATTN_SMEM);

    // 1: weight products + vectors (gv folded into bias2[0:512])
    wpre_k<<<dim3(8, 8, 4), 256>>>(Wq, Wk, Wv, Wr, Wo, bv, br, bo, bq, W3, bias2);
    // 2: input conversion + weight transposes
    prep2_k<<<PREP_CONV_BLOCKS + 1024, 256>>>(inp, If16, Win, W3, WinT, Wb);
    // 3: gemm1 (128 threads, 64x64 warp tiles)
    gemm_f16<true ><<<dim3(4, 256),  128, MG_SMEM>>>(If16, WinT, bin, Xf16, 512);
    // 4: gemm2 (T block carries +gv bias)
    gemm_f16<false><<<dim3(12, 256), 128, MG_SMEM>>>(Xf16, Wb, bias2, TVR, NTVR);
    // 5: attention (2 CTAs per batch)
    attn_tc<<<NBATCH * 2, 256, ATTN_SMEM>>>(Xf16, TVR, out);
}